// round 1
// baseline (speedup 1.0000x reference)
#include <cuda_runtime.h>
#include <math.h>

#define TOKENS 4096
#define DM     1024
#define DFF    4096
#define SEQ    2048
#define NH     16
#define DK     64

// ---------------- scratch (device globals; no allocation allowed) ----------------
__device__ float g_h[TOKENS*DM];
__device__ float g_Qh[TOKENS*DM];
__device__ float g_Kh[TOKENS*DM];
__device__ float g_Vh[TOKENS*DM];
__device__ float g_attn[TOKENS*DM];
__device__ float g_attnT[TOKENS*DM];
__device__ float g_x1[TOKENS*DM];
__device__ float g_h2[TOKENS*DM];
__device__ float g_u[TOKENS*DFF];
__device__ float g_gb[TOKENS*DFF];
__device__ float g_cs[SEQ*32];
__device__ float g_sn[SEQ*32];

// ---------------- RoPE table (mimic jax fp32 math) ----------------
__global__ void rope_table_k() {
    int i = blockIdx.x * 256 + threadIdx.x;      // 2048*32 = 65536
    int pos = i >> 5;
    int j   = i & 31;
    float invf = (float)pow(10000.0, -(double)(2 * j) / 64.0);
    float ang  = (float)pos * invf;              // fp32 product like the reference
    g_cs[i] = cosf(ang);
    g_sn[i] = sinf(ang);
}

// ---------------- RMSNorm ----------------
__global__ __launch_bounds__(256) void rmsnorm_k(const float* __restrict__ x,
                                                 const float* __restrict__ g,
                                                 float* __restrict__ out) {
    int row = blockIdx.x;
    int t   = threadIdx.x;
    const float4* xr = (const float4*)(x + (size_t)row * DM);
    float4 xv = xr[t];
    float ss = xv.x*xv.x + xv.y*xv.y + xv.z*xv.z + xv.w*xv.w;
    #pragma unroll
    for (int off = 16; off > 0; off >>= 1)
        ss += __shfl_xor_sync(0xffffffffu, ss, off);
    __shared__ float warpsum[8];
    if ((t & 31) == 0) warpsum[t >> 5] = ss;
    __syncthreads();
    float tot = warpsum[0] + warpsum[1] + warpsum[2] + warpsum[3]
              + warpsum[4] + warpsum[5] + warpsum[6] + warpsum[7];
    float r = rsqrtf(tot * (1.0f / (float)DM) + 1e-5f);
    float4 gv = ((const float4*)g)[t];
    float4 ov = make_float4(xv.x*r*gv.x, xv.y*r*gv.y, xv.z*r*gv.z, xv.w*r*gv.w);
    ((float4*)(out + (size_t)row * DM))[t] = ov;
}

// ---------------- SGEMM NT: C[M,N] = A[M,K] * B[N,K]^T, fused epilogues ----------------
#define EPI_NONE     0
#define EPI_ROPE     1   // write to [b,h,s,dk] with RoPE
#define EPI_BHSD     2   // write to [b,h,s,dk]
#define EPI_ADD      3   // C = other + acc
#define EPI_SILU_MUL 4   // C = silu(other) * acc

template<int EPI>
__global__ __launch_bounds__(256, 2) void sgemm_nt(
    const float* __restrict__ A, const float* __restrict__ B,
    float* __restrict__ C, const float* __restrict__ other,
    int M, int N, int K)
{
    __shared__ float As[8][128];
    __shared__ float Bs[8][128];
    const int tid = threadIdx.x;
    const int bm = blockIdx.y, bn = blockIdx.x;
    const int tx = tid & 15, ty = tid >> 4;
    const int lrow = tid >> 1;
    const int lcol = (tid & 1) * 4;
    const float* Ap = A + (size_t)(bm * 128 + lrow) * K + lcol;
    const float* Bp = B + (size_t)(bn * 128 + lrow) * K + lcol;

    float acc[8][8];
    #pragma unroll
    for (int i = 0; i < 8; i++)
        #pragma unroll
        for (int j = 0; j < 8; j++) acc[i][j] = 0.0f;

    for (int k0 = 0; k0 < K; k0 += 8) {
        float4 av = *(const float4*)(Ap + k0);
        float4 bv = *(const float4*)(Bp + k0);
        __syncthreads();
        As[lcol+0][lrow] = av.x; As[lcol+1][lrow] = av.y;
        As[lcol+2][lrow] = av.z; As[lcol+3][lrow] = av.w;
        Bs[lcol+0][lrow] = bv.x; Bs[lcol+1][lrow] = bv.y;
        Bs[lcol+2][lrow] = bv.z; Bs[lcol+3][lrow] = bv.w;
        __syncthreads();
        #pragma unroll
        for (int k = 0; k < 8; k++) {
            float a[8], b[8];
            *(float4*)(a)     = *(const float4*)&As[k][ty*8];
            *(float4*)(a + 4) = *(const float4*)&As[k][ty*8 + 4];
            *(float4*)(b)     = *(const float4*)&Bs[k][tx*8];
            *(float4*)(b + 4) = *(const float4*)&Bs[k][tx*8 + 4];
            #pragma unroll
            for (int i = 0; i < 8; i++)
                #pragma unroll
                for (int j = 0; j < 8; j++)
                    acc[i][j] += a[i] * b[j];
        }
    }

    const int row0 = bm * 128 + ty * 8;
    const int col0 = bn * 128 + tx * 8;
    #pragma unroll
    for (int i = 0; i < 8; i++) {
        int m = row0 + i;
        if (EPI == EPI_ROPE || EPI == EPI_BHSD) {
            int pos = m & (SEQ - 1);
            int b   = m >> 11;
            #pragma unroll
            for (int j = 0; j < 8; j += 2) {
                int c    = col0 + j;
                int head = c >> 6;
                int hi   = c & 63;
                size_t oidx = ((size_t)((b * NH + head) * SEQ) + pos) * DK + hi;
                if (EPI == EPI_ROPE) {
                    int pr   = hi >> 1;
                    float cs = g_cs[pos * 32 + pr];
                    float sn = g_sn[pos * 32 + pr];
                    float v0 = acc[i][j], v1 = acc[i][j + 1];
                    C[oidx]     = v0 * cs - v1 * sn;
                    C[oidx + 1] = v0 * sn + v1 * cs;
                } else {
                    C[oidx]     = acc[i][j];
                    C[oidx + 1] = acc[i][j + 1];
                }
            }
        } else {
            size_t base = (size_t)m * N + col0;
            #pragma unroll
            for (int j = 0; j < 8; j++) {
                float v = acc[i][j];
                if (EPI == EPI_ADD) {
                    v += other[base + j];
                } else if (EPI == EPI_SILU_MUL) {
                    float uu = other[base + j];
                    v *= uu / (1.0f + __expf(-uu));
                }
                C[base + j] = v;
            }
        }
    }
}

// ---------------- Flash attention (causal), thread-per-query ----------------
__global__ __launch_bounds__(64) void flash_attn(
    const float* __restrict__ Q, const float* __restrict__ K,
    const float* __restrict__ V, float* __restrict__ O)
{
    __shared__ float Ks[64 * 64];
    __shared__ float Vs[64 * 64];
    const int bh = blockIdx.y;     // 0..31 (b*16+h)
    const int qt = blockIdx.x;     // 0..31 query tile
    const int t  = threadIdx.x;    // 0..63 query within tile
    const size_t base = (size_t)bh * SEQ * DK;
    const int qi = qt * 64 + t;

    float q[64];
    const float4* qsrc = (const float4*)(Q + base + (size_t)qi * DK);
    #pragma unroll
    for (int d4 = 0; d4 < 16; d4++) {
        float4 v = qsrc[d4];
        q[d4*4+0] = v.x * 0.125f; q[d4*4+1] = v.y * 0.125f;
        q[d4*4+2] = v.z * 0.125f; q[d4*4+3] = v.w * 0.125f;
    }
    float o[64];
    #pragma unroll
    for (int d = 0; d < 64; d++) o[d] = 0.0f;
    float mI = -3.0e38f, l = 0.0f;

    for (int kt = 0; kt <= qt; kt++) {
        const float4* Ksrc = (const float4*)(K + base + (size_t)kt * 64 * DK);
        const float4* Vsrc = (const float4*)(V + base + (size_t)kt * 64 * DK);
        __syncthreads();
        for (int i = t; i < 1024; i += 64) {
            ((float4*)Ks)[i] = Ksrc[i];
            ((float4*)Vs)[i] = Vsrc[i];
        }
        __syncthreads();

        float s[64];
        float tmax = -3.0e38f;
        const int lim = (kt == qt) ? (t + 1) : 64;

        if (kt < qt) {
            #pragma unroll 4
            for (int j = 0; j < 64; j++) {
                const float4* kr = (const float4*)(Ks + j * 64);
                float a0 = 0, a1 = 0, a2 = 0, a3 = 0;
                #pragma unroll
                for (int d4 = 0; d4 < 16; d4++) {
                    float4 kv = kr[d4];
                    a0 += q[d4*4+0] * kv.x; a1 += q[d4*4+1] * kv.y;
                    a2 += q[d4*4+2] * kv.z; a3 += q[d4*4+3] * kv.w;
                }
                float accv = (a0 + a1) + (a2 + a3);
                s[j] = accv;
                tmax = fmaxf(tmax, accv);
            }
        } else {
            #pragma unroll 4
            for (int j = 0; j < 64; j++) {
                if (j >= lim) break;
                const float4* kr = (const float4*)(Ks + j * 64);
                float a0 = 0, a1 = 0, a2 = 0, a3 = 0;
                #pragma unroll
                for (int d4 = 0; d4 < 16; d4++) {
                    float4 kv = kr[d4];
                    a0 += q[d4*4+0] * kv.x; a1 += q[d4*4+1] * kv.y;
                    a2 += q[d4*4+2] * kv.z; a3 += q[d4*4+3] * kv.w;
                }
                float accv = (a0 + a1) + (a2 + a3);
                s[j] = accv;
                tmax = fmaxf(tmax, accv);
            }
        }

        float newm = fmaxf(mI, tmax);
        float corr = __expf(mI - newm);
        l *= corr;
        #pragma unroll
        for (int d = 0; d < 64; d++) o[d] *= corr;

        #pragma unroll 2
        for (int j = 0; j < 64; j++) {
            if (j >= lim) break;
            float p = __expf(s[j] - newm);
            l += p;
            const float4* vr = (const float4*)(Vs + j * 64);
            #pragma unroll
            for (int d4 = 0; d4 < 16; d4++) {
                float4 vv = vr[d4];
                o[d4*4+0] += p * vv.x; o[d4*4+1] += p * vv.y;
                o[d4*4+2] += p * vv.z; o[d4*4+3] += p * vv.w;
            }
        }
        mI = newm;
    }

    float inv = 1.0f / l;
    float4* od = (float4*)(O + base + (size_t)qi * DK);
    #pragma unroll
    for (int d4 = 0; d4 < 16; d4++)
        od[d4] = make_float4(o[d4*4+0]*inv, o[d4*4+1]*inv,
                             o[d4*4+2]*inv, o[d4*4+3]*inv);
}

// ---------------- [b,h,s,dk] -> [token, d] ----------------
__global__ void bhsd_to_td(const float* __restrict__ in, float* __restrict__ out) {
    int i  = blockIdx.x * 256 + threadIdx.x;   // float4 index over TOKENS*DM/4
    int c4 = i & 255;
    int m  = i >> 8;
    int s  = m & (SEQ - 1);
    int b  = m >> 11;
    int c  = c4 * 4;
    int head = c >> 6;
    int hi   = c & 63;
    const float4* src = (const float4*)(in + (((size_t)(b * NH + head) * SEQ + s) * DK + hi));
    ((float4*)out)[i] = *src;
}

// ---------------- launch ----------------
extern "C" void kernel_launch(void* const* d_in, const int* in_sizes, int n_in,
                              void* d_out, int out_size)
{
    const float* x  = (const float*)d_in[0];
    const float* Wq = (const float*)d_in[1];
    const float* Wk = (const float*)d_in[2];
    const float* Wv = (const float*)d_in[3];
    const float* Wo = (const float*)d_in[4];
    const float* g1 = (const float*)d_in[5];
    const float* g2 = (const float*)d_in[6];
    const float* W1 = (const float*)d_in[7];
    const float* W3 = (const float*)d_in[8];
    const float* W2 = (const float*)d_in[9];
    float* out = (float*)d_out;

    float *h, *Qh, *Kh, *Vh, *attn, *attnT, *x1, *h2, *u, *gb;
    cudaGetSymbolAddress((void**)&h,     g_h);
    cudaGetSymbolAddress((void**)&Qh,    g_Qh);
    cudaGetSymbolAddress((void**)&Kh,    g_Kh);
    cudaGetSymbolAddress((void**)&Vh,    g_Vh);
    cudaGetSymbolAddress((void**)&attn,  g_attn);
    cudaGetSymbolAddress((void**)&attnT, g_attnT);
    cudaGetSymbolAddress((void**)&x1,    g_x1);
    cudaGetSymbolAddress((void**)&h2,    g_h2);
    cudaGetSymbolAddress((void**)&u,     g_u);
    cudaGetSymbolAddress((void**)&gb,    g_gb);

    dim3 gProj(DM / 128, TOKENS / 128);    // N=1024
    dim3 gFF(DFF / 128, TOKENS / 128);     // N=4096

    rope_table_k<<<SEQ * 32 / 256, 256>>>();
    rmsnorm_k<<<TOKENS, 256>>>(x, g1, h);

    sgemm_nt<EPI_ROPE><<<gProj, 256>>>(h, Wq, Qh, nullptr, TOKENS, DM, DM);
    sgemm_nt<EPI_ROPE><<<gProj, 256>>>(h, Wk, Kh, nullptr, TOKENS, DM, DM);
    sgemm_nt<EPI_BHSD><<<gProj, 256>>>(h, Wv, Vh, nullptr, TOKENS, DM, DM);

    flash_attn<<<dim3(SEQ / 64, 2 * NH), 64>>>(Qh, Kh, Vh, attn);
    bhsd_to_td<<<(TOKENS * DM / 4) / 256, 256>>>(attn, attnT);

    sgemm_nt<EPI_ADD><<<gProj, 256>>>(attnT, Wo, x1, x, TOKENS, DM, DM);
    rmsnorm_k<<<TOKENS, 256>>>(x1, g2, h2);

    sgemm_nt<EPI_NONE><<<gFF, 256>>>(h2, W1, u, nullptr, TOKENS, DFF, DM);
    sgemm_nt<EPI_SILU_MUL><<<gFF, 256>>>(h2, W3, gb, u, TOKENS, DFF, DM);
    sgemm_nt<EPI_ADD><<<gProj, 256>>>(gb, W2, out, x1, TOKENS, DM, DFF);
}

// round 3
// speedup vs baseline: 1.8642x; 1.8642x over previous
#include <cuda_runtime.h>
#include <cuda_bf16.h>
#include <math.h>
#include <stdint.h>

#define TOKENS 4096
#define DM     1024
#define DFF    4096
#define SEQ    2048
#define NH     16
#define DK     64

// ---------------- scratch (device globals; no allocation allowed) ----------------
__device__ float g_Qh[TOKENS*DM];
__device__ float g_Kh[TOKENS*DM];
__device__ float g_Vh[TOKENS*DM];
__device__ float g_attn[TOKENS*DM];
__device__ float g_x1[TOKENS*DM];
__device__ float g_u[TOKENS*DFF];
__device__ float g_cs[SEQ*32];
__device__ float g_sn[SEQ*32];

// bf16 split activations
__device__ __nv_bfloat16 g_hh[TOKENS*DM],  g_hl[TOKENS*DM];    // rmsnorm1 out
__device__ __nv_bfloat16 g_ath[TOKENS*DM], g_atl[TOKENS*DM];   // attn (token-major)
__device__ __nv_bfloat16 g_h2h[TOKENS*DM], g_h2l[TOKENS*DM];   // rmsnorm2 out
__device__ __nv_bfloat16 g_gbh[TOKENS*DFF], g_gbl[TOKENS*DFF]; // silu(u)*v

// bf16 split weights, packed
#define WOFF_Q  0
#define WOFF_K  (1u<<20)
#define WOFF_V  (2u<<20)
#define WOFF_O  (3u<<20)
#define WOFF_1  (4u<<20)
#define WOFF_3  (8u<<20)
#define WOFF_2  (12u<<20)
__device__ __nv_bfloat16 g_wh[16u<<20];
__device__ __nv_bfloat16 g_wl[16u<<20];

// ---------------- helpers ----------------
__device__ __forceinline__ uint32_t smem_u32(const void* p){
    uint32_t r;
    asm("{ .reg .u64 t; cvta.to.shared.u64 t, %1; cvt.u32.u64 %0, t; }" : "=r"(r) : "l"(p));
    return r;
}
__device__ __forceinline__ void cpa16(uint32_t dst, const void* src){
    asm volatile("cp.async.cg.shared.global [%0], [%1], 16;" :: "r"(dst), "l"(src) : "memory");
}
__device__ __forceinline__ void cp_commit(){ asm volatile("cp.async.commit_group;" ::: "memory"); }
__device__ __forceinline__ void cp_wait1(){ asm volatile("cp.async.wait_group 1;" ::: "memory"); }
__device__ __forceinline__ void cp_wait0(){ asm volatile("cp.async.wait_group 0;" ::: "memory"); }

__device__ __forceinline__ void ldsm4(uint32_t* r, uint32_t addr){
    asm volatile("ldmatrix.sync.aligned.m8n8.x4.shared.b16 {%0,%1,%2,%3}, [%4];"
        : "=r"(r[0]),"=r"(r[1]),"=r"(r[2]),"=r"(r[3]) : "r"(addr));
}
__device__ __forceinline__ void mma16816(float* c, const uint32_t* a, uint32_t b0, uint32_t b1){
    asm volatile("mma.sync.aligned.m16n8k16.row.col.f32.bf16.bf16.f32 "
        "{%0,%1,%2,%3}, {%4,%5,%6,%7}, {%8,%9}, {%0,%1,%2,%3};"
        : "+f"(c[0]),"+f"(c[1]),"+f"(c[2]),"+f"(c[3])
        : "r"(a[0]),"r"(a[1]),"r"(a[2]),"r"(a[3]), "r"(b0),"r"(b1));
}
#define SW(o) ((o) ^ (((o)>>3)&0x30))

// ---------------- RoPE table (mimic jax fp32 math) ----------------
__global__ void rope_table_k() {
    int i = blockIdx.x * 256 + threadIdx.x;
    int pos = i >> 5;
    int j   = i & 31;
    float invf = (float)pow(10000.0, -(double)(2 * j) / 64.0);
    float ang  = (float)pos * invf;
    g_cs[i] = cosf(ang);
    g_sn[i] = sinf(ang);
}

// ---------------- weight split fp32 -> bf16 hi/lo ----------------
__global__ void split_k(const float* __restrict__ s, __nv_bfloat16* __restrict__ h,
                        __nv_bfloat16* __restrict__ l, int n){
    int i = blockIdx.x * 256 + threadIdx.x;
    if (i < n){
        float v = s[i];
        __nv_bfloat16 hh = __float2bfloat16(v);
        h[i] = hh;
        l[i] = __float2bfloat16(v - __bfloat162float(hh));
    }
}

// ---------------- RMSNorm -> bf16 hi/lo ----------------
__global__ __launch_bounds__(256) void rms_split_k(const float* __restrict__ x,
                                                   const float* __restrict__ g,
                                                   __nv_bfloat16* __restrict__ oh,
                                                   __nv_bfloat16* __restrict__ ol) {
    int row = blockIdx.x;
    int t   = threadIdx.x;
    const float4* xr = (const float4*)(x + (size_t)row * DM);
    float4 xv = xr[t];
    float ss = xv.x*xv.x + xv.y*xv.y + xv.z*xv.z + xv.w*xv.w;
    #pragma unroll
    for (int off = 16; off > 0; off >>= 1)
        ss += __shfl_xor_sync(0xffffffffu, ss, off);
    __shared__ float warpsum[8];
    if ((t & 31) == 0) warpsum[t >> 5] = ss;
    __syncthreads();
    float tot = warpsum[0]+warpsum[1]+warpsum[2]+warpsum[3]
              + warpsum[4]+warpsum[5]+warpsum[6]+warpsum[7];
    float r = rsqrtf(tot * (1.0f / (float)DM) + 1e-5f);
    float4 gv = ((const float4*)g)[t];
    float v[4] = { xv.x*r*gv.x, xv.y*r*gv.y, xv.z*r*gv.z, xv.w*r*gv.w };
    size_t base = (size_t)row * DM + t * 4;
    #pragma unroll
    for (int k = 0; k < 4; k++){
        __nv_bfloat16 hh = __float2bfloat16(v[k]);
        oh[base+k] = hh;
        ol[base+k] = __float2bfloat16(v[k] - __bfloat162float(hh));
    }
}

// ---------------- [b,h,s,dk] fp32 -> [token,d] bf16 hi/lo ----------------
__global__ void bhsd_split_k(const float* __restrict__ in,
                             __nv_bfloat16* __restrict__ oh,
                             __nv_bfloat16* __restrict__ ol) {
    int i  = blockIdx.x * 256 + threadIdx.x;  // over TOKENS*DM
    int c  = i & (DM - 1);
    int m  = i >> 10;
    int s  = m & (SEQ - 1);
    int b  = m >> 11;
    int head = c >> 6;
    int hi   = c & 63;
    float v = in[(((size_t)(b * NH + head) * SEQ) + s) * DK + hi];
    __nv_bfloat16 hh = __float2bfloat16(v);
    oh[i] = hh;
    ol[i] = __float2bfloat16(v - __bfloat162float(hh));
}

// ---------------- MMA GEMM NT: C[M,N] = A[M,K]*B[N,K]^T (bf16-split x3) ----------------
#define EPI_NONE       0
#define EPI_ROPE       1
#define EPI_BHSD       2
#define EPI_ADD        3
#define EPI_SILU_SPLIT 4

#define STG_BYTES 32768          // Ah(8K) Al(8K) Bh(8K) Bl(8K)
#define GEMM_SMEM (3*STG_BYTES)  // 96 KB, 3 stages

template<int EPI>
__global__ __launch_bounds__(256, 1) void gemm_mma(
    const __nv_bfloat16* __restrict__ Ah, const __nv_bfloat16* __restrict__ Al,
    const __nv_bfloat16* __restrict__ Bh, const __nv_bfloat16* __restrict__ Bl,
    float* __restrict__ C, const float* __restrict__ other,
    __nv_bfloat16* __restrict__ Chi, __nv_bfloat16* __restrict__ Clo,
    int M, int N, int K)
{
    extern __shared__ char smem[];
    uint32_t sb = smem_u32(smem);
    const int tid  = threadIdx.x;
    const int lane = tid & 31;
    const int wid  = tid >> 5;
    const int wm   = wid & 1;        // 2 warp-rows (64 each)
    const int wn   = wid >> 1;       // 4 warp-cols (32 each)
    const int bn = blockIdx.x, bm = blockIdx.y;
    const int m0 = bm * 128, n0 = bn * 128;
    const int NC = K >> 5;           // K-chunks of 32

    float acc[4][4][4];
    #pragma unroll
    for (int i = 0; i < 4; i++)
        #pragma unroll
        for (int j = 0; j < 4; j++)
            #pragma unroll
            for (int k = 0; k < 4; k++) acc[i][j][k] = 0.0f;

    auto load_chunk = [&](int kc, int stage){
        uint32_t tb = sb + stage * STG_BYTES;
        int k0 = kc * 32;
        #pragma unroll
        for (int mtx = 0; mtx < 4; mtx++){
            const __nv_bfloat16* base = (mtx == 0) ? Ah : (mtx == 1) ? Al : (mtx == 2) ? Bh : Bl;
            int row0 = (mtx < 2) ? m0 : n0;
            #pragma unroll
            for (int j = 0; j < 2; j++){
                int i = j * 256 + tid;         // 0..511 16B chunks
                int r = i >> 2, c16 = i & 3;
                uint32_t o = (uint32_t)(r << 6) + (c16 << 4);
                cpa16(tb + (mtx << 13) + SW(o),
                      base + (size_t)(row0 + r) * K + k0 + c16 * 8);
            }
        }
        cp_commit();
    };

    load_chunk(0, 0);
    load_chunk(1, 1);

    for (int kc = 0; kc < NC; kc++){
        if (kc + 1 < NC) cp_wait1(); else cp_wait0();
        __syncthreads();
        uint32_t tb = sb + (kc % 3) * STG_BYTES;

        #pragma unroll
        for (int s = 0; s < 2; s++){
            uint32_t ah[4][4], al[4][4];
            #pragma unroll
            for (int t = 0; t < 4; t++){
                uint32_t o = (uint32_t)((wm*64 + t*16 + (lane & 15)) << 6)
                           + s*32 + ((lane >> 4) << 4);
                uint32_t so = SW(o);
                ldsm4(ah[t], tb + so);
                ldsm4(al[t], tb + 8192 + so);
            }
            uint32_t bh2[2][4], bl2[2][4];
            #pragma unroll
            for (int g = 0; g < 2; g++){
                uint32_t o = (uint32_t)((wn*32 + g*16 + (lane & 15)) << 6)
                           + s*32 + ((lane >> 4) << 4);
                uint32_t so = SW(o);
                ldsm4(bh2[g], tb + 16384 + so);
                ldsm4(bl2[g], tb + 24576 + so);
            }
            #pragma unroll
            for (int tm = 0; tm < 4; tm++)
                #pragma unroll
                for (int g = 0; g < 2; g++)
                    #pragma unroll
                    for (int j = 0; j < 2; j++){
                        int tn = g*2 + j;
                        mma16816(acc[tm][tn], ah[tm], bh2[g][j], bh2[g][j+2]);
                        mma16816(acc[tm][tn], ah[tm], bl2[g][j], bl2[g][j+2]);
                        mma16816(acc[tm][tn], al[tm], bh2[g][j], bh2[g][j+2]);
                    }
        }
        if (kc + 2 < NC) load_chunk(kc + 2, (kc + 2) % 3);
    }

    // ---------------- epilogue ----------------
    const int gid = lane >> 2, tig = lane & 3;
    #pragma unroll
    for (int tm = 0; tm < 4; tm++){
        #pragma unroll
        for (int half = 0; half < 2; half++){
            int m = m0 + wm*64 + tm*16 + gid + half*8;
            if (EPI == EPI_ROPE || EPI == EPI_BHSD){
                int pos = m & (SEQ - 1), b = m >> 11;
                #pragma unroll
                for (int tn = 0; tn < 4; tn++){
                    int c = n0 + wn*32 + tn*8 + tig*2;   // even
                    int head = c >> 6, hi = c & 63;
                    size_t ob = ((size_t)(b * NH + head) * SEQ + pos) * DK + hi;
                    float v0 = acc[tm][tn][half*2];
                    float v1 = acc[tm][tn][half*2 + 1];
                    if (EPI == EPI_ROPE){
                        float cs = g_cs[pos * 32 + (hi >> 1)];
                        float sn = g_sn[pos * 32 + (hi >> 1)];
                        C[ob]     = v0 * cs - v1 * sn;
                        C[ob + 1] = v0 * sn + v1 * cs;
                    } else {
                        C[ob]     = v0;
                        C[ob + 1] = v1;
                    }
                }
            } else {
                #pragma unroll
                for (int tn = 0; tn < 4; tn++){
                    int c = n0 + wn*32 + tn*8 + tig*2;
                    size_t base = (size_t)m * N + c;
                    float v0 = acc[tm][tn][half*2];
                    float v1 = acc[tm][tn][half*2 + 1];
                    if (EPI == EPI_ADD){
                        C[base]     = other[base] + v0;
                        C[base + 1] = other[base + 1] + v1;
                    } else if (EPI == EPI_NONE){
                        C[base]     = v0;
                        C[base + 1] = v1;
                    } else {
                        float u0 = other[base], u1 = other[base + 1];
                        float w0 = v0 * u0 / (1.0f + __expf(-u0));
                        float w1 = v1 * u1 / (1.0f + __expf(-u1));
                        __nv_bfloat16 h0 = __float2bfloat16(w0);
                        __nv_bfloat16 h1 = __float2bfloat16(w1);
                        Chi[base]     = h0;
                        Chi[base + 1] = h1;
                        Clo[base]     = __float2bfloat16(w0 - __bfloat162float(h0));
                        Clo[base + 1] = __float2bfloat16(w1 - __bfloat162float(h1));
                    }
                }
            }
        }
    }
}

// ---------------- Flash attention (causal), thread-per-query ----------------
__global__ __launch_bounds__(64) void flash_attn(
    const float* __restrict__ Q, const float* __restrict__ K,
    const float* __restrict__ V, float* __restrict__ O)
{
    __shared__ float Ks[64 * 64];
    __shared__ float Vs[64 * 64];
    const int bh = blockIdx.y;
    const int qt = blockIdx.x;
    const int t  = threadIdx.x;
    const size_t base = (size_t)bh * SEQ * DK;
    const int qi = qt * 64 + t;

    float q[64];
    const float4* qsrc = (const float4*)(Q + base + (size_t)qi * DK);
    #pragma unroll
    for (int d4 = 0; d4 < 16; d4++) {
        float4 v = qsrc[d4];
        q[d4*4+0] = v.x * 0.125f; q[d4*4+1] = v.y * 0.125f;
        q[d4*4+2] = v.z * 0.125f; q[d4*4+3] = v.w * 0.125f;
    }
    float o[64];
    #pragma unroll
    for (int d = 0; d < 64; d++) o[d] = 0.0f;
    float mI = -3.0e38f, l = 0.0f;

    for (int kt = 0; kt <= qt; kt++) {
        const float4* Ksrc = (const float4*)(K + base + (size_t)kt * 64 * DK);
        const float4* Vsrc = (const float4*)(V + base + (size_t)kt * 64 * DK);
        __syncthreads();
        for (int i = t; i < 1024; i += 64) {
            ((float4*)Ks)[i] = Ksrc[i];
            ((float4*)Vs)[i] = Vsrc[i];
        }
        __syncthreads();

        float s[64];
        float tmax = -3.0e38f;
        const int lim = (kt == qt) ? (t + 1) : 64;

        if (kt < qt) {
            #pragma unroll 4
            for (int j = 0; j < 64; j++) {
                const float4* kr = (const float4*)(Ks + j * 64);
                float a0 = 0, a1 = 0, a2 = 0, a3 = 0;
                #pragma unroll
                for (int d4 = 0; d4 < 16; d4++) {
                    float4 kv = kr[d4];
                    a0 += q[d4*4+0] * kv.x; a1 += q[d4*4+1] * kv.y;
                    a2 += q[d4*4+2] * kv.z; a3 += q[d4*4+3] * kv.w;
                }
                float accv = (a0 + a1) + (a2 + a3);
                s[j] = accv;
                tmax = fmaxf(tmax, accv);
            }
        } else {
            #pragma unroll 4
            for (int j = 0; j < 64; j++) {
                if (j >= lim) break;
                const float4* kr = (const float4*)(Ks + j * 64);
                float a0 = 0, a1 = 0, a2 = 0, a3 = 0;
                #pragma unroll
                for (int d4 = 0; d4 < 16; d4++) {
                    float4 kv = kr[d4];
                    a0 += q[d4*4+0] * kv.x; a1 += q[d4*4+1] * kv.y;
                    a2 += q[d4*4+2] * kv.z; a3 += q[d4*4+3] * kv.w;
                }
                float accv = (a0 + a1) + (a2 + a3);
                s[j] = accv;
                tmax = fmaxf(tmax, accv);
            }
        }

        float newm = fmaxf(mI, tmax);
        float corr = __expf(mI - newm);
        l *= corr;
        #pragma unroll
        for (int d = 0; d < 64; d++) o[d] *= corr;

        #pragma unroll 2
        for (int j = 0; j < 64; j++) {
            if (j >= lim) break;
            float p = __expf(s[j] - newm);
            l += p;
            const float4* vr = (const float4*)(Vs + j * 64);
            #pragma unroll
            for (int d4 = 0; d4 < 16; d4++) {
                float4 vv = vr[d4];
                o[d4*4+0] += p * vv.x; o[d4*4+1] += p * vv.y;
                o[d4*4+2] += p * vv.z; o[d4*4+3] += p * vv.w;
            }
        }
        mI = newm;
    }

    float inv = 1.0f / l;
    float4* od = (float4*)(O + base + (size_t)qi * DK);
    #pragma unroll
    for (int d4 = 0; d4 < 16; d4++)
        od[d4] = make_float4(o[d4*4+0]*inv, o[d4*4+1]*inv,
                             o[d4*4+2]*inv, o[d4*4+3]*inv);
}

// ---------------- launch ----------------
extern "C" void kernel_launch(void* const* d_in, const int* in_sizes, int n_in,
                              void* d_out, int out_size)
{
    const float* x  = (const float*)d_in[0];
    const float* Wq = (const float*)d_in[1];
    const float* Wk = (const float*)d_in[2];
    const float* Wv = (const float*)d_in[3];
    const float* Wo = (const float*)d_in[4];
    const float* g1 = (const float*)d_in[5];
    const float* g2 = (const float*)d_in[6];
    const float* W1 = (const float*)d_in[7];
    const float* W3 = (const float*)d_in[8];
    const float* W2 = (const float*)d_in[9];
    float* out = (float*)d_out;

    float *Qh,*Kh,*Vh,*attn,*x1,*u;
    __nv_bfloat16 *hh,*hl,*ath,*atl,*h2h,*h2l,*gbh,*gbl,*wh,*wl;
    cudaGetSymbolAddress((void**)&Qh,   g_Qh);
    cudaGetSymbolAddress((void**)&Kh,   g_Kh);
    cudaGetSymbolAddress((void**)&Vh,   g_Vh);
    cudaGetSymbolAddress((void**)&attn, g_attn);
    cudaGetSymbolAddress((void**)&x1,   g_x1);
    cudaGetSymbolAddress((void**)&u,    g_u);
    cudaGetSymbolAddress((void**)&hh,   g_hh);
    cudaGetSymbolAddress((void**)&hl,   g_hl);
    cudaGetSymbolAddress((void**)&ath,  g_ath);
    cudaGetSymbolAddress((void**)&atl,  g_atl);
    cudaGetSymbolAddress((void**)&h2h,  g_h2h);
    cudaGetSymbolAddress((void**)&h2l,  g_h2l);
    cudaGetSymbolAddress((void**)&gbh,  g_gbh);
    cudaGetSymbolAddress((void**)&gbl,  g_gbl);
    cudaGetSymbolAddress((void**)&wh,   g_wh);
    cudaGetSymbolAddress((void**)&wl,   g_wl);

    cudaFuncSetAttribute(gemm_mma<EPI_NONE>,       cudaFuncAttributeMaxDynamicSharedMemorySize, GEMM_SMEM);
    cudaFuncSetAttribute(gemm_mma<EPI_ROPE>,       cudaFuncAttributeMaxDynamicSharedMemorySize, GEMM_SMEM);
    cudaFuncSetAttribute(gemm_mma<EPI_BHSD>,       cudaFuncAttributeMaxDynamicSharedMemorySize, GEMM_SMEM);
    cudaFuncSetAttribute(gemm_mma<EPI_ADD>,        cudaFuncAttributeMaxDynamicSharedMemorySize, GEMM_SMEM);
    cudaFuncSetAttribute(gemm_mma<EPI_SILU_SPLIT>, cudaFuncAttributeMaxDynamicSharedMemorySize, GEMM_SMEM);

    const int MEG = 1 << 20;
    rope_table_k<<<SEQ * 32 / 256, 256>>>();
    split_k<<<(1*MEG)/256, 256>>>(Wq, wh + WOFF_Q, wl + WOFF_Q, 1*MEG);
    split_k<<<(1*MEG)/256, 256>>>(Wk, wh + WOFF_K, wl + WOFF_K, 1*MEG);
    split_k<<<(1*MEG)/256, 256>>>(Wv, wh + WOFF_V, wl + WOFF_V, 1*MEG);
    split_k<<<(1*MEG)/256, 256>>>(Wo, wh + WOFF_O, wl + WOFF_O, 1*MEG);
    split_k<<<(4*MEG)/256, 256>>>(W1, wh + WOFF_1, wl + WOFF_1, 4*MEG);
    split_k<<<(4*MEG)/256, 256>>>(W3, wh + WOFF_3, wl + WOFF_3, 4*MEG);
    split_k<<<(4*MEG)/256, 256>>>(W2, wh + WOFF_2, wl + WOFF_2, 4*MEG);

    rms_split_k<<<TOKENS, 256>>>(x, g1, hh, hl);

    dim3 gProj(DM / 128, TOKENS / 128);
    dim3 gFF(DFF / 128, TOKENS / 128);

    gemm_mma<EPI_ROPE><<<gProj, 256, GEMM_SMEM>>>(hh, hl, wh+WOFF_Q, wl+WOFF_Q, Qh, nullptr, nullptr, nullptr, TOKENS, DM, DM);
    gemm_mma<EPI_ROPE><<<gProj, 256, GEMM_SMEM>>>(hh, hl, wh+WOFF_K, wl+WOFF_K, Kh, nullptr, nullptr, nullptr, TOKENS, DM, DM);
    gemm_mma<EPI_BHSD><<<gProj, 256, GEMM_SMEM>>>(hh, hl, wh+WOFF_V, wl+WOFF_V, Vh, nullptr, nullptr, nullptr, TOKENS, DM, DM);

    flash_attn<<<dim3(SEQ / 64, 2 * NH), 64>>>(Qh, Kh, Vh, attn);
    bhsd_split_k<<<(TOKENS * DM) / 256, 256>>>(attn, ath, atl);

    gemm_mma<EPI_ADD><<<gProj, 256, GEMM_SMEM>>>(ath, atl, wh+WOFF_O, wl+WOFF_O, x1, x, nullptr, nullptr, TOKENS, DM, DM);
    rms_split_k<<<TOKENS, 256>>>(x1, g2, h2h, h2l);

    gemm_mma<EPI_NONE><<<gFF, 256, GEMM_SMEM>>>(h2h, h2l, wh+WOFF_1, wl+WOFF_1, u, nullptr, nullptr, nullptr, TOKENS, DFF, DM);
    gemm_mma<EPI_SILU_SPLIT><<<gFF, 256, GEMM_SMEM>>>(h2h, h2l, wh+WOFF_3, wl+WOFF_3, nullptr, u, gbh, gbl, TOKENS, DFF, DM);
    gemm_mma<EPI_ADD><<<gProj, 256, GEMM_SMEM>>>(gbh, gbl, wh+WOFF_2, wl+WOFF_2, out, x1, nullptr, nullptr, TOKENS, DM, DFF);
}

// round 4
// speedup vs baseline: 2.5621x; 1.3744x over previous
#include <cuda_runtime.h>
#include <cuda_bf16.h>
#include <math.h>
#include <stdint.h>

#define TOKENS 4096
#define DM     1024
#define DFF    4096
#define SEQ    2048
#define NH     16
#define DK     64

// ---------------- scratch (device globals; no allocation allowed) ----------------
__device__ float g_x1[TOKENS*DM];
__device__ float g_u[TOKENS*DFF];
__device__ float g_cs[SEQ*32];
__device__ float g_sn[SEQ*32];

// bf16 split activations
__device__ __nv_bfloat16 g_hh[TOKENS*DM],  g_hl[TOKENS*DM];    // rmsnorm1 out
__device__ __nv_bfloat16 g_ath[TOKENS*DM], g_atl[TOKENS*DM];   // attn out (token-major)
__device__ __nv_bfloat16 g_h2h[TOKENS*DM], g_h2l[TOKENS*DM];   // rmsnorm2 out
__device__ __nv_bfloat16 g_gbh[TOKENS*DFF], g_gbl[TOKENS*DFF]; // silu(u)*v
// Q/K/V bf16 split, [b,h,s,dk] layout
__device__ __nv_bfloat16 g_qhh[TOKENS*DM], g_qhl[TOKENS*DM];
__device__ __nv_bfloat16 g_khh[TOKENS*DM], g_khl[TOKENS*DM];
__device__ __nv_bfloat16 g_vhh[TOKENS*DM], g_vhl[TOKENS*DM];

// bf16 split weights, packed
#define WOFF_Q  0
#define WOFF_K  (1u<<20)
#define WOFF_V  (2u<<20)
#define WOFF_O  (3u<<20)
#define WOFF_1  (4u<<20)
#define WOFF_3  (8u<<20)
#define WOFF_2  (12u<<20)
__device__ __nv_bfloat16 g_wh[16u<<20];
__device__ __nv_bfloat16 g_wl[16u<<20];

// ---------------- helpers ----------------
__device__ __forceinline__ uint32_t smem_u32(const void* p){
    uint32_t r;
    asm("{ .reg .u64 t; cvta.to.shared.u64 t, %1; cvt.u32.u64 %0, t; }" : "=r"(r) : "l"(p));
    return r;
}
__device__ __forceinline__ void cpa16(uint32_t dst, const void* src){
    asm volatile("cp.async.cg.shared.global [%0], [%1], 16;" :: "r"(dst), "l"(src) : "memory");
}
__device__ __forceinline__ void cp_commit(){ asm volatile("cp.async.commit_group;" ::: "memory"); }
__device__ __forceinline__ void cp_wait2(){ asm volatile("cp.async.wait_group 2;" ::: "memory"); }
__device__ __forceinline__ void cp_wait1(){ asm volatile("cp.async.wait_group 1;" ::: "memory"); }
__device__ __forceinline__ void cp_wait0(){ asm volatile("cp.async.wait_group 0;" ::: "memory"); }

__device__ __forceinline__ void ldsm4(uint32_t* r, uint32_t addr){
    asm volatile("ldmatrix.sync.aligned.m8n8.x4.shared.b16 {%0,%1,%2,%3}, [%4];"
        : "=r"(r[0]),"=r"(r[1]),"=r"(r[2]),"=r"(r[3]) : "r"(addr));
}
__device__ __forceinline__ void ldsm4t(uint32_t* r, uint32_t addr){
    asm volatile("ldmatrix.sync.aligned.m8n8.x4.trans.shared.b16 {%0,%1,%2,%3}, [%4];"
        : "=r"(r[0]),"=r"(r[1]),"=r"(r[2]),"=r"(r[3]) : "r"(addr));
}
__device__ __forceinline__ void mma16816(float* c, const uint32_t* a, uint32_t b0, uint32_t b1){
    asm volatile("mma.sync.aligned.m16n8k16.row.col.f32.bf16.bf16.f32 "
        "{%0,%1,%2,%3}, {%4,%5,%6,%7}, {%8,%9}, {%0,%1,%2,%3};"
        : "+f"(c[0]),"+f"(c[1]),"+f"(c[2]),"+f"(c[3])
        : "r"(a[0]),"r"(a[1]),"r"(a[2]),"r"(a[3]), "r"(b0),"r"(b1));
}
#define SW(o)    ((o) ^ (((o)>>3)&0x30))   // 64B rows
#define SW128(o) ((o) ^ (((o)>>3)&0x70))   // 128B rows

__device__ __forceinline__ void split_store(float w, __nv_bfloat16* h, __nv_bfloat16* l, size_t i){
    __nv_bfloat16 hh = __float2bfloat16(w);
    h[i] = hh;
    l[i] = __float2bfloat16(w - __bfloat162float(hh));
}
__device__ __forceinline__ void splitpack(float x, float y, uint32_t& ph, uint32_t& pl){
    __nv_bfloat16 hx = __float2bfloat16(x), hy = __float2bfloat16(y);
    __nv_bfloat16 lx = __float2bfloat16(x - __bfloat162float(hx));
    __nv_bfloat16 ly = __float2bfloat16(y - __bfloat162float(hy));
    ph = ((uint32_t)__bfloat16_as_ushort(hy) << 16) | __bfloat16_as_ushort(hx);
    pl = ((uint32_t)__bfloat16_as_ushort(ly) << 16) | __bfloat16_as_ushort(lx);
}

// ---------------- RoPE table (mimic jax fp32 math) ----------------
__global__ void rope_table_k() {
    int i = blockIdx.x * 256 + threadIdx.x;
    int pos = i >> 5;
    int j   = i & 31;
    float invf = (float)pow(10000.0, -(double)(2 * j) / 64.0);
    float ang  = (float)pos * invf;
    g_cs[i] = cosf(ang);
    g_sn[i] = sinf(ang);
}

// ---------------- weight split fp32 -> bf16 hi/lo (4 elems/thread) ----------------
__global__ void split_k(const float* __restrict__ s, __nv_bfloat16* __restrict__ h,
                        __nv_bfloat16* __restrict__ l, int n4){
    int i = blockIdx.x * 256 + threadIdx.x;
    if (i < n4){
        float4 v = ((const float4*)s)[i];
        size_t base = (size_t)i * 4;
        split_store(v.x, h, l, base);
        split_store(v.y, h, l, base+1);
        split_store(v.z, h, l, base+2);
        split_store(v.w, h, l, base+3);
    }
}

// ---------------- RMSNorm -> bf16 hi/lo ----------------
__global__ __launch_bounds__(256) void rms_split_k(const float* __restrict__ x,
                                                   const float* __restrict__ g,
                                                   __nv_bfloat16* __restrict__ oh,
                                                   __nv_bfloat16* __restrict__ ol) {
    int row = blockIdx.x;
    int t   = threadIdx.x;
    const float4* xr = (const float4*)(x + (size_t)row * DM);
    float4 xv = xr[t];
    float ss = xv.x*xv.x + xv.y*xv.y + xv.z*xv.z + xv.w*xv.w;
    #pragma unroll
    for (int off = 16; off > 0; off >>= 1)
        ss += __shfl_xor_sync(0xffffffffu, ss, off);
    __shared__ float warpsum[8];
    if ((t & 31) == 0) warpsum[t >> 5] = ss;
    __syncthreads();
    float tot = warpsum[0]+warpsum[1]+warpsum[2]+warpsum[3]
              + warpsum[4]+warpsum[5]+warpsum[6]+warpsum[7];
    float r = rsqrtf(tot * (1.0f / (float)DM) + 1e-5f);
    float4 gv = ((const float4*)g)[t];
    float v[4] = { xv.x*r*gv.x, xv.y*r*gv.y, xv.z*r*gv.z, xv.w*r*gv.w };
    size_t base = (size_t)row * DM + t * 4;
    #pragma unroll
    for (int k = 0; k < 4; k++) split_store(v[k], oh, ol, base+k);
}

// ---------------- MMA GEMM NT: C[M,N] = A[M,K]*B[N,K]^T (bf16-split x3) ----------------
#define EPI_NONE       0
#define EPI_ROPE       1   // -> bf16 split [b,h,s,dk], rope, *scale
#define EPI_BHSD       2   // -> bf16 split [b,h,s,dk]
#define EPI_ADD        3
#define EPI_SILU_SPLIT 4

#define STG_BYTES 32768          // Ah(8K) Al(8K) Bh(8K) Bl(8K)
#define GEMM_SMEM (3*STG_BYTES)  // 96 KB, 3 stages

template<int EPI>
__global__ __launch_bounds__(256, 1) void gemm_mma(
    const __nv_bfloat16* __restrict__ Ah, const __nv_bfloat16* __restrict__ Al,
    const __nv_bfloat16* __restrict__ Bh, const __nv_bfloat16* __restrict__ Bl,
    float* __restrict__ C, const float* __restrict__ other,
    __nv_bfloat16* __restrict__ Chi, __nv_bfloat16* __restrict__ Clo,
    int M, int N, int K, float scale)
{
    extern __shared__ char smem[];
    uint32_t sb = smem_u32(smem);
    const int tid  = threadIdx.x;
    const int lane = tid & 31;
    const int wid  = tid >> 5;
    const int wm   = wid & 1;
    const int wn   = wid >> 1;
    const int bn = blockIdx.x, bm = blockIdx.y;
    const int m0 = bm * 128, n0 = bn * 128;
    const int NC = K >> 5;

    float acc[4][4][4];
    #pragma unroll
    for (int i = 0; i < 4; i++)
        #pragma unroll
        for (int j = 0; j < 4; j++)
            #pragma unroll
            for (int k = 0; k < 4; k++) acc[i][j][k] = 0.0f;

    auto load_chunk = [&](int kc, int stage){
        uint32_t tb = sb + stage * STG_BYTES;
        int k0 = kc * 32;
        #pragma unroll
        for (int mtx = 0; mtx < 4; mtx++){
            const __nv_bfloat16* base = (mtx == 0) ? Ah : (mtx == 1) ? Al : (mtx == 2) ? Bh : Bl;
            int row0 = (mtx < 2) ? m0 : n0;
            #pragma unroll
            for (int j = 0; j < 2; j++){
                int i = j * 256 + tid;
                int r = i >> 2, c16 = i & 3;
                uint32_t o = (uint32_t)(r << 6) + (c16 << 4);
                cpa16(tb + (mtx << 13) + SW(o),
                      base + (size_t)(row0 + r) * K + k0 + c16 * 8);
            }
        }
        cp_commit();
    };

    load_chunk(0, 0);
    load_chunk(1, 1);

    for (int kc = 0; kc < NC; kc++){
        if (kc + 1 < NC) cp_wait1(); else cp_wait0();
        __syncthreads();
        uint32_t tb = sb + (kc % 3) * STG_BYTES;

        #pragma unroll
        for (int s = 0; s < 2; s++){
            uint32_t ah[4][4], al[4][4];
            #pragma unroll
            for (int t = 0; t < 4; t++){
                uint32_t o = (uint32_t)((wm*64 + t*16 + (lane & 15)) << 6)
                           + s*32 + ((lane >> 4) << 4);
                uint32_t so = SW(o);
                ldsm4(ah[t], tb + so);
                ldsm4(al[t], tb + 8192 + so);
            }
            uint32_t bh2[2][4], bl2[2][4];
            #pragma unroll
            for (int g = 0; g < 2; g++){
                uint32_t o = (uint32_t)((wn*32 + g*16 + (lane & 15)) << 6)
                           + s*32 + ((lane >> 4) << 4);
                uint32_t so = SW(o);
                ldsm4(bh2[g], tb + 16384 + so);
                ldsm4(bl2[g], tb + 24576 + so);
            }
            #pragma unroll
            for (int tm = 0; tm < 4; tm++)
                #pragma unroll
                for (int g = 0; g < 2; g++)
                    #pragma unroll
                    for (int j = 0; j < 2; j++){
                        int tn = g*2 + j;
                        mma16816(acc[tm][tn], ah[tm], bh2[g][j], bh2[g][j+2]);
                        mma16816(acc[tm][tn], ah[tm], bl2[g][j], bl2[g][j+2]);
                        mma16816(acc[tm][tn], al[tm], bh2[g][j], bh2[g][j+2]);
                    }
        }
        if (kc + 2 < NC) load_chunk(kc + 2, (kc + 2) % 3);
    }

    // ---------------- epilogue ----------------
    const int gid = lane >> 2, tig = lane & 3;
    #pragma unroll
    for (int tm = 0; tm < 4; tm++){
        #pragma unroll
        for (int half = 0; half < 2; half++){
            int m = m0 + wm*64 + tm*16 + gid + half*8;
            if (EPI == EPI_ROPE || EPI == EPI_BHSD){
                int pos = m & (SEQ - 1), b = m >> 11;
                #pragma unroll
                for (int tn = 0; tn < 4; tn++){
                    int c = n0 + wn*32 + tn*8 + tig*2;
                    int head = c >> 6, hi = c & 63;
                    size_t ob = ((size_t)(b * NH + head) * SEQ + pos) * DK + hi;
                    float v0 = acc[tm][tn][half*2];
                    float v1 = acc[tm][tn][half*2 + 1];
                    float w0, w1;
                    if (EPI == EPI_ROPE){
                        float cs = g_cs[pos * 32 + (hi >> 1)];
                        float sn = g_sn[pos * 32 + (hi >> 1)];
                        w0 = (v0 * cs - v1 * sn) * scale;
                        w1 = (v0 * sn + v1 * cs) * scale;
                    } else { w0 = v0; w1 = v1; }
                    split_store(w0, Chi, Clo, ob);
                    split_store(w1, Chi, Clo, ob + 1);
                }
            } else {
                #pragma unroll
                for (int tn = 0; tn < 4; tn++){
                    int c = n0 + wn*32 + tn*8 + tig*2;
                    size_t base = (size_t)m * N + c;
                    float v0 = acc[tm][tn][half*2];
                    float v1 = acc[tm][tn][half*2 + 1];
                    if (EPI == EPI_ADD){
                        C[base]     = other[base] + v0;
                        C[base + 1] = other[base + 1] + v1;
                    } else if (EPI == EPI_NONE){
                        C[base]     = v0;
                        C[base + 1] = v1;
                    } else {
                        float u0 = other[base], u1 = other[base + 1];
                        float w0 = v0 * u0 / (1.0f + __expf(-u0));
                        float w1 = v1 * u1 / (1.0f + __expf(-u1));
                        split_store(w0, Chi, Clo, base);
                        split_store(w1, Chi, Clo, base + 1);
                    }
                }
            }
        }
    }
}

// ---------------- Tensor-core flash attention (causal, bf16-split x3) ----------------
// CTA: 128 queries, 8 warps x 16 rows. K/V tiles of 64 keys, 3-stage cp.async.
// smem: Q hi(16K) lo(16K) @0; KV stages @32K: [Kh 8K | Kl 8K | Vh 8K | Vl 8K] x3
#define FA_SMEM (32768 + 3*32768)

__global__ __launch_bounds__(256, 1) void flash_tc(
    const __nv_bfloat16* __restrict__ Qh_, const __nv_bfloat16* __restrict__ Ql_,
    const __nv_bfloat16* __restrict__ Kh_, const __nv_bfloat16* __restrict__ Kl_,
    const __nv_bfloat16* __restrict__ Vh_, const __nv_bfloat16* __restrict__ Vl_,
    __nv_bfloat16* __restrict__ Oh, __nv_bfloat16* __restrict__ Ol)
{
    extern __shared__ char smem[];
    uint32_t sb = smem_u32(smem);
    const int tid  = threadIdx.x;
    const int lane = tid & 31;
    const int w    = tid >> 5;
    const int gid  = lane >> 2, tig = lane & 3;
    const int qt   = (int)gridDim.x - 1 - (int)blockIdx.x;   // heavy tiles first
    const int bh   = blockIdx.y;
    const int b    = bh >> 4, head = bh & 15;
    const size_t base = (size_t)bh * SEQ * DK;
    const int q0 = qt * 128;
    const int NT = 2 * qt + 2;

    // ---- Q load (group 0) ----
    #pragma unroll
    for (int m = 0; m < 2; m++){
        const __nv_bfloat16* src = m ? Ql_ : Qh_;
        #pragma unroll
        for (int j = 0; j < 4; j++){
            int i = j * 256 + tid;            // 0..1023
            int r = i >> 3, c16 = i & 7;
            cpa16(sb + (m << 14) + SW128((r << 7) + (c16 << 4)),
                  src + base + (size_t)(q0 + r) * DK + c16 * 8);
        }
    }
    cp_commit();

    auto load_kv = [&](int kt, int stage){
        uint32_t tb = sb + 32768 + stage * 32768;
        size_t kb = base + (size_t)kt * 64 * DK;
        #pragma unroll
        for (int m = 0; m < 4; m++){
            const __nv_bfloat16* src = (m==0)?Kh_:(m==1)?Kl_:(m==2)?Vh_:Vl_;
            #pragma unroll
            for (int j = 0; j < 2; j++){
                int i = j * 256 + tid;        // 0..511
                int r = i >> 3, c16 = i & 7;
                cpa16(tb + (m << 13) + SW128((r << 7) + (c16 << 4)),
                      src + kb + (size_t)r * DK + c16 * 8);
            }
        }
        cp_commit();
    };
    load_kv(0, 0);
    load_kv(1, 1);

    cp_wait2();                 // Q ready
    __syncthreads();

    // ---- Q fragments ----
    uint32_t qh[4][4], ql[4][4];
    #pragma unroll
    for (int s = 0; s < 4; s++){
        uint32_t o = (uint32_t)((w*16 + (lane & 15)) << 7) + s*32 + ((lane >> 4) << 4);
        uint32_t so = SW128(o);
        ldsm4(qh[s], sb + so);
        ldsm4(ql[s], sb + 16384 + so);
    }

    float oacc[8][4];
    #pragma unroll
    for (int i = 0; i < 8; i++)
        #pragma unroll
        for (int j = 0; j < 4; j++) oacc[i][j] = 0.0f;
    float m0 = -1e30f, m1 = -1e30f, l0 = 0.0f, l1 = 0.0f;
    const int qrow0 = q0 + w * 16;

    for (int kt = 0; kt < NT; kt++){
        if (kt + 1 < NT) cp_wait1(); else cp_wait0();
        __syncthreads();
        uint32_t tb = sb + 32768 + (kt % 3) * 32768;

        // ---- S = Q K^T ----
        float sc[8][4];
        #pragma unroll
        for (int i = 0; i < 8; i++)
            #pragma unroll
            for (int j = 0; j < 4; j++) sc[i][j] = 0.0f;

        #pragma unroll
        for (int s = 0; s < 4; s++){
            #pragma unroll
            for (int g = 0; g < 4; g++){
                uint32_t o = (uint32_t)((g*16 + (lane & 15)) << 7) + s*32 + ((lane >> 4) << 4);
                uint32_t so = SW128(o);
                uint32_t kh[4], kl[4];
                ldsm4(kh, tb + so);
                ldsm4(kl, tb + 8192 + so);
                #pragma unroll
                for (int j = 0; j < 2; j++){
                    int tn = g*2 + j;
                    mma16816(sc[tn], qh[s], kh[j], kh[j+2]);
                    mma16816(sc[tn], qh[s], kl[j], kl[j+2]);
                    mma16816(sc[tn], ql[s], kh[j], kh[j+2]);
                }
            }
        }

        // ---- causal mask (diagonal region only) ----
        if (kt*64 + 63 > qrow0){
            int r0 = qrow0 + gid, r1 = r0 + 8;
            #pragma unroll
            for (int tn = 0; tn < 8; tn++){
                int key = kt*64 + tn*8 + tig*2;
                if (key     > r0) sc[tn][0] = -1e9f;
                if (key + 1 > r0) sc[tn][1] = -1e9f;
                if (key     > r1) sc[tn][2] = -1e9f;
                if (key + 1 > r1) sc[tn][3] = -1e9f;
            }
        }

        // ---- online softmax ----
        float t0 = -1e30f, t1 = -1e30f;
        #pragma unroll
        for (int tn = 0; tn < 8; tn++){
            t0 = fmaxf(t0, fmaxf(sc[tn][0], sc[tn][1]));
            t1 = fmaxf(t1, fmaxf(sc[tn][2], sc[tn][3]));
        }
        t0 = fmaxf(t0, __shfl_xor_sync(0xffffffffu, t0, 1));
        t0 = fmaxf(t0, __shfl_xor_sync(0xffffffffu, t0, 2));
        t1 = fmaxf(t1, __shfl_xor_sync(0xffffffffu, t1, 1));
        t1 = fmaxf(t1, __shfl_xor_sync(0xffffffffu, t1, 2));
        float nm0 = fmaxf(m0, t0), nm1 = fmaxf(m1, t1);
        float c0 = __expf(m0 - nm0), c1 = __expf(m1 - nm1);
        l0 *= c0; l1 *= c1;
        #pragma unroll
        for (int tn = 0; tn < 8; tn++){
            sc[tn][0] = __expf(sc[tn][0] - nm0);
            sc[tn][1] = __expf(sc[tn][1] - nm0);
            sc[tn][2] = __expf(sc[tn][2] - nm1);
            sc[tn][3] = __expf(sc[tn][3] - nm1);
            l0 += sc[tn][0] + sc[tn][1];
            l1 += sc[tn][2] + sc[tn][3];
        }
        #pragma unroll
        for (int od = 0; od < 8; od++){
            oacc[od][0] *= c0; oacc[od][1] *= c0;
            oacc[od][2] *= c1; oacc[od][3] *= c1;
        }
        m0 = nm0; m1 = nm1;

        // ---- P fragments (hi/lo) ----
        uint32_t ph[4][4], pl[4][4];
        #pragma unroll
        for (int s = 0; s < 4; s++){
            splitpack(sc[2*s][0],   sc[2*s][1],   ph[s][0], pl[s][0]);
            splitpack(sc[2*s][2],   sc[2*s][3],   ph[s][1], pl[s][1]);
            splitpack(sc[2*s+1][0], sc[2*s+1][1], ph[s][2], pl[s][2]);
            splitpack(sc[2*s+1][2], sc[2*s+1][3], ph[s][3], pl[s][3]);
        }

        // ---- O += P V ----
        #pragma unroll
        for (int s = 0; s < 4; s++){
            #pragma unroll
            for (int gd = 0; gd < 4; gd++){
                uint32_t row = s*16 + (lane & 7) + ((lane & 16) >> 1);
                uint32_t col = gd*16 + (lane & 8);
                uint32_t o = (row << 7) + (col << 1);
                uint32_t so = SW128(o);
                uint32_t vh[4], vl[4];
                ldsm4t(vh, tb + 16384 + so);
                ldsm4t(vl, tb + 24576 + so);
                #pragma unroll
                for (int j = 0; j < 2; j++){
                    int od = gd*2 + j;
                    mma16816(oacc[od], ph[s], vh[j], vh[j+2]);
                    mma16816(oacc[od], ph[s], vl[j], vl[j+2]);
                    mma16816(oacc[od], pl[s], vh[j], vh[j+2]);
                }
            }
        }

        if (kt + 2 < NT) load_kv(kt + 2, (kt + 2) % 3);
    }

    // ---- finalize + write token-major bf16 split ----
    l0 += __shfl_xor_sync(0xffffffffu, l0, 1);
    l0 += __shfl_xor_sync(0xffffffffu, l0, 2);
    l1 += __shfl_xor_sync(0xffffffffu, l1, 1);
    l1 += __shfl_xor_sync(0xffffffffu, l1, 2);
    float inv0 = 1.0f / l0, inv1 = 1.0f / l1;

    int q = qrow0 + gid;
    size_t tk0 = (size_t)(b * SEQ + q) * DM + head * 64;
    size_t tk1 = tk0 + (size_t)8 * DM;
    #pragma unroll
    for (int od = 0; od < 8; od++){
        int d = od*8 + tig*2;
        split_store(oacc[od][0] * inv0, Oh, Ol, tk0 + d);
        split_store(oacc[od][1] * inv0, Oh, Ol, tk0 + d + 1);
        split_store(oacc[od][2] * inv1, Oh, Ol, tk1 + d);
        split_store(oacc[od][3] * inv1, Oh, Ol, tk1 + d + 1);
    }
}

// ---------------- launch ----------------
extern "C" void kernel_launch(void* const* d_in, const int* in_sizes, int n_in,
                              void* d_out, int out_size)
{
    const float* x  = (const float*)d_in[0];
    const float* Wq = (const float*)d_in[1];
    const float* Wk = (const float*)d_in[2];
    const float* Wv = (const float*)d_in[3];
    const float* Wo = (const float*)d_in[4];
    const float* g1 = (const float*)d_in[5];
    const float* g2 = (const float*)d_in[6];
    const float* W1 = (const float*)d_in[7];
    const float* W3 = (const float*)d_in[8];
    const float* W2 = (const float*)d_in[9];
    float* out = (float*)d_out;

    float *x1,*u;
    __nv_bfloat16 *hh,*hl,*ath,*atl,*h2h,*h2l,*gbh,*gbl,*wh,*wl;
    __nv_bfloat16 *qhh,*qhl,*khh,*khl,*vhh,*vhl;
    cudaGetSymbolAddress((void**)&x1,   g_x1);
    cudaGetSymbolAddress((void**)&u,    g_u);
    cudaGetSymbolAddress((void**)&hh,   g_hh);
    cudaGetSymbolAddress((void**)&hl,   g_hl);
    cudaGetSymbolAddress((void**)&ath,  g_ath);
    cudaGetSymbolAddress((void**)&atl,  g_atl);
    cudaGetSymbolAddress((void**)&h2h,  g_h2h);
    cudaGetSymbolAddress((void**)&h2l,  g_h2l);
    cudaGetSymbolAddress((void**)&gbh,  g_gbh);
    cudaGetSymbolAddress((void**)&gbl,  g_gbl);
    cudaGetSymbolAddress((void**)&wh,   g_wh);
    cudaGetSymbolAddress((void**)&wl,   g_wl);
    cudaGetSymbolAddress((void**)&qhh,  g_qhh);
    cudaGetSymbolAddress((void**)&qhl,  g_qhl);
    cudaGetSymbolAddress((void**)&khh,  g_khh);
    cudaGetSymbolAddress((void**)&khl,  g_khl);
    cudaGetSymbolAddress((void**)&vhh,  g_vhh);
    cudaGetSymbolAddress((void**)&vhl,  g_vhl);

    cudaFuncSetAttribute(gemm_mma<EPI_NONE>,       cudaFuncAttributeMaxDynamicSharedMemorySize, GEMM_SMEM);
    cudaFuncSetAttribute(gemm_mma<EPI_ROPE>,       cudaFuncAttributeMaxDynamicSharedMemorySize, GEMM_SMEM);
    cudaFuncSetAttribute(gemm_mma<EPI_BHSD>,       cudaFuncAttributeMaxDynamicSharedMemorySize, GEMM_SMEM);
    cudaFuncSetAttribute(gemm_mma<EPI_ADD>,        cudaFuncAttributeMaxDynamicSharedMemorySize, GEMM_SMEM);
    cudaFuncSetAttribute(gemm_mma<EPI_SILU_SPLIT>, cudaFuncAttributeMaxDynamicSharedMemorySize, GEMM_SMEM);
    cudaFuncSetAttribute(flash_tc,                 cudaFuncAttributeMaxDynamicSharedMemorySize, FA_SMEM);

    const int MEG = 1 << 20;
    rope_table_k<<<SEQ * 32 / 256, 256>>>();
    split_k<<<(1*MEG/4)/256, 256>>>(Wq, wh + WOFF_Q, wl + WOFF_Q, 1*MEG/4);
    split_k<<<(1*MEG/4)/256, 256>>>(Wk, wh + WOFF_K, wl + WOFF_K, 1*MEG/4);
    split_k<<<(1*MEG/4)/256, 256>>>(Wv, wh + WOFF_V, wl + WOFF_V, 1*MEG/4);
    split_k<<<(1*MEG/4)/256, 256>>>(Wo, wh + WOFF_O, wl + WOFF_O, 1*MEG/4);
    split_k<<<(4*MEG/4)/256, 256>>>(W1, wh + WOFF_1, wl + WOFF_1, 4*MEG/4);
    split_k<<<(4*MEG/4)/256, 256>>>(W3, wh + WOFF_3, wl + WOFF_3, 4*MEG/4);
    split_k<<<(4*MEG/4)/256, 256>>>(W2, wh + WOFF_2, wl + WOFF_2, 4*MEG/4);

    rms_split_k<<<TOKENS, 256>>>(x, g1, hh, hl);

    dim3 gProj(DM / 128, TOKENS / 128);
    dim3 gFF(DFF / 128, TOKENS / 128);

    gemm_mma<EPI_ROPE><<<gProj, 256, GEMM_SMEM>>>(hh, hl, wh+WOFF_Q, wl+WOFF_Q, nullptr, nullptr, qhh, qhl, TOKENS, DM, DM, 0.125f);
    gemm_mma<EPI_ROPE><<<gProj, 256, GEMM_SMEM>>>(hh, hl, wh+WOFF_K, wl+WOFF_K, nullptr, nullptr, khh, khl, TOKENS, DM, DM, 1.0f);
    gemm_mma<EPI_BHSD><<<gProj, 256, GEMM_SMEM>>>(hh, hl, wh+WOFF_V, wl+WOFF_V, nullptr, nullptr, vhh, vhl, TOKENS, DM, DM, 1.0f);

    flash_tc<<<dim3(SEQ / 128, 2 * NH), 256, FA_SMEM>>>(qhh, qhl, khh, khl, vhh, vhl, ath, atl);

    gemm_mma<EPI_ADD><<<gProj, 256, GEMM_SMEM>>>(ath, atl, wh+WOFF_O, wl+WOFF_O, x1, x, nullptr, nullptr, TOKENS, DM, DM, 1.0f);
    rms_split_k<<<TOKENS, 256>>>(x1, g2, h2h, h2l);

    gemm_mma<EPI_NONE><<<gFF, 256, GEMM_SMEM>>>(h2h, h2l, wh+WOFF_1, wl+WOFF_1, u, nullptr, nullptr, nullptr, TOKENS, DFF, DM, 1.0f);
    gemm_mma<EPI_SILU_SPLIT><<<gFF, 256, GEMM_SMEM>>>(h2h, h2l, wh+WOFF_3, wl+WOFF_3, nullptr, u, gbh, gbl, TOKENS, DFF, DM, 1.0f);
    gemm_mma<EPI_ADD><<<gProj, 256, GEMM_SMEM>>>(gbh, gbl, wh+WOFF_2, wl+WOFF_2, out, x1, nullptr, nullptr, TOKENS, DM, DFF, 1.0f);
}

// round 5
// speedup vs baseline: 2.7532x; 1.0746x over previous
#include <cuda_runtime.h>
#include <cuda_bf16.h>
#include <math.h>
#include <stdint.h>

#define TOKENS 4096
#define DM     1024
#define DFF    4096
#define SEQ    2048
#define NH     16
#define DK     64

// ---------------- scratch (device globals; no allocation allowed) ----------------
__device__ float g_x1[TOKENS*DM];
__device__ float g_cs[SEQ*32];
__device__ float g_sn[SEQ*32];

// bf16 split activations
__device__ __nv_bfloat16 g_hh[TOKENS*DM],  g_hl[TOKENS*DM];    // rmsnorm1 out
__device__ __nv_bfloat16 g_ath[TOKENS*DM], g_atl[TOKENS*DM];   // attn out (token-major)
__device__ __nv_bfloat16 g_h2h[TOKENS*DM], g_h2l[TOKENS*DM];   // rmsnorm2 out
__device__ __nv_bfloat16 g_gbh[TOKENS*DFF], g_gbl[TOKENS*DFF]; // silu(u)*v
// Q/K/V bf16 split, [b,h,s,dk] layout
__device__ __nv_bfloat16 g_qhh[TOKENS*DM], g_qhl[TOKENS*DM];
__device__ __nv_bfloat16 g_khh[TOKENS*DM], g_khl[TOKENS*DM];
__device__ __nv_bfloat16 g_vhh[TOKENS*DM], g_vhl[TOKENS*DM];

// bf16 split weights, packed
#define WOFF_Q  0
#define WOFF_K  (1u<<20)
#define WOFF_V  (2u<<20)
#define WOFF_O  (3u<<20)
#define WOFF_1  (4u<<20)
#define WOFF_3  (8u<<20)
#define WOFF_2  (12u<<20)
__device__ __nv_bfloat16 g_wh[16u<<20];
__device__ __nv_bfloat16 g_wl[16u<<20];

// ---------------- helpers ----------------
__device__ __forceinline__ uint32_t smem_u32(const void* p){
    uint32_t r;
    asm("{ .reg .u64 t; cvta.to.shared.u64 t, %1; cvt.u32.u64 %0, t; }" : "=r"(r) : "l"(p));
    return r;
}
__device__ __forceinline__ void cpa16(uint32_t dst, const void* src){
    asm volatile("cp.async.cg.shared.global [%0], [%1], 16;" :: "r"(dst), "l"(src) : "memory");
}
__device__ __forceinline__ void cp_commit(){ asm volatile("cp.async.commit_group;" ::: "memory"); }
__device__ __forceinline__ void cp_wait2(){ asm volatile("cp.async.wait_group 2;" ::: "memory"); }
__device__ __forceinline__ void cp_wait1(){ asm volatile("cp.async.wait_group 1;" ::: "memory"); }
__device__ __forceinline__ void cp_wait0(){ asm volatile("cp.async.wait_group 0;" ::: "memory"); }

__device__ __forceinline__ void ldsm4(uint32_t* r, uint32_t addr){
    asm volatile("ldmatrix.sync.aligned.m8n8.x4.shared.b16 {%0,%1,%2,%3}, [%4];"
        : "=r"(r[0]),"=r"(r[1]),"=r"(r[2]),"=r"(r[3]) : "r"(addr));
}
__device__ __forceinline__ void ldsm4t(uint32_t* r, uint32_t addr){
    asm volatile("ldmatrix.sync.aligned.m8n8.x4.trans.shared.b16 {%0,%1,%2,%3}, [%4];"
        : "=r"(r[0]),"=r"(r[1]),"=r"(r[2]),"=r"(r[3]) : "r"(addr));
}
__device__ __forceinline__ void mma16816(float* c, const uint32_t* a, uint32_t b0, uint32_t b1){
    asm volatile("mma.sync.aligned.m16n8k16.row.col.f32.bf16.bf16.f32 "
        "{%0,%1,%2,%3}, {%4,%5,%6,%7}, {%8,%9}, {%0,%1,%2,%3};"
        : "+f"(c[0]),"+f"(c[1]),"+f"(c[2]),"+f"(c[3])
        : "r"(a[0]),"r"(a[1]),"r"(a[2]),"r"(a[3]), "r"(b0),"r"(b1));
}
#define SW(o)    ((o) ^ (((o)>>3)&0x30))   // 64B rows
#define SW128(o) ((o) ^ (((o)>>3)&0x70))   // 128B rows

__device__ __forceinline__ void split_store(float w, __nv_bfloat16* h, __nv_bfloat16* l, size_t i){
    __nv_bfloat16 hh = __float2bfloat16(w);
    h[i] = hh;
    l[i] = __float2bfloat16(w - __bfloat162float(hh));
}
__device__ __forceinline__ void splitpack(float x, float y, uint32_t& ph, uint32_t& pl){
    __nv_bfloat16 hx = __float2bfloat16(x), hy = __float2bfloat16(y);
    __nv_bfloat16 lx = __float2bfloat16(x - __bfloat162float(hx));
    __nv_bfloat16 ly = __float2bfloat16(y - __bfloat162float(hy));
    ph = ((uint32_t)__bfloat16_as_ushort(hy) << 16) | __bfloat16_as_ushort(hx);
    pl = ((uint32_t)__bfloat16_as_ushort(ly) << 16) | __bfloat16_as_ushort(lx);
}

// ---------------- RoPE table (mimic jax fp32 math) ----------------
__global__ void rope_table_k() {
    int i = blockIdx.x * 256 + threadIdx.x;
    int pos = i >> 5;
    int j   = i & 31;
    float invf = (float)pow(10000.0, -(double)(2 * j) / 64.0);
    float ang  = (float)pos * invf;
    g_cs[i] = cosf(ang);
    g_sn[i] = sinf(ang);
}

// ---------------- all weight splits in ONE kernel ----------------
// blocks: Q[0,1024) K[1024,2048) V[2048,3072) O[3072,4096) W1[4096,8192) W3[8192,12288) W2[12288,16384)
__global__ void split_all_k(const float* __restrict__ Wq, const float* __restrict__ Wk,
                            const float* __restrict__ Wv, const float* __restrict__ Wo,
                            const float* __restrict__ W1, const float* __restrict__ W3,
                            const float* __restrict__ W2,
                            __nv_bfloat16* __restrict__ wh, __nv_bfloat16* __restrict__ wl){
    int gb = blockIdx.x;
    const float* src; uint32_t woff; int lb;
    if (gb < 4096){
        int m = gb >> 10; lb = gb & 1023;
        src = (m==0)?Wq:(m==1)?Wk:(m==2)?Wv:Wo;
        woff = (uint32_t)m << 20;
    } else if (gb < 8192){ src = W1; woff = WOFF_1; lb = gb - 4096; }
    else if (gb < 12288){ src = W3; woff = WOFF_3; lb = gb - 8192; }
    else                { src = W2; woff = WOFF_2; lb = gb - 12288; }
    int i = lb * 256 + threadIdx.x;
    float4 v = ((const float4*)src)[i];
    size_t base = (size_t)woff + (size_t)i * 4;
    split_store(v.x, wh, wl, base);
    split_store(v.y, wh, wl, base+1);
    split_store(v.z, wh, wl, base+2);
    split_store(v.w, wh, wl, base+3);
}

// ---------------- RMSNorm -> bf16 hi/lo ----------------
__global__ __launch_bounds__(256) void rms_split_k(const float* __restrict__ x,
                                                   const float* __restrict__ g,
                                                   __nv_bfloat16* __restrict__ oh,
                                                   __nv_bfloat16* __restrict__ ol) {
    int row = blockIdx.x;
    int t   = threadIdx.x;
    const float4* xr = (const float4*)(x + (size_t)row * DM);
    float4 xv = xr[t];
    float ss = xv.x*xv.x + xv.y*xv.y + xv.z*xv.z + xv.w*xv.w;
    #pragma unroll
    for (int off = 16; off > 0; off >>= 1)
        ss += __shfl_xor_sync(0xffffffffu, ss, off);
    __shared__ float warpsum[8];
    if ((t & 31) == 0) warpsum[t >> 5] = ss;
    __syncthreads();
    float tot = warpsum[0]+warpsum[1]+warpsum[2]+warpsum[3]
              + warpsum[4]+warpsum[5]+warpsum[6]+warpsum[7];
    float r = rsqrtf(tot * (1.0f / (float)DM) + 1e-5f);
    float4 gv = ((const float4*)g)[t];
    float v[4] = { xv.x*r*gv.x, xv.y*r*gv.y, xv.z*r*gv.z, xv.w*r*gv.w };
    size_t base = (size_t)row * DM + t * 4;
    #pragma unroll
    for (int k = 0; k < 4; k++) split_store(v[k], oh, ol, base+k);
}

// ---------------- MMA GEMM NT: C[M,N] = A[M,K]*B[N,K]^T (bf16-split x3) ----------------
#define EPI_ROPE       1   // -> bf16 split [b,h,s,dk], rope, *scale
#define EPI_BHSD       2   // -> bf16 split [b,h,s,dk]
#define EPI_ADD        3

#define STG_BYTES 32768          // Ah(8K) Al(8K) Bh(8K) Bl(8K)
#define GEMM_SMEM (3*STG_BYTES)  // 96 KB, 3 stages

template<int EPI>
__global__ __launch_bounds__(256, 1) void gemm_mma(
    const __nv_bfloat16* __restrict__ Ah, const __nv_bfloat16* __restrict__ Al,
    const __nv_bfloat16* __restrict__ Bh, const __nv_bfloat16* __restrict__ Bl,
    float* __restrict__ C, const float* __restrict__ other,
    __nv_bfloat16* __restrict__ Chi, __nv_bfloat16* __restrict__ Clo,
    int M, int N, int K, float scale)
{
    extern __shared__ char smem[];
    uint32_t sb = smem_u32(smem);
    const int tid  = threadIdx.x;
    const int lane = tid & 31;
    const int wid  = tid >> 5;
    const int wm   = wid & 1;
    const int wn   = wid >> 1;
    const int bn = blockIdx.x, bm = blockIdx.y;
    const int m0 = bm * 128, n0 = bn * 128;
    const int NC = K >> 5;

    float acc[4][4][4];
    #pragma unroll
    for (int i = 0; i < 4; i++)
        #pragma unroll
        for (int j = 0; j < 4; j++)
            #pragma unroll
            for (int k = 0; k < 4; k++) acc[i][j][k] = 0.0f;

    auto load_chunk = [&](int kc, int stage){
        uint32_t tb = sb + stage * STG_BYTES;
        int k0 = kc * 32;
        #pragma unroll
        for (int mtx = 0; mtx < 4; mtx++){
            const __nv_bfloat16* base = (mtx == 0) ? Ah : (mtx == 1) ? Al : (mtx == 2) ? Bh : Bl;
            int row0 = (mtx < 2) ? m0 : n0;
            #pragma unroll
            for (int j = 0; j < 2; j++){
                int i = j * 256 + tid;
                int r = i >> 2, c16 = i & 3;
                uint32_t o = (uint32_t)(r << 6) + (c16 << 4);
                cpa16(tb + (mtx << 13) + SW(o),
                      base + (size_t)(row0 + r) * K + k0 + c16 * 8);
            }
        }
        cp_commit();
    };

    load_chunk(0, 0);
    load_chunk(1, 1);

    for (int kc = 0; kc < NC; kc++){
        if (kc + 1 < NC) cp_wait1(); else cp_wait0();
        __syncthreads();
        uint32_t tb = sb + (kc % 3) * STG_BYTES;

        #pragma unroll
        for (int s = 0; s < 2; s++){
            uint32_t ah[4][4], al[4][4];
            #pragma unroll
            for (int t = 0; t < 4; t++){
                uint32_t o = (uint32_t)((wm*64 + t*16 + (lane & 15)) << 6)
                           + s*32 + ((lane >> 4) << 4);
                uint32_t so = SW(o);
                ldsm4(ah[t], tb + so);
                ldsm4(al[t], tb + 8192 + so);
            }
            uint32_t bh2[2][4], bl2[2][4];
            #pragma unroll
            for (int g = 0; g < 2; g++){
                uint32_t o = (uint32_t)((wn*32 + g*16 + (lane & 15)) << 6)
                           + s*32 + ((lane >> 4) << 4);
                uint32_t so = SW(o);
                ldsm4(bh2[g], tb + 16384 + so);
                ldsm4(bl2[g], tb + 24576 + so);
            }
            // three independent passes: acc reuse distance = 16 MMAs
            #pragma unroll
            for (int tm = 0; tm < 4; tm++)
                #pragma unroll
                for (int g = 0; g < 2; g++)
                    #pragma unroll
                    for (int j = 0; j < 2; j++)
                        mma16816(acc[tm][g*2+j], ah[tm], bh2[g][j], bh2[g][j+2]);
            #pragma unroll
            for (int tm = 0; tm < 4; tm++)
                #pragma unroll
                for (int g = 0; g < 2; g++)
                    #pragma unroll
                    for (int j = 0; j < 2; j++)
                        mma16816(acc[tm][g*2+j], ah[tm], bl2[g][j], bl2[g][j+2]);
            #pragma unroll
            for (int tm = 0; tm < 4; tm++)
                #pragma unroll
                for (int g = 0; g < 2; g++)
                    #pragma unroll
                    for (int j = 0; j < 2; j++)
                        mma16816(acc[tm][g*2+j], al[tm], bh2[g][j], bh2[g][j+2]);
        }
        if (kc + 2 < NC) load_chunk(kc + 2, (kc + 2) % 3);
    }

    // ---------------- epilogue ----------------
    const int gid = lane >> 2, tig = lane & 3;
    #pragma unroll
    for (int tm = 0; tm < 4; tm++){
        #pragma unroll
        for (int half = 0; half < 2; half++){
            int m = m0 + wm*64 + tm*16 + gid + half*8;
            if (EPI == EPI_ROPE || EPI == EPI_BHSD){
                int pos = m & (SEQ - 1), b = m >> 11;
                #pragma unroll
                for (int tn = 0; tn < 4; tn++){
                    int c = n0 + wn*32 + tn*8 + tig*2;
                    int head = c >> 6, hi = c & 63;
                    size_t ob = ((size_t)(b * NH + head) * SEQ + pos) * DK + hi;
                    float v0 = acc[tm][tn][half*2];
                    float v1 = acc[tm][tn][half*2 + 1];
                    float w0, w1;
                    if (EPI == EPI_ROPE){
                        float cs = g_cs[pos * 32 + (hi >> 1)];
                        float sn = g_sn[pos * 32 + (hi >> 1)];
                        w0 = (v0 * cs - v1 * sn) * scale;
                        w1 = (v0 * sn + v1 * cs) * scale;
                    } else { w0 = v0; w1 = v1; }
                    split_store(w0, Chi, Clo, ob);
                    split_store(w1, Chi, Clo, ob + 1);
                }
            } else {
                #pragma unroll
                for (int tn = 0; tn < 4; tn++){
                    int c = n0 + wn*32 + tn*8 + tig*2;
                    size_t base = (size_t)m * N + c;
                    float v0 = acc[tm][tn][half*2];
                    float v1 = acc[tm][tn][half*2 + 1];
                    C[base]     = other[base] + v0;
                    C[base + 1] = other[base + 1] + v1;
                }
            }
        }
    }
}

// ---------------- fused W1/W3 GEMM + silu(u)*v -> bf16 split ----------------
#define W13_STG   49152            // A hi/lo 16K, B1 hi/lo 16K, B3 hi/lo 16K
#define W13_SMEM  (3*W13_STG)      // 144 KB

__global__ __launch_bounds__(256, 1) void gemm_w13(
    const __nv_bfloat16* __restrict__ Ah, const __nv_bfloat16* __restrict__ Al,
    const __nv_bfloat16* __restrict__ B1h, const __nv_bfloat16* __restrict__ B1l,
    const __nv_bfloat16* __restrict__ B3h, const __nv_bfloat16* __restrict__ B3l,
    __nv_bfloat16* __restrict__ Chi, __nv_bfloat16* __restrict__ Clo)
{
    extern __shared__ char smem[];
    uint32_t sb = smem_u32(smem);
    const int tid  = threadIdx.x;
    const int lane = tid & 31;
    const int wid  = tid >> 5;
    const int wm   = wid & 1;
    const int wn   = wid >> 1;
    const int bn = blockIdx.x, bm = blockIdx.y;
    const int m0 = bm * 128, n0 = bn * 128;
    const int NC = DM >> 5;     // 32
    const int K  = DM;

    float accU[4][4][4], accV[4][4][4];
    #pragma unroll
    for (int i = 0; i < 4; i++)
        #pragma unroll
        for (int j = 0; j < 4; j++)
            #pragma unroll
            for (int k = 0; k < 4; k++){ accU[i][j][k] = 0.0f; accV[i][j][k] = 0.0f; }

    auto load_chunk = [&](int kc, int stage){
        uint32_t tb = sb + stage * W13_STG;
        int k0 = kc * 32;
        #pragma unroll
        for (int mtx = 0; mtx < 6; mtx++){
            const __nv_bfloat16* base =
                (mtx==0)?Ah:(mtx==1)?Al:(mtx==2)?B1h:(mtx==3)?B1l:(mtx==4)?B3h:B3l;
            int row0 = (mtx < 2) ? m0 : n0;
            #pragma unroll
            for (int j = 0; j < 2; j++){
                int i = j * 256 + tid;
                int r = i >> 2, c16 = i & 3;
                uint32_t o = (uint32_t)(r << 6) + (c16 << 4);
                cpa16(tb + (mtx << 13) + SW(o),
                      base + (size_t)(row0 + r) * K + k0 + c16 * 8);
            }
        }
        cp_commit();
    };

    load_chunk(0, 0);
    load_chunk(1, 1);

    for (int kc = 0; kc < NC; kc++){
        if (kc + 1 < NC) cp_wait1(); else cp_wait0();
        __syncthreads();
        uint32_t tb = sb + (kc % 3) * W13_STG;

        #pragma unroll
        for (int s = 0; s < 2; s++){
            uint32_t ah[4][4], al[4][4];
            #pragma unroll
            for (int t = 0; t < 4; t++){
                uint32_t o = (uint32_t)((wm*64 + t*16 + (lane & 15)) << 6)
                           + s*32 + ((lane >> 4) << 4);
                uint32_t so = SW(o);
                ldsm4(ah[t], tb + so);
                ldsm4(al[t], tb + 8192 + so);
            }
            uint32_t bo = (uint32_t)((wn*32 + (lane & 15)) << 6) + s*32 + ((lane >> 4) << 4);
            uint32_t bo2 = (uint32_t)((wn*32 + 16 + (lane & 15)) << 6) + s*32 + ((lane >> 4) << 4);
            // ---- W1 ----
            {
                uint32_t bh2[2][4], bl2[2][4];
                ldsm4(bh2[0], tb + 16384 + SW(bo));
                ldsm4(bh2[1], tb + 16384 + SW(bo2));
                ldsm4(bl2[0], tb + 24576 + SW(bo));
                ldsm4(bl2[1], tb + 24576 + SW(bo2));
                #pragma unroll
                for (int tm = 0; tm < 4; tm++)
                    #pragma unroll
                    for (int g = 0; g < 2; g++)
                        #pragma unroll
                        for (int j = 0; j < 2; j++)
                            mma16816(accU[tm][g*2+j], ah[tm], bh2[g][j], bh2[g][j+2]);
                #pragma unroll
                for (int tm = 0; tm < 4; tm++)
                    #pragma unroll
                    for (int g = 0; g < 2; g++)
                        #pragma unroll
                        for (int j = 0; j < 2; j++)
                            mma16816(accU[tm][g*2+j], ah[tm], bl2[g][j], bl2[g][j+2]);
                #pragma unroll
                for (int tm = 0; tm < 4; tm++)
                    #pragma unroll
                    for (int g = 0; g < 2; g++)
                        #pragma unroll
                        for (int j = 0; j < 2; j++)
                            mma16816(accU[tm][g*2+j], al[tm], bh2[g][j], bh2[g][j+2]);
            }
            // ---- W3 ----
            {
                uint32_t bh2[2][4], bl2[2][4];
                ldsm4(bh2[0], tb + 32768 + SW(bo));
                ldsm4(bh2[1], tb + 32768 + SW(bo2));
                ldsm4(bl2[0], tb + 40960 + SW(bo));
                ldsm4(bl2[1], tb + 40960 + SW(bo2));
                #pragma unroll
                for (int tm = 0; tm < 4; tm++)
                    #pragma unroll
                    for (int g = 0; g < 2; g++)
                        #pragma unroll
                        for (int j = 0; j < 2; j++)
                            mma16816(accV[tm][g*2+j], ah[tm], bh2[g][j], bh2[g][j+2]);
                #pragma unroll
                for (int tm = 0; tm < 4; tm++)
                    #pragma unroll
                    for (int g = 0; g < 2; g++)
                        #pragma unroll
                        for (int j = 0; j < 2; j++)
                            mma16816(accV[tm][g*2+j], ah[tm], bl2[g][j], bl2[g][j+2]);
                #pragma unroll
                for (int tm = 0; tm < 4; tm++)
                    #pragma unroll
                    for (int g = 0; g < 2; g++)
                        #pragma unroll
                        for (int j = 0; j < 2; j++)
                            mma16816(accV[tm][g*2+j], al[tm], bh2[g][j], bh2[g][j+2]);
            }
        }
        if (kc + 2 < NC) load_chunk(kc + 2, (kc + 2) % 3);
    }

    const int gid = lane >> 2, tig = lane & 3;
    #pragma unroll
    for (int tm = 0; tm < 4; tm++){
        #pragma unroll
        for (int half = 0; half < 2; half++){
            int m = m0 + wm*64 + tm*16 + gid + half*8;
            #pragma unroll
            for (int tn = 0; tn < 4; tn++){
                int c = n0 + wn*32 + tn*8 + tig*2;
                size_t base = (size_t)m * DFF + c;
                float u0 = accU[tm][tn][half*2], u1 = accU[tm][tn][half*2+1];
                float v0 = accV[tm][tn][half*2], v1 = accV[tm][tn][half*2+1];
                float w0 = v0 * u0 / (1.0f + __expf(-u0));
                float w1 = v1 * u1 / (1.0f + __expf(-u1));
                split_store(w0, Chi, Clo, base);
                split_store(w1, Chi, Clo, base + 1);
            }
        }
    }
}

// ---------------- Tensor-core flash attention (causal, bf16-split x3) ----------------
#define FA_SMEM (32768 + 3*32768)

__global__ __launch_bounds__(256, 1) void flash_tc(
    const __nv_bfloat16* __restrict__ Qh_, const __nv_bfloat16* __restrict__ Ql_,
    const __nv_bfloat16* __restrict__ Kh_, const __nv_bfloat16* __restrict__ Kl_,
    const __nv_bfloat16* __restrict__ Vh_, const __nv_bfloat16* __restrict__ Vl_,
    __nv_bfloat16* __restrict__ Oh, __nv_bfloat16* __restrict__ Ol)
{
    extern __shared__ char smem[];
    uint32_t sb = smem_u32(smem);
    const int tid  = threadIdx.x;
    const int lane = tid & 31;
    const int w    = tid >> 5;
    const int gid  = lane >> 2, tig = lane & 3;
    const int qt   = (int)gridDim.x - 1 - (int)blockIdx.x;
    const int bh   = blockIdx.y;
    const int b    = bh >> 4, head = bh & 15;
    const size_t base = (size_t)bh * SEQ * DK;
    const int q0 = qt * 128;
    const int NT = 2 * qt + 2;

    #pragma unroll
    for (int m = 0; m < 2; m++){
        const __nv_bfloat16* src = m ? Ql_ : Qh_;
        #pragma unroll
        for (int j = 0; j < 4; j++){
            int i = j * 256 + tid;
            int r = i >> 3, c16 = i & 7;
            cpa16(sb + (m << 14) + SW128((r << 7) + (c16 << 4)),
                  src + base + (size_t)(q0 + r) * DK + c16 * 8);
        }
    }
    cp_commit();

    auto load_kv = [&](int kt, int stage){
        uint32_t tb = sb + 32768 + stage * 32768;
        size_t kb = base + (size_t)kt * 64 * DK;
        #pragma unroll
        for (int m = 0; m < 4; m++){
            const __nv_bfloat16* src = (m==0)?Kh_:(m==1)?Kl_:(m==2)?Vh_:Vl_;
            #pragma unroll
            for (int j = 0; j < 2; j++){
                int i = j * 256 + tid;
                int r = i >> 3, c16 = i & 7;
                cpa16(tb + (m << 13) + SW128((r << 7) + (c16 << 4)),
                      src + kb + (size_t)r * DK + c16 * 8);
            }
        }
        cp_commit();
    };
    load_kv(0, 0);
    load_kv(1, 1);

    cp_wait2();
    __syncthreads();

    uint32_t qh[4][4], ql[4][4];
    #pragma unroll
    for (int s = 0; s < 4; s++){
        uint32_t o = (uint32_t)((w*16 + (lane & 15)) << 7) + s*32 + ((lane >> 4) << 4);
        uint32_t so = SW128(o);
        ldsm4(qh[s], sb + so);
        ldsm4(ql[s], sb + 16384 + so);
    }

    float oacc[8][4];
    #pragma unroll
    for (int i = 0; i < 8; i++)
        #pragma unroll
        for (int j = 0; j < 4; j++) oacc[i][j] = 0.0f;
    float m0 = -1e30f, m1 = -1e30f, l0 = 0.0f, l1 = 0.0f;
    const int qrow0 = q0 + w * 16;

    for (int kt = 0; kt < NT; kt++){
        if (kt + 1 < NT) cp_wait1(); else cp_wait0();
        __syncthreads();
        uint32_t tb = sb + 32768 + (kt % 3) * 32768;

        // ---- S = Q K^T (3 independent passes per s) ----
        float sc[8][4];
        #pragma unroll
        for (int i = 0; i < 8; i++)
            #pragma unroll
            for (int j = 0; j < 4; j++) sc[i][j] = 0.0f;

        #pragma unroll
        for (int s = 0; s < 4; s++){
            uint32_t khf[4][4], klf[4][4];
            #pragma unroll
            for (int g = 0; g < 4; g++){
                uint32_t o = (uint32_t)((g*16 + (lane & 15)) << 7) + s*32 + ((lane >> 4) << 4);
                uint32_t so = SW128(o);
                ldsm4(khf[g], tb + so);
                ldsm4(klf[g], tb + 8192 + so);
            }
            #pragma unroll
            for (int g = 0; g < 4; g++)
                #pragma unroll
                for (int j = 0; j < 2; j++)
                    mma16816(sc[g*2+j], qh[s], khf[g][j], khf[g][j+2]);
            #pragma unroll
            for (int g = 0; g < 4; g++)
                #pragma unroll
                for (int j = 0; j < 2; j++)
                    mma16816(sc[g*2+j], qh[s], klf[g][j], klf[g][j+2]);
            #pragma unroll
            for (int g = 0; g < 4; g++)
                #pragma unroll
                for (int j = 0; j < 2; j++)
                    mma16816(sc[g*2+j], ql[s], khf[g][j], khf[g][j+2]);
        }

        if (kt*64 + 63 > qrow0){
            int r0 = qrow0 + gid, r1 = r0 + 8;
            #pragma unroll
            for (int tn = 0; tn < 8; tn++){
                int key = kt*64 + tn*8 + tig*2;
                if (key     > r0) sc[tn][0] = -1e9f;
                if (key + 1 > r0) sc[tn][1] = -1e9f;
                if (key     > r1) sc[tn][2] = -1e9f;
                if (key + 1 > r1) sc[tn][3] = -1e9f;
            }
        }

        float t0 = -1e30f, t1 = -1e30f;
        #pragma unroll
        for (int tn = 0; tn < 8; tn++){
            t0 = fmaxf(t0, fmaxf(sc[tn][0], sc[tn][1]));
            t1 = fmaxf(t1, fmaxf(sc[tn][2], sc[tn][3]));
        }
        t0 = fmaxf(t0, __shfl_xor_sync(0xffffffffu, t0, 1));
        t0 = fmaxf(t0, __shfl_xor_sync(0xffffffffu, t0, 2));
        t1 = fmaxf(t1, __shfl_xor_sync(0xffffffffu, t1, 1));
        t1 = fmaxf(t1, __shfl_xor_sync(0xffffffffu, t1, 2));
        float nm0 = fmaxf(m0, t0), nm1 = fmaxf(m1, t1);
        float c0 = __expf(m0 - nm0), c1 = __expf(m1 - nm1);
        l0 *= c0; l1 *= c1;
        #pragma unroll
        for (int tn = 0; tn < 8; tn++){
            sc[tn][0] = __expf(sc[tn][0] - nm0);
            sc[tn][1] = __expf(sc[tn][1] - nm0);
            sc[tn][2] = __expf(sc[tn][2] - nm1);
            sc[tn][3] = __expf(sc[tn][3] - nm1);
            l0 += sc[tn][0] + sc[tn][1];
            l1 += sc[tn][2] + sc[tn][3];
        }
        #pragma unroll
        for (int od = 0; od < 8; od++){
            oacc[od][0] *= c0; oacc[od][1] *= c0;
            oacc[od][2] *= c1; oacc[od][3] *= c1;
        }
        m0 = nm0; m1 = nm1;

        uint32_t ph[4][4], pl[4][4];
        #pragma unroll
        for (int s = 0; s < 4; s++){
            splitpack(sc[2*s][0],   sc[2*s][1],   ph[s][0], pl[s][0]);
            splitpack(sc[2*s][2],   sc[2*s][3],   ph[s][1], pl[s][1]);
            splitpack(sc[2*s+1][0], sc[2*s+1][1], ph[s][2], pl[s][2]);
            splitpack(sc[2*s+1][2], sc[2*s+1][3], ph[s][3], pl[s][3]);
        }

        // ---- O += P V (3 independent passes per s) ----
        #pragma unroll
        for (int s = 0; s < 4; s++){
            uint32_t vhf[4][4], vlf[4][4];
            #pragma unroll
            for (int gd = 0; gd < 4; gd++){
                uint32_t row = s*16 + (lane & 7) + ((lane & 16) >> 1);
                uint32_t col = gd*16 + (lane & 8);
                uint32_t o = (row << 7) + (col << 1);
                uint32_t so = SW128(o);
                ldsm4t(vhf[gd], tb + 16384 + so);
                ldsm4t(vlf[gd], tb + 24576 + so);
            }
            #pragma unroll
            for (int gd = 0; gd < 4; gd++)
                #pragma unroll
                for (int j = 0; j < 2; j++)
                    mma16816(oacc[gd*2+j], ph[s], vhf[gd][j], vhf[gd][j+2]);
            #pragma unroll
            for (int gd = 0; gd < 4; gd++)
                #pragma unroll
                for (int j = 0; j < 2; j++)
                    mma16816(oacc[gd*2+j], ph[s], vlf[gd][j], vlf[gd][j+2]);
            #pragma unroll
            for (int gd = 0; gd < 4; gd++)
                #pragma unroll
                for (int j = 0; j < 2; j++)
                    mma16816(oacc[gd*2+j], pl[s], vhf[gd][j], vhf[gd][j+2]);
        }

        if (kt + 2 < NT) load_kv(kt + 2, (kt + 2) % 3);
    }

    l0 += __shfl_xor_sync(0xffffffffu, l0, 1);
    l0 += __shfl_xor_sync(0xffffffffu, l0, 2);
    l1 += __shfl_xor_sync(0xffffffffu, l1, 1);
    l1 += __shfl_xor_sync(0xffffffffu, l1, 2);
    float inv0 = 1.0f / l0, inv1 = 1.0f / l1;

    int q = qrow0 + gid;
    size_t tk0 = (size_t)(b * SEQ + q) * DM + head * 64;
    size_t tk1 = tk0 + (size_t)8 * DM;
    #pragma unroll
    for (int od = 0; od < 8; od++){
        int d = od*8 + tig*2;
        split_store(oacc[od][0] * inv0, Oh, Ol, tk0 + d);
        split_store(oacc[od][1] * inv0, Oh, Ol, tk0 + d + 1);
        split_store(oacc[od][2] * inv1, Oh, Ol, tk1 + d);
        split_store(oacc[od][3] * inv1, Oh, Ol, tk1 + d + 1);
    }
}

// ---------------- launch ----------------
extern "C" void kernel_launch(void* const* d_in, const int* in_sizes, int n_in,
                              void* d_out, int out_size)
{
    const float* x  = (const float*)d_in[0];
    const float* Wq = (const float*)d_in[1];
    const float* Wk = (const float*)d_in[2];
    const float* Wv = (const float*)d_in[3];
    const float* Wo = (const float*)d_in[4];
    const float* g1 = (const float*)d_in[5];
    const float* g2 = (const float*)d_in[6];
    const float* W1 = (const float*)d_in[7];
    const float* W3 = (const float*)d_in[8];
    const float* W2 = (const float*)d_in[9];
    float* out = (float*)d_out;

    float *x1;
    __nv_bfloat16 *hh,*hl,*ath,*atl,*h2h,*h2l,*gbh,*gbl,*wh,*wl;
    __nv_bfloat16 *qhh,*qhl,*khh,*khl,*vhh,*vhl;
    cudaGetSymbolAddress((void**)&x1,   g_x1);
    cudaGetSymbolAddress((void**)&hh,   g_hh);
    cudaGetSymbolAddress((void**)&hl,   g_hl);
    cudaGetSymbolAddress((void**)&ath,  g_ath);
    cudaGetSymbolAddress((void**)&atl,  g_atl);
    cudaGetSymbolAddress((void**)&h2h,  g_h2h);
    cudaGetSymbolAddress((void**)&h2l,  g_h2l);
    cudaGetSymbolAddress((void**)&gbh,  g_gbh);
    cudaGetSymbolAddress((void**)&gbl,  g_gbl);
    cudaGetSymbolAddress((void**)&wh,   g_wh);
    cudaGetSymbolAddress((void**)&wl,   g_wl);
    cudaGetSymbolAddress((void**)&qhh,  g_qhh);
    cudaGetSymbolAddress((void**)&qhl,  g_qhl);
    cudaGetSymbolAddress((void**)&khh,  g_khh);
    cudaGetSymbolAddress((void**)&khl,  g_khl);
    cudaGetSymbolAddress((void**)&vhh,  g_vhh);
    cudaGetSymbolAddress((void**)&vhl,  g_vhl);

    cudaFuncSetAttribute(gemm_mma<EPI_ROPE>, cudaFuncAttributeMaxDynamicSharedMemorySize, GEMM_SMEM);
    cudaFuncSetAttribute(gemm_mma<EPI_BHSD>, cudaFuncAttributeMaxDynamicSharedMemorySize, GEMM_SMEM);
    cudaFuncSetAttribute(gemm_mma<EPI_ADD>,  cudaFuncAttributeMaxDynamicSharedMemorySize, GEMM_SMEM);
    cudaFuncSetAttribute(gemm_w13,           cudaFuncAttributeMaxDynamicSharedMemorySize, W13_SMEM);
    cudaFuncSetAttribute(flash_tc,           cudaFuncAttributeMaxDynamicSharedMemorySize, FA_SMEM);

    rope_table_k<<<SEQ * 32 / 256, 256>>>();
    split_all_k<<<16384, 256>>>(Wq, Wk, Wv, Wo, W1, W3, W2, wh, wl);

    rms_split_k<<<TOKENS, 256>>>(x, g1, hh, hl);

    dim3 gProj(DM / 128, TOKENS / 128);
    dim3 gFF(DFF / 128, TOKENS / 128);

    gemm_mma<EPI_ROPE><<<gProj, 256, GEMM_SMEM>>>(hh, hl, wh+WOFF_Q, wl+WOFF_Q, nullptr, nullptr, qhh, qhl, TOKENS, DM, DM, 0.125f);
    gemm_mma<EPI_ROPE><<<gProj, 256, GEMM_SMEM>>>(hh, hl, wh+WOFF_K, wl+WOFF_K, nullptr, nullptr, khh, khl, TOKENS, DM, DM, 1.0f);
    gemm_mma<EPI_BHSD><<<gProj, 256, GEMM_SMEM>>>(hh, hl, wh+WOFF_V, wl+WOFF_V, nullptr, nullptr, vhh, vhl, TOKENS, DM, DM, 1.0f);

    flash_tc<<<dim3(SEQ / 128, 2 * NH), 256, FA_SMEM>>>(qhh, qhl, khh, khl, vhh, vhl, ath, atl);

    gemm_mma<EPI_ADD><<<gProj, 256, GEMM_SMEM>>>(ath, atl, wh+WOFF_O, wl+WOFF_O, x1, x, nullptr, nullptr, TOKENS, DM, DM, 1.0f);
    rms_split_k<<<TOKENS, 256>>>(x1, g2, h2h, h2l);

    gemm_w13<<<gFF, 256, W13_SMEM>>>(h2h, h2l, wh+WOFF_1, wl+WOFF_1, wh+WOFF_3, wl+WOFF_3, gbh, gbl);
    gemm_mma<EPI_ADD><<<gProj, 256, GEMM_SMEM>>>(gbh, gbl, wh+WOFF_2, wl+WOFF_2, out, x1, nullptr, nullptr, TOKENS, DM, DFF, 1.0f);
}

// round 6
// speedup vs baseline: 2.8788x; 1.0456x over previous
#include <cuda_runtime.h>
#include <cuda_bf16.h>
#include <math.h>
#include <stdint.h>

#define TOKENS 4096
#define DM     1024
#define DFF    4096
#define SEQ    2048
#define NH     16
#define DK     64

// ---------------- scratch (device globals; no allocation allowed) ----------------
__device__ float g_x1[TOKENS*DM];
__device__ float g_cs[SEQ*32];
__device__ float g_sn[SEQ*32];

// bf16 split activations
__device__ __nv_bfloat16 g_hh[TOKENS*DM],  g_hl[TOKENS*DM];
__device__ __nv_bfloat16 g_ath[TOKENS*DM], g_atl[TOKENS*DM];
__device__ __nv_bfloat16 g_h2h[TOKENS*DM], g_h2l[TOKENS*DM];
__device__ __nv_bfloat16 g_gbh[TOKENS*DFF], g_gbl[TOKENS*DFF];
__device__ __nv_bfloat16 g_qhh[TOKENS*DM], g_qhl[TOKENS*DM];
__device__ __nv_bfloat16 g_khh[TOKENS*DM], g_khl[TOKENS*DM];
__device__ __nv_bfloat16 g_vhh[TOKENS*DM], g_vhl[TOKENS*DM];

// bf16 split weights, packed
#define WOFF_Q  0
#define WOFF_K  (1u<<20)
#define WOFF_V  (2u<<20)
#define WOFF_O  (3u<<20)
#define WOFF_1  (4u<<20)
#define WOFF_3  (8u<<20)
#define WOFF_2  (12u<<20)
__device__ __nv_bfloat16 g_wh[16u<<20];
__device__ __nv_bfloat16 g_wl[16u<<20];

// ---------------- helpers ----------------
__device__ __forceinline__ uint32_t smem_u32(const void* p){
    uint32_t r;
    asm("{ .reg .u64 t; cvta.to.shared.u64 t, %1; cvt.u32.u64 %0, t; }" : "=r"(r) : "l"(p));
    return r;
}
__device__ __forceinline__ void cpa16(uint32_t dst, const void* src){
    asm volatile("cp.async.cg.shared.global [%0], [%1], 16;" :: "r"(dst), "l"(src) : "memory");
}
__device__ __forceinline__ void cp_commit(){ asm volatile("cp.async.commit_group;" ::: "memory"); }
__device__ __forceinline__ void cp_wait2(){ asm volatile("cp.async.wait_group 2;" ::: "memory"); }
__device__ __forceinline__ void cp_wait1(){ asm volatile("cp.async.wait_group 1;" ::: "memory"); }
__device__ __forceinline__ void cp_wait0(){ asm volatile("cp.async.wait_group 0;" ::: "memory"); }

__device__ __forceinline__ void ldsm4(uint32_t* r, uint32_t addr){
    asm volatile("ldmatrix.sync.aligned.m8n8.x4.shared.b16 {%0,%1,%2,%3}, [%4];"
        : "=r"(r[0]),"=r"(r[1]),"=r"(r[2]),"=r"(r[3]) : "r"(addr));
}
__device__ __forceinline__ void ldsm4t(uint32_t* r, uint32_t addr){
    asm volatile("ldmatrix.sync.aligned.m8n8.x4.trans.shared.b16 {%0,%1,%2,%3}, [%4];"
        : "=r"(r[0]),"=r"(r[1]),"=r"(r[2]),"=r"(r[3]) : "r"(addr));
}
__device__ __forceinline__ void mma16816(float* c, const uint32_t* a, uint32_t b0, uint32_t b1){
    asm volatile("mma.sync.aligned.m16n8k16.row.col.f32.bf16.bf16.f32 "
        "{%0,%1,%2,%3}, {%4,%5,%6,%7}, {%8,%9}, {%0,%1,%2,%3};"
        : "+f"(c[0]),"+f"(c[1]),"+f"(c[2]),"+f"(c[3])
        : "r"(a[0]),"r"(a[1]),"r"(a[2]),"r"(a[3]), "r"(b0),"r"(b1));
}
#define SW(o)    ((o) ^ (((o)>>3)&0x30))   // 64B rows
#define SW128(o) ((o) ^ (((o)>>3)&0x70))   // 128B rows

__device__ __forceinline__ void split_store(float w, __nv_bfloat16* h, __nv_bfloat16* l, size_t i){
    __nv_bfloat16 hh = __float2bfloat16(w);
    h[i] = hh;
    l[i] = __float2bfloat16(w - __bfloat162float(hh));
}
__device__ __forceinline__ void splitpack(float x, float y, uint32_t& ph, uint32_t& pl){
    __nv_bfloat16 hx = __float2bfloat16(x), hy = __float2bfloat16(y);
    __nv_bfloat16 lx = __float2bfloat16(x - __bfloat162float(hx));
    __nv_bfloat16 ly = __float2bfloat16(y - __bfloat162float(hy));
    ph = ((uint32_t)__bfloat16_as_ushort(hy) << 16) | __bfloat16_as_ushort(hx);
    pl = ((uint32_t)__bfloat16_as_ushort(ly) << 16) | __bfloat16_as_ushort(lx);
}

// ---------------- RoPE table ----------------
__global__ void rope_table_k() {
    __shared__ float invf[32];
    int t = threadIdx.x;
    if (t < 32) invf[t] = (float)pow(10000.0, -(double)(2 * t) / 64.0);
    __syncthreads();
    int i = blockIdx.x * 256 + t;
    int pos = i >> 5;
    int j   = i & 31;
    float ang = (float)pos * invf[j];
    g_cs[i] = cosf(ang);
    g_sn[i] = sinf(ang);
}

// ---------------- all weight splits, vectorized ----------------
// 4096 blocks: proj 4x256, W1/W3/W2 1024 each. 16 elems/thread, packed uint2 stores.
__global__ void split_all_k(const float* __restrict__ Wq, const float* __restrict__ Wk,
                            const float* __restrict__ Wv, const float* __restrict__ Wo,
                            const float* __restrict__ W1, const float* __restrict__ W3,
                            const float* __restrict__ W2,
                            __nv_bfloat16* __restrict__ wh, __nv_bfloat16* __restrict__ wl){
    int gb = blockIdx.x;
    const float* src; uint32_t woff; int lb;
    if (gb < 1024){
        int m = gb >> 8; lb = gb & 255;
        src = (m==0)?Wq:(m==1)?Wk:(m==2)?Wv:Wo;
        woff = (uint32_t)m << 20;
    } else if (gb < 2048){ src = W1; woff = WOFF_1; lb = gb - 1024; }
    else if (gb < 3072){ src = W3; woff = WOFF_3; lb = gb - 2048; }
    else               { src = W2; woff = WOFF_2; lb = gb - 3072; }
    uint2* hp = (uint2*)(wh + woff);
    uint2* lp = (uint2*)(wl + woff);
    #pragma unroll
    for (int j = 0; j < 4; j++){
        int i4 = lb * 1024 + j * 256 + threadIdx.x;
        float4 v = ((const float4*)src)[i4];
        uint32_t h01, l01, h23, l23;
        splitpack(v.x, v.y, h01, l01);
        splitpack(v.z, v.w, h23, l23);
        hp[i4] = make_uint2(h01, h23);
        lp[i4] = make_uint2(l01, l23);
    }
}

// ---------------- RMSNorm -> bf16 hi/lo ----------------
__global__ __launch_bounds__(256) void rms_split_k(const float* __restrict__ x,
                                                   const float* __restrict__ g,
                                                   __nv_bfloat16* __restrict__ oh,
                                                   __nv_bfloat16* __restrict__ ol) {
    int row = blockIdx.x;
    int t   = threadIdx.x;
    const float4* xr = (const float4*)(x + (size_t)row * DM);
    float4 xv = xr[t];
    float ss = xv.x*xv.x + xv.y*xv.y + xv.z*xv.z + xv.w*xv.w;
    #pragma unroll
    for (int off = 16; off > 0; off >>= 1)
        ss += __shfl_xor_sync(0xffffffffu, ss, off);
    __shared__ float warpsum[8];
    if ((t & 31) == 0) warpsum[t >> 5] = ss;
    __syncthreads();
    float tot = warpsum[0]+warpsum[1]+warpsum[2]+warpsum[3]
              + warpsum[4]+warpsum[5]+warpsum[6]+warpsum[7];
    float r = rsqrtf(tot * (1.0f / (float)DM) + 1e-5f);
    float4 gv = ((const float4*)g)[t];
    float v[4] = { xv.x*r*gv.x, xv.y*r*gv.y, xv.z*r*gv.z, xv.w*r*gv.w };
    size_t base = (size_t)row * DM + t * 4;
    uint32_t h01, l01, h23, l23;
    splitpack(v[0], v[1], h01, l01);
    splitpack(v[2], v[3], h23, l23);
    *(uint2*)(oh + base) = make_uint2(h01, h23);
    *(uint2*)(ol + base) = make_uint2(l01, l23);
}

// ---------------- MMA GEMM NT (512 thr, CTA 128x128, warp 64x16, bf16-split x3) ----------------
#define EPI_ROPE       1
#define EPI_BHSD       2
#define EPI_ADD        3

#define STG_BYTES 32768          // Ah(8K) Al(8K) Bh(8K) Bl(8K)
#define GEMM_SMEM (3*STG_BYTES)  // 96 KB, 3 stages

template<int EPI>
__global__ __launch_bounds__(512, 1) void gemm_mma(
    const __nv_bfloat16* __restrict__ Ah, const __nv_bfloat16* __restrict__ Al,
    const __nv_bfloat16* __restrict__ Bh, const __nv_bfloat16* __restrict__ Bl,
    float* __restrict__ C, const float* __restrict__ other,
    __nv_bfloat16* __restrict__ Chi, __nv_bfloat16* __restrict__ Clo,
    int M, int N, int K, float scale)
{
    extern __shared__ char smem[];
    uint32_t sb = smem_u32(smem);
    const int tid  = threadIdx.x;
    const int lane = tid & 31;
    const int wid  = tid >> 5;        // 0..15
    const int wm   = wid & 1;         // 2 row-groups of 64
    const int wn   = wid >> 1;        // 8 col-groups of 16
    const int bn = blockIdx.x, bm = blockIdx.y;
    const int m0 = bm * 128, n0 = bn * 128;
    const int NC = K >> 5;

    float acc[4][2][4];
    #pragma unroll
    for (int i = 0; i < 4; i++)
        #pragma unroll
        for (int j = 0; j < 2; j++)
            #pragma unroll
            for (int k = 0; k < 4; k++) acc[i][j][k] = 0.0f;

    auto load_chunk = [&](int kc, int stage){
        uint32_t tb = sb + stage * STG_BYTES;
        int k0 = kc * 32;
        #pragma unroll
        for (int mtx = 0; mtx < 4; mtx++){
            const __nv_bfloat16* base = (mtx == 0) ? Ah : (mtx == 1) ? Al : (mtx == 2) ? Bh : Bl;
            int row0 = (mtx < 2) ? m0 : n0;
            int r = tid >> 2, c16 = tid & 3;          // 512 chunks, 1/thread
            uint32_t o = (uint32_t)(r << 6) + (c16 << 4);
            cpa16(tb + (mtx << 13) + SW(o),
                  base + (size_t)(row0 + r) * K + k0 + c16 * 8);
        }
        cp_commit();
    };

    load_chunk(0, 0);
    load_chunk(1, 1);

    for (int kc = 0; kc < NC; kc++){
        if (kc + 1 < NC) cp_wait1(); else cp_wait0();
        __syncthreads();
        uint32_t tb = sb + (kc % 3) * STG_BYTES;

        #pragma unroll
        for (int s = 0; s < 2; s++){
            uint32_t ah[4][4], al[4][4];
            #pragma unroll
            for (int t = 0; t < 4; t++){
                uint32_t o = (uint32_t)((wm*64 + t*16 + (lane & 15)) << 6)
                           + s*32 + ((lane >> 4) << 4);
                uint32_t so = SW(o);
                ldsm4(ah[t], tb + so);
                ldsm4(al[t], tb + 8192 + so);
            }
            uint32_t bh[4], bl[4];
            {
                uint32_t o = (uint32_t)((wn*16 + (lane & 15)) << 6)
                           + s*32 + ((lane >> 4) << 4);
                uint32_t so = SW(o);
                ldsm4(bh, tb + 16384 + so);
                ldsm4(bl, tb + 24576 + so);
            }
            #pragma unroll
            for (int t = 0; t < 4; t++)
                #pragma unroll
                for (int j = 0; j < 2; j++)
                    mma16816(acc[t][j], ah[t], bh[j], bh[j+2]);
            #pragma unroll
            for (int t = 0; t < 4; t++)
                #pragma unroll
                for (int j = 0; j < 2; j++)
                    mma16816(acc[t][j], ah[t], bl[j], bl[j+2]);
            #pragma unroll
            for (int t = 0; t < 4; t++)
                #pragma unroll
                for (int j = 0; j < 2; j++)
                    mma16816(acc[t][j], al[t], bh[j], bh[j+2]);
        }
        if (kc + 2 < NC) load_chunk(kc + 2, (kc + 2) % 3);
    }

    // ---------------- epilogue ----------------
    const int gid = lane >> 2, tig = lane & 3;
    #pragma unroll
    for (int tm = 0; tm < 4; tm++){
        #pragma unroll
        for (int half = 0; half < 2; half++){
            int m = m0 + wm*64 + tm*16 + gid + half*8;
            if (EPI == EPI_ROPE || EPI == EPI_BHSD){
                int pos = m & (SEQ - 1), b = m >> 11;
                #pragma unroll
                for (int tn = 0; tn < 2; tn++){
                    int c = n0 + wn*16 + tn*8 + tig*2;
                    int head = c >> 6, hi = c & 63;
                    size_t ob = ((size_t)(b * NH + head) * SEQ + pos) * DK + hi;
                    float v0 = acc[tm][tn][half*2];
                    float v1 = acc[tm][tn][half*2 + 1];
                    float w0, w1;
                    if (EPI == EPI_ROPE){
                        float cs = g_cs[pos * 32 + (hi >> 1)];
                        float sn = g_sn[pos * 32 + (hi >> 1)];
                        w0 = (v0 * cs - v1 * sn) * scale;
                        w1 = (v0 * sn + v1 * cs) * scale;
                    } else { w0 = v0; w1 = v1; }
                    split_store(w0, Chi, Clo, ob);
                    split_store(w1, Chi, Clo, ob + 1);
                }
            } else {
                #pragma unroll
                for (int tn = 0; tn < 2; tn++){
                    int c = n0 + wn*16 + tn*8 + tig*2;
                    size_t base = (size_t)m * N + c;
                    float v0 = acc[tm][tn][half*2];
                    float v1 = acc[tm][tn][half*2 + 1];
                    C[base]     = other[base] + v0;
                    C[base + 1] = other[base + 1] + v1;
                }
            }
        }
    }
}

// ---------------- fused W1/W3 GEMM + silu(u)*v -> bf16 split (512 thr) ----------------
#define W13_STG   49152            // A hi/lo 16K, B1 hi/lo 16K, B3 hi/lo 16K
#define W13_SMEM  (3*W13_STG)      // 144 KB

__global__ __launch_bounds__(512, 1) void gemm_w13(
    const __nv_bfloat16* __restrict__ Ah, const __nv_bfloat16* __restrict__ Al,
    const __nv_bfloat16* __restrict__ B1h, const __nv_bfloat16* __restrict__ B1l,
    const __nv_bfloat16* __restrict__ B3h, const __nv_bfloat16* __restrict__ B3l,
    __nv_bfloat16* __restrict__ Chi, __nv_bfloat16* __restrict__ Clo)
{
    extern __shared__ char smem[];
    uint32_t sb = smem_u32(smem);
    const int tid  = threadIdx.x;
    const int lane = tid & 31;
    const int wid  = tid >> 5;
    const int wm   = wid & 1;
    const int wn   = wid >> 1;
    const int bn = blockIdx.x, bm = blockIdx.y;
    const int m0 = bm * 128, n0 = bn * 128;
    const int NC = DM >> 5;
    const int K  = DM;

    float accU[4][2][4], accV[4][2][4];
    #pragma unroll
    for (int i = 0; i < 4; i++)
        #pragma unroll
        for (int j = 0; j < 2; j++)
            #pragma unroll
            for (int k = 0; k < 4; k++){ accU[i][j][k] = 0.0f; accV[i][j][k] = 0.0f; }

    auto load_chunk = [&](int kc, int stage){
        uint32_t tb = sb + stage * W13_STG;
        int k0 = kc * 32;
        #pragma unroll
        for (int mtx = 0; mtx < 6; mtx++){
            const __nv_bfloat16* base =
                (mtx==0)?Ah:(mtx==1)?Al:(mtx==2)?B1h:(mtx==3)?B1l:(mtx==4)?B3h:B3l;
            int row0 = (mtx < 2) ? m0 : n0;
            int r = tid >> 2, c16 = tid & 3;
            uint32_t o = (uint32_t)(r << 6) + (c16 << 4);
            cpa16(tb + (mtx << 13) + SW(o),
                  base + (size_t)(row0 + r) * K + k0 + c16 * 8);
        }
        cp_commit();
    };

    load_chunk(0, 0);
    load_chunk(1, 1);

    for (int kc = 0; kc < NC; kc++){
        if (kc + 1 < NC) cp_wait1(); else cp_wait0();
        __syncthreads();
        uint32_t tb = sb + (kc % 3) * W13_STG;

        #pragma unroll
        for (int s = 0; s < 2; s++){
            uint32_t ah[4][4], al[4][4];
            #pragma unroll
            for (int t = 0; t < 4; t++){
                uint32_t o = (uint32_t)((wm*64 + t*16 + (lane & 15)) << 6)
                           + s*32 + ((lane >> 4) << 4);
                uint32_t so = SW(o);
                ldsm4(ah[t], tb + so);
                ldsm4(al[t], tb + 8192 + so);
            }
            uint32_t bo = SW((uint32_t)((wn*16 + (lane & 15)) << 6)
                             + s*32 + ((lane >> 4) << 4));
            // ---- W1 ----
            {
                uint32_t bh[4], bl[4];
                ldsm4(bh, tb + 16384 + bo);
                ldsm4(bl, tb + 24576 + bo);
                #pragma unroll
                for (int t = 0; t < 4; t++)
                    #pragma unroll
                    for (int j = 0; j < 2; j++)
                        mma16816(accU[t][j], ah[t], bh[j], bh[j+2]);
                #pragma unroll
                for (int t = 0; t < 4; t++)
                    #pragma unroll
                    for (int j = 0; j < 2; j++)
                        mma16816(accU[t][j], ah[t], bl[j], bl[j+2]);
                #pragma unroll
                for (int t = 0; t < 4; t++)
                    #pragma unroll
                    for (int j = 0; j < 2; j++)
                        mma16816(accU[t][j], al[t], bh[j], bh[j+2]);
            }
            // ---- W3 ----
            {
                uint32_t bh[4], bl[4];
                ldsm4(bh, tb + 32768 + bo);
                ldsm4(bl, tb + 40960 + bo);
                #pragma unroll
                for (int t = 0; t < 4; t++)
                    #pragma unroll
                    for (int j = 0; j < 2; j++)
                        mma16816(accV[t][j], ah[t], bh[j], bh[j+2]);
                #pragma unroll
                for (int t = 0; t < 4; t++)
                    #pragma unroll
                    for (int j = 0; j < 2; j++)
                        mma16816(accV[t][j], ah[t], bl[j], bl[j+2]);
                #pragma unroll
                for (int t = 0; t < 4; t++)
                    #pragma unroll
                    for (int j = 0; j < 2; j++)
                        mma16816(accV[t][j], al[t], bh[j], bh[j+2]);
            }
        }
        if (kc + 2 < NC) load_chunk(kc + 2, (kc + 2) % 3);
    }

    const int gid = lane >> 2, tig = lane & 3;
    #pragma unroll
    for (int tm = 0; tm < 4; tm++){
        #pragma unroll
        for (int half = 0; half < 2; half++){
            int m = m0 + wm*64 + tm*16 + gid + half*8;
            #pragma unroll
            for (int tn = 0; tn < 2; tn++){
                int c = n0 + wn*16 + tn*8 + tig*2;
                size_t base = (size_t)m * DFF + c;
                float u0 = accU[tm][tn][half*2], u1 = accU[tm][tn][half*2+1];
                float v0 = accV[tm][tn][half*2], v1 = accV[tm][tn][half*2+1];
                float w0 = v0 * u0 / (1.0f + __expf(-u0));
                float w1 = v1 * u1 / (1.0f + __expf(-u1));
                split_store(w0, Chi, Clo, base);
                split_store(w1, Chi, Clo, base + 1);
            }
        }
    }
}

// ---------------- Tensor-core flash attention (causal, bf16-split x3) ----------------
#define FA_SMEM (32768 + 3*32768)

__global__ __launch_bounds__(256, 1) void flash_tc(
    const __nv_bfloat16* __restrict__ Qh_, const __nv_bfloat16* __restrict__ Ql_,
    const __nv_bfloat16* __restrict__ Kh_, const __nv_bfloat16* __restrict__ Kl_,
    const __nv_bfloat16* __restrict__ Vh_, const __nv_bfloat16* __restrict__ Vl_,
    __nv_bfloat16* __restrict__ Oh, __nv_bfloat16* __restrict__ Ol)
{
    extern __shared__ char smem[];
    uint32_t sb = smem_u32(smem);
    const int tid  = threadIdx.x;
    const int lane = tid & 31;
    const int w    = tid >> 5;
    const int gid  = lane >> 2, tig = lane & 3;
    const int qt   = (int)gridDim.x - 1 - (int)blockIdx.x;
    const int bh   = blockIdx.y;
    const int b    = bh >> 4, head = bh & 15;
    const size_t base = (size_t)bh * SEQ * DK;
    const int q0 = qt * 128;
    const int NT = 2 * qt + 2;

    #pragma unroll
    for (int m = 0; m < 2; m++){
        const __nv_bfloat16* src = m ? Ql_ : Qh_;
        #pragma unroll
        for (int j = 0; j < 4; j++){
            int i = j * 256 + tid;
            int r = i >> 3, c16 = i & 7;
            cpa16(sb + (m << 14) + SW128((r << 7) + (c16 << 4)),
                  src + base + (size_t)(q0 + r) * DK + c16 * 8);
        }
    }
    cp_commit();

    auto load_kv = [&](int kt, int stage){
        uint32_t tb = sb + 32768 + stage * 32768;
        size_t kb = base + (size_t)kt * 64 * DK;
        #pragma unroll
        for (int m = 0; m < 4; m++){
            const __nv_bfloat16* src = (m==0)?Kh_:(m==1)?Kl_:(m==2)?Vh_:Vl_;
            #pragma unroll
            for (int j = 0; j < 2; j++){
                int i = j * 256 + tid;
                int r = i >> 3, c16 = i & 7;
                cpa16(tb + (m << 13) + SW128((r << 7) + (c16 << 4)),
                      src + kb + (size_t)r * DK + c16 * 8);
            }
        }
        cp_commit();
    };
    load_kv(0, 0);
    load_kv(1, 1);

    cp_wait2();
    __syncthreads();

    uint32_t qh[4][4], ql[4][4];
    #pragma unroll
    for (int s = 0; s < 4; s++){
        uint32_t o = (uint32_t)((w*16 + (lane & 15)) << 7) + s*32 + ((lane >> 4) << 4);
        uint32_t so = SW128(o);
        ldsm4(qh[s], sb + so);
        ldsm4(ql[s], sb + 16384 + so);
    }

    float oacc[8][4];
    #pragma unroll
    for (int i = 0; i < 8; i++)
        #pragma unroll
        for (int j = 0; j < 4; j++) oacc[i][j] = 0.0f;
    float m0 = -1e30f, m1 = -1e30f, l0 = 0.0f, l1 = 0.0f;
    const int qrow0 = q0 + w * 16;

    for (int kt = 0; kt < NT; kt++){
        if (kt + 1 < NT) cp_wait1(); else cp_wait0();
        __syncthreads();
        uint32_t tb = sb + 32768 + (kt % 3) * 32768;

        float sc[8][4];
        #pragma unroll
        for (int i = 0; i < 8; i++)
            #pragma unroll
            for (int j = 0; j < 4; j++) sc[i][j] = 0.0f;

        #pragma unroll
        for (int s = 0; s < 4; s++){
            uint32_t khf[4][4], klf[4][4];
            #pragma unroll
            for (int g = 0; g < 4; g++){
                uint32_t o = (uint32_t)((g*16 + (lane & 15)) << 7) + s*32 + ((lane >> 4) << 4);
                uint32_t so = SW128(o);
                ldsm4(khf[g], tb + so);
                ldsm4(klf[g], tb + 8192 + so);
            }
            #pragma unroll
            for (int g = 0; g < 4; g++)
                #pragma unroll
                for (int j = 0; j < 2; j++)
                    mma16816(sc[g*2+j], qh[s], khf[g][j], khf[g][j+2]);
            #pragma unroll
            for (int g = 0; g < 4; g++)
                #pragma unroll
                for (int j = 0; j < 2; j++)
                    mma16816(sc[g*2+j], qh[s], klf[g][j], klf[g][j+2]);
            #pragma unroll
            for (int g = 0; g < 4; g++)
                #pragma unroll
                for (int j = 0; j < 2; j++)
                    mma16816(sc[g*2+j], ql[s], khf[g][j], khf[g][j+2]);
        }

        if (kt*64 + 63 > qrow0){
            int r0 = qrow0 + gid, r1 = r0 + 8;
            #pragma unroll
            for (int tn = 0; tn < 8; tn++){
                int key = kt*64 + tn*8 + tig*2;
                if (key     > r0) sc[tn][0] = -1e9f;
                if (key + 1 > r0) sc[tn][1] = -1e9f;
                if (key     > r1) sc[tn][2] = -1e9f;
                if (key + 1 > r1) sc[tn][3] = -1e9f;
            }
        }

        float t0 = -1e30f, t1 = -1e30f;
        #pragma unroll
        for (int tn = 0; tn < 8; tn++){
            t0 = fmaxf(t0, fmaxf(sc[tn][0], sc[tn][1]));
            t1 = fmaxf(t1, fmaxf(sc[tn][2], sc[tn][3]));
        }
        t0 = fmaxf(t0, __shfl_xor_sync(0xffffffffu, t0, 1));
        t0 = fmaxf(t0, __shfl_xor_sync(0xffffffffu, t0, 2));
        t1 = fmaxf(t1, __shfl_xor_sync(0xffffffffu, t1, 1));
        t1 = fmaxf(t1, __shfl_xor_sync(0xffffffffu, t1, 2));
        float nm0 = fmaxf(m0, t0), nm1 = fmaxf(m1, t1);
        float c0 = __expf(m0 - nm0), c1 = __expf(m1 - nm1);
        l0 *= c0; l1 *= c1;
        #pragma unroll
        for (int tn = 0; tn < 8; tn++){
            sc[tn][0] = __expf(sc[tn][0] - nm0);
            sc[tn][1] = __expf(sc[tn][1] - nm0);
            sc[tn][2] = __expf(sc[tn][2] - nm1);
            sc[tn][3] = __expf(sc[tn][3] - nm1);
            l0 += sc[tn][0] + sc[tn][1];
            l1 += sc[tn][2] + sc[tn][3];
        }
        #pragma unroll
        for (int od = 0; od < 8; od++){
            oacc[od][0] *= c0; oacc[od][1] *= c0;
            oacc[od][2] *= c1; oacc[od][3] *= c1;
        }
        m0 = nm0; m1 = nm1;

        uint32_t ph[4][4], pl[4][4];
        #pragma unroll
        for (int s = 0; s < 4; s++){
            splitpack(sc[2*s][0],   sc[2*s][1],   ph[s][0], pl[s][0]);
            splitpack(sc[2*s][2],   sc[2*s][3],   ph[s][1], pl[s][1]);
            splitpack(sc[2*s+1][0], sc[2*s+1][1], ph[s][2], pl[s][2]);
            splitpack(sc[2*s+1][2], sc[2*s+1][3], ph[s][3], pl[s][3]);
        }

        #pragma unroll
        for (int s = 0; s < 4; s++){
            uint32_t vhf[4][4], vlf[4][4];
            #pragma unroll
            for (int gd = 0; gd < 4; gd++){
                uint32_t row = s*16 + (lane & 7) + ((lane & 16) >> 1);
                uint32_t col = gd*16 + (lane & 8);
                uint32_t o = (row << 7) + (col << 1);
                uint32_t so = SW128(o);
                ldsm4t(vhf[gd], tb + 16384 + so);
                ldsm4t(vlf[gd], tb + 24576 + so);
            }
            #pragma unroll
            for (int gd = 0; gd < 4; gd++)
                #pragma unroll
                for (int j = 0; j < 2; j++)
                    mma16816(oacc[gd*2+j], ph[s], vhf[gd][j], vhf[gd][j+2]);
            #pragma unroll
            for (int gd = 0; gd < 4; gd++)
                #pragma unroll
                for (int j = 0; j < 2; j++)
                    mma16816(oacc[gd*2+j], ph[s], vlf[gd][j], vlf[gd][j+2]);
            #pragma unroll
            for (int gd = 0; gd < 4; gd++)
                #pragma unroll
                for (int j = 0; j < 2; j++)
                    mma16816(oacc[gd*2+j], pl[s], vhf[gd][j], vhf[gd][j+2]);
        }

        if (kt + 2 < NT) load_kv(kt + 2, (kt + 2) % 3);
    }

    l0 += __shfl_xor_sync(0xffffffffu, l0, 1);
    l0 += __shfl_xor_sync(0xffffffffu, l0, 2);
    l1 += __shfl_xor_sync(0xffffffffu, l1, 1);
    l1 += __shfl_xor_sync(0xffffffffu, l1, 2);
    float inv0 = 1.0f / l0, inv1 = 1.0f / l1;

    int q = qrow0 + gid;
    size_t tk0 = (size_t)(b * SEQ + q) * DM + head * 64;
    size_t tk1 = tk0 + (size_t)8 * DM;
    #pragma unroll
    for (int od = 0; od < 8; od++){
        int d = od*8 + tig*2;
        split_store(oacc[od][0] * inv0, Oh, Ol, tk0 + d);
        split_store(oacc[od][1] * inv0, Oh, Ol, tk0 + d + 1);
        split_store(oacc[od][2] * inv1, Oh, Ol, tk1 + d);
        split_store(oacc[od][3] * inv1, Oh, Ol, tk1 + d + 1);
    }
}

// ---------------- launch ----------------
extern "C" void kernel_launch(void* const* d_in, const int* in_sizes, int n_in,
                              void* d_out, int out_size)
{
    const float* x  = (const float*)d_in[0];
    const float* Wq = (const float*)d_in[1];
    const float* Wk = (const float*)d_in[2];
    const float* Wv = (const float*)d_in[3];
    const float* Wo = (const float*)d_in[4];
    const float* g1 = (const float*)d_in[5];
    const float* g2 = (const float*)d_in[6];
    const float* W1 = (const float*)d_in[7];
    const float* W3 = (const float*)d_in[8];
    const float* W2 = (const float*)d_in[9];
    float* out = (float*)d_out;

    float *x1;
    __nv_bfloat16 *hh,*hl,*ath,*atl,*h2h,*h2l,*gbh,*gbl,*wh,*wl;
    __nv_bfloat16 *qhh,*qhl,*khh,*khl,*vhh,*vhl;
    cudaGetSymbolAddress((void**)&x1,   g_x1);
    cudaGetSymbolAddress((void**)&hh,   g_hh);
    cudaGetSymbolAddress((void**)&hl,   g_hl);
    cudaGetSymbolAddress((void**)&ath,  g_ath);
    cudaGetSymbolAddress((void**)&atl,  g_atl);
    cudaGetSymbolAddress((void**)&h2h,  g_h2h);
    cudaGetSymbolAddress((void**)&h2l,  g_h2l);
    cudaGetSymbolAddress((void**)&gbh,  g_gbh);
    cudaGetSymbolAddress((void**)&gbl,  g_gbl);
    cudaGetSymbolAddress((void**)&wh,   g_wh);
    cudaGetSymbolAddress((void**)&wl,   g_wl);
    cudaGetSymbolAddress((void**)&qhh,  g_qhh);
    cudaGetSymbolAddress((void**)&qhl,  g_qhl);
    cudaGetSymbolAddress((void**)&khh,  g_khh);
    cudaGetSymbolAddress((void**)&khl,  g_khl);
    cudaGetSymbolAddress((void**)&vhh,  g_vhh);
    cudaGetSymbolAddress((void**)&vhl,  g_vhl);

    cudaFuncSetAttribute(gemm_mma<EPI_ROPE>, cudaFuncAttributeMaxDynamicSharedMemorySize, GEMM_SMEM);
    cudaFuncSetAttribute(gemm_mma<EPI_BHSD>, cudaFuncAttributeMaxDynamicSharedMemorySize, GEMM_SMEM);
    cudaFuncSetAttribute(gemm_mma<EPI_ADD>,  cudaFuncAttributeMaxDynamicSharedMemorySize, GEMM_SMEM);
    cudaFuncSetAttribute(gemm_w13,           cudaFuncAttributeMaxDynamicSharedMemorySize, W13_SMEM);
    cudaFuncSetAttribute(flash_tc,           cudaFuncAttributeMaxDynamicSharedMemorySize, FA_SMEM);

    rope_table_k<<<SEQ * 32 / 256, 256>>>();
    split_all_k<<<4096, 256>>>(Wq, Wk, Wv, Wo, W1, W3, W2, wh, wl);

    rms_split_k<<<TOKENS, 256>>>(x, g1, hh, hl);

    dim3 gProj(DM / 128, TOKENS / 128);
    dim3 gFF(DFF / 128, TOKENS / 128);

    gemm_mma<EPI_ROPE><<<gProj, 512, GEMM_SMEM>>>(hh, hl, wh+WOFF_Q, wl+WOFF_Q, nullptr, nullptr, qhh, qhl, TOKENS, DM, DM, 0.125f);
    gemm_mma<EPI_ROPE><<<gProj, 512, GEMM_SMEM>>>(hh, hl, wh+WOFF_K, wl+WOFF_K, nullptr, nullptr, khh, khl, TOKENS, DM, DM, 1.0f);
    gemm_mma<EPI_BHSD><<<gProj, 512, GEMM_SMEM>>>(hh, hl, wh+WOFF_V, wl+WOFF_V, nullptr, nullptr, vhh, vhl, TOKENS, DM, DM, 1.0f);

    flash_tc<<<dim3(SEQ / 128, 2 * NH), 256, FA_SMEM>>>(qhh, qhl, khh, khl, vhh, vhl, ath, atl);

    gemm_mma<EPI_ADD><<<gProj, 512, GEMM_SMEM>>>(ath, atl, wh+WOFF_O, wl+WOFF_O, x1, x, nullptr, nullptr, TOKENS, DM, DM, 1.0f);
    rms_split_k<<<TOKENS, 256>>>(x1, g2, h2h, h2l);

    gemm_w13<<<gFF, 512, W13_SMEM>>>(h2h, h2l, wh+WOFF_1, wl+WOFF_1, wh+WOFF_3, wl+WOFF_3, gbh, gbl);
    gemm_mma<EPI_ADD><<<gProj, 512, GEMM_SMEM>>>(gbh, gbl, wh+WOFF_2, wl+WOFF_2, out, x1, nullptr, nullptr, TOKENS, DM, DFF, 1.0f);
}

// round 7
// speedup vs baseline: 2.9953x; 1.0405x over previous
#include <cuda_runtime.h>
#include <cuda_bf16.h>
#include <math.h>
#include <stdint.h>

#define TOKENS 4096
#define DM     1024
#define DFF    4096
#define SEQ    2048
#define NH     16
#define DK     64

// ---------------- scratch (device globals; no allocation allowed) ----------------
__device__ float g_x1[TOKENS*DM];
__device__ float g_cs[SEQ*32];
__device__ float g_sn[SEQ*32];

__device__ __nv_bfloat16 g_hh[TOKENS*DM],  g_hl[TOKENS*DM];
__device__ __nv_bfloat16 g_ath[TOKENS*DM], g_atl[TOKENS*DM];
__device__ __nv_bfloat16 g_h2h[TOKENS*DM], g_h2l[TOKENS*DM];
__device__ __nv_bfloat16 g_gbh[TOKENS*DFF], g_gbl[TOKENS*DFF];
__device__ __nv_bfloat16 g_qhh[TOKENS*DM], g_qhl[TOKENS*DM];
__device__ __nv_bfloat16 g_khh[TOKENS*DM], g_khl[TOKENS*DM];
__device__ __nv_bfloat16 g_vhh[TOKENS*DM], g_vhl[TOKENS*DM];

// bf16 split weights, packed (Q,K,V contiguous => fused QKV GEMM over N=3072)
#define WOFF_Q  0
#define WOFF_K  (1u<<20)
#define WOFF_V  (2u<<20)
#define WOFF_O  (3u<<20)
#define WOFF_1  (4u<<20)
#define WOFF_3  (8u<<20)
#define WOFF_2  (12u<<20)
__device__ __nv_bfloat16 g_wh[16u<<20];
__device__ __nv_bfloat16 g_wl[16u<<20];

// ---------------- helpers ----------------
__device__ __forceinline__ uint32_t smem_u32(const void* p){
    uint32_t r;
    asm("{ .reg .u64 t; cvta.to.shared.u64 t, %1; cvt.u32.u64 %0, t; }" : "=r"(r) : "l"(p));
    return r;
}
__device__ __forceinline__ void cpa16(uint32_t dst, const void* src){
    asm volatile("cp.async.cg.shared.global [%0], [%1], 16;" :: "r"(dst), "l"(src) : "memory");
}
__device__ __forceinline__ void cp_commit(){ asm volatile("cp.async.commit_group;" ::: "memory"); }
__device__ __forceinline__ void cp_wait2(){ asm volatile("cp.async.wait_group 2;" ::: "memory"); }
__device__ __forceinline__ void cp_wait1(){ asm volatile("cp.async.wait_group 1;" ::: "memory"); }
__device__ __forceinline__ void cp_wait0(){ asm volatile("cp.async.wait_group 0;" ::: "memory"); }

__device__ __forceinline__ void ldsm4(uint32_t* r, uint32_t addr){
    asm volatile("ldmatrix.sync.aligned.m8n8.x4.shared.b16 {%0,%1,%2,%3}, [%4];"
        : "=r"(r[0]),"=r"(r[1]),"=r"(r[2]),"=r"(r[3]) : "r"(addr));
}
__device__ __forceinline__ void ldsm4t(uint32_t* r, uint32_t addr){
    asm volatile("ldmatrix.sync.aligned.m8n8.x4.trans.shared.b16 {%0,%1,%2,%3}, [%4];"
        : "=r"(r[0]),"=r"(r[1]),"=r"(r[2]),"=r"(r[3]) : "r"(addr));
}
__device__ __forceinline__ void mma16816(float* c, const uint32_t* a, uint32_t b0, uint32_t b1){
    asm volatile("mma.sync.aligned.m16n8k16.row.col.f32.bf16.bf16.f32 "
        "{%0,%1,%2,%3}, {%4,%5,%6,%7}, {%8,%9}, {%0,%1,%2,%3};"
        : "+f"(c[0]),"+f"(c[1]),"+f"(c[2]),"+f"(c[3])
        : "r"(a[0]),"r"(a[1]),"r"(a[2]),"r"(a[3]), "r"(b0),"r"(b1));
}
#define SW128(o) ((o) ^ (((o)>>3)&0x70))   // 128B rows

__device__ __forceinline__ void split_store(float w, __nv_bfloat16* h, __nv_bfloat16* l, size_t i){
    __nv_bfloat16 hh = __float2bfloat16(w);
    h[i] = hh;
    l[i] = __float2bfloat16(w - __bfloat162float(hh));
}
__device__ __forceinline__ void splitpack(float x, float y, uint32_t& ph, uint32_t& pl){
    __nv_bfloat16 hx = __float2bfloat16(x), hy = __float2bfloat16(y);
    __nv_bfloat16 lx = __float2bfloat16(x - __bfloat162float(hx));
    __nv_bfloat16 ly = __float2bfloat16(y - __bfloat162float(hy));
    ph = ((uint32_t)__bfloat16_as_ushort(hy) << 16) | __bfloat16_as_ushort(hx);
    pl = ((uint32_t)__bfloat16_as_ushort(ly) << 16) | __bfloat16_as_ushort(lx);
}

// ---------------- RoPE table ----------------
__global__ void rope_table_k() {
    __shared__ float invf[32];
    int t = threadIdx.x;
    if (t < 32) invf[t] = (float)pow(10000.0, -(double)(2 * t) / 64.0);
    __syncthreads();
    int i = blockIdx.x * 256 + t;
    int pos = i >> 5;
    int j   = i & 31;
    float ang = (float)pos * invf[j];
    g_cs[i] = cosf(ang);
    g_sn[i] = sinf(ang);
}

// ---------------- all weight splits, vectorized ----------------
__global__ void split_all_k(const float* __restrict__ Wq, const float* __restrict__ Wk,
                            const float* __restrict__ Wv, const float* __restrict__ Wo,
                            const float* __restrict__ W1, const float* __restrict__ W3,
                            const float* __restrict__ W2,
                            __nv_bfloat16* __restrict__ wh, __nv_bfloat16* __restrict__ wl){
    int gb = blockIdx.x;
    const float* src; uint32_t woff; int lb;
    if (gb < 1024){
        int m = gb >> 8; lb = gb & 255;
        src = (m==0)?Wq:(m==1)?Wk:(m==2)?Wv:Wo;
        woff = (uint32_t)m << 20;
    } else if (gb < 2048){ src = W1; woff = WOFF_1; lb = gb - 1024; }
    else if (gb < 3072){ src = W3; woff = WOFF_3; lb = gb - 2048; }
    else               { src = W2; woff = WOFF_2; lb = gb - 3072; }
    uint2* hp = (uint2*)(wh + woff);
    uint2* lp = (uint2*)(wl + woff);
    #pragma unroll
    for (int j = 0; j < 4; j++){
        int i4 = lb * 1024 + j * 256 + threadIdx.x;
        float4 v = ((const float4*)src)[i4];
        uint32_t h01, l01, h23, l23;
        splitpack(v.x, v.y, h01, l01);
        splitpack(v.z, v.w, h23, l23);
        hp[i4] = make_uint2(h01, h23);
        lp[i4] = make_uint2(l01, l23);
    }
}

// ---------------- RMSNorm -> bf16 hi/lo ----------------
__global__ __launch_bounds__(256) void rms_split_k(const float* __restrict__ x,
                                                   const float* __restrict__ g,
                                                   __nv_bfloat16* __restrict__ oh,
                                                   __nv_bfloat16* __restrict__ ol) {
    int row = blockIdx.x;
    int t   = threadIdx.x;
    const float4* xr = (const float4*)(x + (size_t)row * DM);
    float4 xv = xr[t];
    float ss = xv.x*xv.x + xv.y*xv.y + xv.z*xv.z + xv.w*xv.w;
    #pragma unroll
    for (int off = 16; off > 0; off >>= 1)
        ss += __shfl_xor_sync(0xffffffffu, ss, off);
    __shared__ float warpsum[8];
    if ((t & 31) == 0) warpsum[t >> 5] = ss;
    __syncthreads();
    float tot = warpsum[0]+warpsum[1]+warpsum[2]+warpsum[3]
              + warpsum[4]+warpsum[5]+warpsum[6]+warpsum[7];
    float r = rsqrtf(tot * (1.0f / (float)DM) + 1e-5f);
    float4 gv = ((const float4*)g)[t];
    float v[4] = { xv.x*r*gv.x, xv.y*r*gv.y, xv.z*r*gv.z, xv.w*r*gv.w };
    size_t base = (size_t)row * DM + t * 4;
    uint32_t h01, l01, h23, l23;
    splitpack(v[0], v[1], h01, l01);
    splitpack(v[2], v[3], h23, l23);
    *(uint2*)(oh + base) = make_uint2(h01, h23);
    *(uint2*)(ol + base) = make_uint2(l01, l23);
}

// =====================================================================
// Shared GEMM machinery: CTA 128x128, 512 thr, warp 64x16, BK=64,
// SW128-swizzled 128B rows. Stage = 4 matrices x 16 KB.
// =====================================================================
#define STG_BYTES 65536
#define GEMM_SMEM (3*STG_BYTES)   // 192 KB, 3 stages

// load one BK=64 chunk of Ah/Al/Bh/Bl into stage
__device__ __forceinline__ void g_load_chunk(
    uint32_t tb, int tid, int m0, int n0, int kc, int K,
    const __nv_bfloat16* Ah, const __nv_bfloat16* Al,
    const __nv_bfloat16* Bh, const __nv_bfloat16* Bl)
{
    int k0 = kc * 64;
    #pragma unroll
    for (int mtx = 0; mtx < 4; mtx++){
        const __nv_bfloat16* base = (mtx==0)?Ah:(mtx==1)?Al:(mtx==2)?Bh:Bl;
        int row0 = (mtx < 2) ? m0 : n0;
        #pragma unroll
        for (int j = 0; j < 2; j++){
            int i = j * 512 + tid;        // 1024 16B-chunks per matrix
            int r = i >> 3, c16 = i & 7;
            uint32_t o = (uint32_t)(r << 7) + (c16 << 4);
            cpa16(tb + (mtx << 14) + SW128(o),
                  base + (size_t)(row0 + r) * K + k0 + c16 * 8);
        }
    }
    cp_commit();
}

// compute one BK=64 chunk: acc[4][2][4], 3-pass split
__device__ __forceinline__ void g_compute_chunk(
    uint32_t tb, int lane, int wm, int wn, float acc[4][2][4])
{
    #pragma unroll
    for (int s = 0; s < 4; s++){
        uint32_t ah[4][4], al[4][4];
        #pragma unroll
        for (int t = 0; t < 4; t++){
            uint32_t o = (uint32_t)((wm*64 + t*16 + (lane & 15)) << 7)
                       + s*32 + ((lane >> 4) << 4);
            uint32_t so = SW128(o);
            ldsm4(ah[t], tb + so);
            ldsm4(al[t], tb + 16384 + so);
        }
        uint32_t bh[4], bl[4];
        {
            uint32_t o = (uint32_t)((wn*16 + (lane & 15)) << 7)
                       + s*32 + ((lane >> 4) << 4);
            uint32_t so = SW128(o);
            ldsm4(bh, tb + 32768 + so);
            ldsm4(bl, tb + 49152 + so);
        }
        #pragma unroll
        for (int t = 0; t < 4; t++)
            #pragma unroll
            for (int j = 0; j < 2; j++)
                mma16816(acc[t][j], ah[t], bh[j], bh[j+2]);
        #pragma unroll
        for (int t = 0; t < 4; t++)
            #pragma unroll
            for (int j = 0; j < 2; j++)
                mma16816(acc[t][j], ah[t], bl[j], bl[j+2]);
        #pragma unroll
        for (int t = 0; t < 4; t++)
            #pragma unroll
            for (int j = 0; j < 2; j++)
                mma16816(acc[t][j], al[t], bh[j], bh[j+2]);
    }
}

// ---------------- fused QKV GEMM: N=3072, epilogue rope/split by matrix ----------------
__global__ __launch_bounds__(512, 1) void gemm_qkv(
    const __nv_bfloat16* __restrict__ Ah, const __nv_bfloat16* __restrict__ Al,
    const __nv_bfloat16* __restrict__ Bh, const __nv_bfloat16* __restrict__ Bl,
    __nv_bfloat16* __restrict__ Qh, __nv_bfloat16* __restrict__ Ql,
    __nv_bfloat16* __restrict__ Kh, __nv_bfloat16* __restrict__ Kl,
    __nv_bfloat16* __restrict__ Vh, __nv_bfloat16* __restrict__ Vl)
{
    extern __shared__ char smem[];
    uint32_t sb = smem_u32(smem);
    const int tid  = threadIdx.x;
    const int lane = tid & 31;
    const int wid  = tid >> 5;
    const int wm   = wid & 1;
    const int wn   = wid >> 1;
    const int m0 = blockIdx.y * 128, n0 = blockIdx.x * 128;
    const int NC = DM / 64;   // 16
    const int K  = DM;

    float acc[4][2][4];
    #pragma unroll
    for (int i = 0; i < 4; i++)
        #pragma unroll
        for (int j = 0; j < 2; j++)
            #pragma unroll
            for (int k = 0; k < 4; k++) acc[i][j][k] = 0.0f;

    g_load_chunk(sb, tid, m0, n0, 0, K, Ah, Al, Bh, Bl);
    g_load_chunk(sb + STG_BYTES, tid, m0, n0, 1, K, Ah, Al, Bh, Bl);

    for (int kc = 0; kc < NC; kc++){
        if (kc + 1 < NC) cp_wait1(); else cp_wait0();
        __syncthreads();
        if (kc + 2 < NC)
            g_load_chunk(sb + ((kc+2)%3)*STG_BYTES, tid, m0, n0, kc+2, K, Ah, Al, Bh, Bl);
        g_compute_chunk(sb + (kc%3)*STG_BYTES, lane, wm, wn, acc);
    }

    // epilogue: whole CTA maps to ONE of Q/K/V (n0 aligned to 128 within 1024 blocks)
    const int mtx = n0 >> 10;          // 0=Q,1=K,2=V
    const float scl = (mtx == 0) ? 0.125f : 1.0f;
    __nv_bfloat16* Dh = (mtx==0)?Qh:(mtx==1)?Kh:Vh;
    __nv_bfloat16* Dl = (mtx==0)?Ql:(mtx==1)?Kl:Vl;
    const int gid = lane >> 2, tig = lane & 3;
    #pragma unroll
    for (int tm = 0; tm < 4; tm++){
        #pragma unroll
        for (int half = 0; half < 2; half++){
            int m = m0 + wm*64 + tm*16 + gid + half*8;
            int pos = m & (SEQ - 1), b = m >> 11;
            #pragma unroll
            for (int tn = 0; tn < 2; tn++){
                int cc = (n0 & 1023) + wn*16 + tn*8 + tig*2;
                int head = cc >> 6, hi = cc & 63;
                size_t ob = ((size_t)(b * NH + head) * SEQ + pos) * DK + hi;
                float v0 = acc[tm][tn][half*2];
                float v1 = acc[tm][tn][half*2 + 1];
                float w0, w1;
                if (mtx < 2){
                    float cs = g_cs[pos * 32 + (hi >> 1)];
                    float sn = g_sn[pos * 32 + (hi >> 1)];
                    w0 = (v0 * cs - v1 * sn) * scl;
                    w1 = (v0 * sn + v1 * cs) * scl;
                } else { w0 = v0; w1 = v1; }
                split_store(w0, Dh, Dl, ob);
                split_store(w1, Dh, Dl, ob + 1);
            }
        }
    }
}

// ---------------- GEMM + residual add (Wo, W2) ----------------
__global__ __launch_bounds__(512, 1) void gemm_add(
    const __nv_bfloat16* __restrict__ Ah, const __nv_bfloat16* __restrict__ Al,
    const __nv_bfloat16* __restrict__ Bh, const __nv_bfloat16* __restrict__ Bl,
    float* __restrict__ C, const float* __restrict__ other, int N, int K)
{
    extern __shared__ char smem[];
    uint32_t sb = smem_u32(smem);
    const int tid  = threadIdx.x;
    const int lane = tid & 31;
    const int wid  = tid >> 5;
    const int wm   = wid & 1;
    const int wn   = wid >> 1;
    const int m0 = blockIdx.y * 128, n0 = blockIdx.x * 128;
    const int NC = K / 64;

    float acc[4][2][4];
    #pragma unroll
    for (int i = 0; i < 4; i++)
        #pragma unroll
        for (int j = 0; j < 2; j++)
            #pragma unroll
            for (int k = 0; k < 4; k++) acc[i][j][k] = 0.0f;

    g_load_chunk(sb, tid, m0, n0, 0, K, Ah, Al, Bh, Bl);
    g_load_chunk(sb + STG_BYTES, tid, m0, n0, 1, K, Ah, Al, Bh, Bl);

    for (int kc = 0; kc < NC; kc++){
        if (kc + 1 < NC) cp_wait1(); else cp_wait0();
        __syncthreads();
        if (kc + 2 < NC)
            g_load_chunk(sb + ((kc+2)%3)*STG_BYTES, tid, m0, n0, kc+2, K, Ah, Al, Bh, Bl);
        g_compute_chunk(sb + (kc%3)*STG_BYTES, lane, wm, wn, acc);
    }

    const int gid = lane >> 2, tig = lane & 3;
    #pragma unroll
    for (int tm = 0; tm < 4; tm++){
        #pragma unroll
        for (int half = 0; half < 2; half++){
            int m = m0 + wm*64 + tm*16 + gid + half*8;
            #pragma unroll
            for (int tn = 0; tn < 2; tn++){
                int c = n0 + wn*16 + tn*8 + tig*2;
                size_t base = (size_t)m * N + c;
                C[base]     = other[base] + acc[tm][tn][half*2];
                C[base + 1] = other[base + 1] + acc[tm][tn][half*2 + 1];
            }
        }
    }
}

// ---------------- fused W1/W3 GEMM + silu(u)*v -> bf16 split ----------------
// stage = 6 matrices x 16 KB = 96 KB; 2 stages = 192 KB
#define W13_STG   98304
#define W13_SMEM  (2*W13_STG)

__global__ __launch_bounds__(512, 1) void gemm_w13(
    const __nv_bfloat16* __restrict__ Ah, const __nv_bfloat16* __restrict__ Al,
    const __nv_bfloat16* __restrict__ B1h, const __nv_bfloat16* __restrict__ B1l,
    const __nv_bfloat16* __restrict__ B3h, const __nv_bfloat16* __restrict__ B3l,
    __nv_bfloat16* __restrict__ Chi, __nv_bfloat16* __restrict__ Clo)
{
    extern __shared__ char smem[];
    uint32_t sb = smem_u32(smem);
    const int tid  = threadIdx.x;
    const int lane = tid & 31;
    const int wid  = tid >> 5;
    const int wm   = wid & 1;
    const int wn   = wid >> 1;
    const int m0 = blockIdx.y * 128, n0 = blockIdx.x * 128;
    const int NC = DM / 64;   // 16
    const int K  = DM;

    float accU[4][2][4], accV[4][2][4];
    #pragma unroll
    for (int i = 0; i < 4; i++)
        #pragma unroll
        for (int j = 0; j < 2; j++)
            #pragma unroll
            for (int k = 0; k < 4; k++){ accU[i][j][k] = 0.0f; accV[i][j][k] = 0.0f; }

    auto load_chunk = [&](int kc, int stage){
        uint32_t tb = sb + stage * W13_STG;
        int k0 = kc * 64;
        #pragma unroll
        for (int mtx = 0; mtx < 6; mtx++){
            const __nv_bfloat16* base =
                (mtx==0)?Ah:(mtx==1)?Al:(mtx==2)?B1h:(mtx==3)?B1l:(mtx==4)?B3h:B3l;
            int row0 = (mtx < 2) ? m0 : n0;
            #pragma unroll
            for (int j = 0; j < 2; j++){
                int i = j * 512 + tid;
                int r = i >> 3, c16 = i & 7;
                uint32_t o = (uint32_t)(r << 7) + (c16 << 4);
                cpa16(tb + (mtx << 14) + SW128(o),
                      base + (size_t)(row0 + r) * K + k0 + c16 * 8);
            }
        }
        cp_commit();
    };

    load_chunk(0, 0);

    for (int kc = 0; kc < NC; kc++){
        cp_wait0();
        __syncthreads();
        if (kc + 1 < NC) load_chunk(kc + 1, (kc + 1) & 1);
        uint32_t tb = sb + (kc & 1) * W13_STG;

        #pragma unroll
        for (int s = 0; s < 4; s++){
            uint32_t ah[4][4], al[4][4];
            #pragma unroll
            for (int t = 0; t < 4; t++){
                uint32_t o = (uint32_t)((wm*64 + t*16 + (lane & 15)) << 7)
                           + s*32 + ((lane >> 4) << 4);
                uint32_t so = SW128(o);
                ldsm4(ah[t], tb + so);
                ldsm4(al[t], tb + 16384 + so);
            }
            uint32_t bo = SW128((uint32_t)((wn*16 + (lane & 15)) << 7)
                                + s*32 + ((lane >> 4) << 4));
            // ---- W1 ----
            {
                uint32_t bh[4], bl[4];
                ldsm4(bh, tb + 32768 + bo);
                ldsm4(bl, tb + 49152 + bo);
                #pragma unroll
                for (int t = 0; t < 4; t++)
                    #pragma unroll
                    for (int j = 0; j < 2; j++)
                        mma16816(accU[t][j], ah[t], bh[j], bh[j+2]);
                #pragma unroll
                for (int t = 0; t < 4; t++)
                    #pragma unroll
                    for (int j = 0; j < 2; j++)
                        mma16816(accU[t][j], ah[t], bl[j], bl[j+2]);
                #pragma unroll
                for (int t = 0; t < 4; t++)
                    #pragma unroll
                    for (int j = 0; j < 2; j++)
                        mma16816(accU[t][j], al[t], bh[j], bh[j+2]);
            }
            // ---- W3 ----
            {
                uint32_t bh[4], bl[4];
                ldsm4(bh, tb + 65536 + bo);
                ldsm4(bl, tb + 81920 + bo);
                #pragma unroll
                for (int t = 0; t < 4; t++)
                    #pragma unroll
                    for (int j = 0; j < 2; j++)
                        mma16816(accV[t][j], ah[t], bh[j], bh[j+2]);
                #pragma unroll
                for (int t = 0; t < 4; t++)
                    #pragma unroll
                    for (int j = 0; j < 2; j++)
                        mma16816(accV[t][j], ah[t], bl[j], bl[j+2]);
                #pragma unroll
                for (int t = 0; t < 4; t++)
                    #pragma unroll
                    for (int j = 0; j < 2; j++)
                        mma16816(accV[t][j], al[t], bh[j], bh[j+2]);
            }
        }
    }

    const int gid = lane >> 2, tig = lane & 3;
    #pragma unroll
    for (int tm = 0; tm < 4; tm++){
        #pragma unroll
        for (int half = 0; half < 2; half++){
            int m = m0 + wm*64 + tm*16 + gid + half*8;
            #pragma unroll
            for (int tn = 0; tn < 2; tn++){
                int c = n0 + wn*16 + tn*8 + tig*2;
                size_t base = (size_t)m * DFF + c;
                float u0 = accU[tm][tn][half*2], u1 = accU[tm][tn][half*2+1];
                float v0 = accV[tm][tn][half*2], v1 = accV[tm][tn][half*2+1];
                float w0 = v0 * u0 / (1.0f + __expf(-u0));
                float w1 = v1 * u1 / (1.0f + __expf(-u1));
                split_store(w0, Chi, Clo, base);
                split_store(w1, Chi, Clo, base + 1);
            }
        }
    }
}

// ---------------- Tensor-core flash attention (causal, bf16-split x3) ----------------
#define FA_SMEM (32768 + 3*32768)

__global__ __launch_bounds__(256, 1) void flash_tc(
    const __nv_bfloat16* __restrict__ Qh_, const __nv_bfloat16* __restrict__ Ql_,
    const __nv_bfloat16* __restrict__ Kh_, const __nv_bfloat16* __restrict__ Kl_,
    const __nv_bfloat16* __restrict__ Vh_, const __nv_bfloat16* __restrict__ Vl_,
    __nv_bfloat16* __restrict__ Oh, __nv_bfloat16* __restrict__ Ol)
{
    extern __shared__ char smem[];
    uint32_t sb = smem_u32(smem);
    const int tid  = threadIdx.x;
    const int lane = tid & 31;
    const int w    = tid >> 5;
    const int gid  = lane >> 2, tig = lane & 3;
    const int qt   = (int)gridDim.x - 1 - (int)blockIdx.x;
    const int bh   = blockIdx.y;
    const int b    = bh >> 4, head = bh & 15;
    const size_t base = (size_t)bh * SEQ * DK;
    const int q0 = qt * 128;
    const int NT = 2 * qt + 2;

    #pragma unroll
    for (int m = 0; m < 2; m++){
        const __nv_bfloat16* src = m ? Ql_ : Qh_;
        #pragma unroll
        for (int j = 0; j < 4; j++){
            int i = j * 256 + tid;
            int r = i >> 3, c16 = i & 7;
            cpa16(sb + (m << 14) + SW128((r << 7) + (c16 << 4)),
                  src + base + (size_t)(q0 + r) * DK + c16 * 8);
        }
    }
    cp_commit();

    auto load_kv = [&](int kt, int stage){
        uint32_t tb = sb + 32768 + stage * 32768;
        size_t kb = base + (size_t)kt * 64 * DK;
        #pragma unroll
        for (int m = 0; m < 4; m++){
            const __nv_bfloat16* src = (m==0)?Kh_:(m==1)?Kl_:(m==2)?Vh_:Vl_;
            #pragma unroll
            for (int j = 0; j < 2; j++){
                int i = j * 256 + tid;
                int r = i >> 3, c16 = i & 7;
                cpa16(tb + (m << 13) + SW128((r << 7) + (c16 << 4)),
                      src + kb + (size_t)r * DK + c16 * 8);
            }
        }
        cp_commit();
    };
    load_kv(0, 0);
    load_kv(1, 1);

    cp_wait2();
    __syncthreads();

    uint32_t qh[4][4], ql[4][4];
    #pragma unroll
    for (int s = 0; s < 4; s++){
        uint32_t o = (uint32_t)((w*16 + (lane & 15)) << 7) + s*32 + ((lane >> 4) << 4);
        uint32_t so = SW128(o);
        ldsm4(qh[s], sb + so);
        ldsm4(ql[s], sb + 16384 + so);
    }

    float oacc[8][4];
    #pragma unroll
    for (int i = 0; i < 8; i++)
        #pragma unroll
        for (int j = 0; j < 4; j++) oacc[i][j] = 0.0f;
    float m0 = -1e30f, m1 = -1e30f, l0 = 0.0f, l1 = 0.0f;
    const int qrow0 = q0 + w * 16;

    for (int kt = 0; kt < NT; kt++){
        if (kt + 1 < NT) cp_wait1(); else cp_wait0();
        __syncthreads();
        uint32_t tb = sb + 32768 + (kt % 3) * 32768;

        float sc[8][4];
        #pragma unroll
        for (int i = 0; i < 8; i++)
            #pragma unroll
            for (int j = 0; j < 4; j++) sc[i][j] = 0.0f;

        #pragma unroll
        for (int s = 0; s < 4; s++){
            uint32_t khf[4][4], klf[4][4];
            #pragma unroll
            for (int g = 0; g < 4; g++){
                uint32_t o = (uint32_t)((g*16 + (lane & 15)) << 7) + s*32 + ((lane >> 4) << 4);
                uint32_t so = SW128(o);
                ldsm4(khf[g], tb + so);
                ldsm4(klf[g], tb + 8192 + so);
            }
            #pragma unroll
            for (int g = 0; g < 4; g++)
                #pragma unroll
                for (int j = 0; j < 2; j++)
                    mma16816(sc[g*2+j], qh[s], khf[g][j], khf[g][j+2]);
            #pragma unroll
            for (int g = 0; g < 4; g++)
                #pragma unroll
                for (int j = 0; j < 2; j++)
                    mma16816(sc[g*2+j], qh[s], klf[g][j], klf[g][j+2]);
            #pragma unroll
            for (int g = 0; g < 4; g++)
                #pragma unroll
                for (int j = 0; j < 2; j++)
                    mma16816(sc[g*2+j], ql[s], khf[g][j], khf[g][j+2]);
        }

        if (kt*64 + 63 > qrow0){
            int r0 = qrow0 + gid, r1 = r0 + 8;
            #pragma unroll
            for (int tn = 0; tn < 8; tn++){
                int key = kt*64 + tn*8 + tig*2;
                if (key     > r0) sc[tn][0] = -1e9f;
                if (key + 1 > r0) sc[tn][1] = -1e9f;
                if (key     > r1) sc[tn][2] = -1e9f;
                if (key + 1 > r1) sc[tn][3] = -1e9f;
            }
        }

        float t0 = -1e30f, t1 = -1e30f;
        #pragma unroll
        for (int tn = 0; tn < 8; tn++){
            t0 = fmaxf(t0, fmaxf(sc[tn][0], sc[tn][1]));
            t1 = fmaxf(t1, fmaxf(sc[tn][2], sc[tn][3]));
        }
        t0 = fmaxf(t0, __shfl_xor_sync(0xffffffffu, t0, 1));
        t0 = fmaxf(t0, __shfl_xor_sync(0xffffffffu, t0, 2));
        t1 = fmaxf(t1, __shfl_xor_sync(0xffffffffu, t1, 1));
        t1 = fmaxf(t1, __shfl_xor_sync(0xffffffffu, t1, 2));
        float nm0 = fmaxf(m0, t0), nm1 = fmaxf(m1, t1);
        float c0 = __expf(m0 - nm0), c1 = __expf(m1 - nm1);
        l0 *= c0; l1 *= c1;
        #pragma unroll
        for (int tn = 0; tn < 8; tn++){
            sc[tn][0] = __expf(sc[tn][0] - nm0);
            sc[tn][1] = __expf(sc[tn][1] - nm0);
            sc[tn][2] = __expf(sc[tn][2] - nm1);
            sc[tn][3] = __expf(sc[tn][3] - nm1);
            l0 += sc[tn][0] + sc[tn][1];
            l1 += sc[tn][2] + sc[tn][3];
        }
        #pragma unroll
        for (int od = 0; od < 8; od++){
            oacc[od][0] *= c0; oacc[od][1] *= c0;
            oacc[od][2] *= c1; oacc[od][3] *= c1;
        }
        m0 = nm0; m1 = nm1;

        uint32_t ph[4][4], pl[4][4];
        #pragma unroll
        for (int s = 0; s < 4; s++){
            splitpack(sc[2*s][0],   sc[2*s][1],   ph[s][0], pl[s][0]);
            splitpack(sc[2*s][2],   sc[2*s][3],   ph[s][1], pl[s][1]);
            splitpack(sc[2*s+1][0], sc[2*s+1][1], ph[s][2], pl[s][2]);
            splitpack(sc[2*s+1][2], sc[2*s+1][3], ph[s][3], pl[s][3]);
        }

        #pragma unroll
        for (int s = 0; s < 4; s++){
            uint32_t vhf[4][4], vlf[4][4];
            #pragma unroll
            for (int gd = 0; gd < 4; gd++){
                uint32_t row = s*16 + (lane & 7) + ((lane & 16) >> 1);
                uint32_t col = gd*16 + (lane & 8);
                uint32_t o = (row << 7) + (col << 1);
                uint32_t so = SW128(o);
                ldsm4t(vhf[gd], tb + 16384 + so);
                ldsm4t(vlf[gd], tb + 24576 + so);
            }
            #pragma unroll
            for (int gd = 0; gd < 4; gd++)
                #pragma unroll
                for (int j = 0; j < 2; j++)
                    mma16816(oacc[gd*2+j], ph[s], vhf[gd][j], vhf[gd][j+2]);
            #pragma unroll
            for (int gd = 0; gd < 4; gd++)
                #pragma unroll
                for (int j = 0; j < 2; j++)
                    mma16816(oacc[gd*2+j], ph[s], vlf[gd][j], vlf[gd][j+2]);
            #pragma unroll
            for (int gd = 0; gd < 4; gd++)
                #pragma unroll
                for (int j = 0; j < 2; j++)
                    mma16816(oacc[gd*2+j], pl[s], vhf[gd][j], vhf[gd][j+2]);
        }

        if (kt + 2 < NT) load_kv(kt + 2, (kt + 2) % 3);
    }

    l0 += __shfl_xor_sync(0xffffffffu, l0, 1);
    l0 += __shfl_xor_sync(0xffffffffu, l0, 2);
    l1 += __shfl_xor_sync(0xffffffffu, l1, 1);
    l1 += __shfl_xor_sync(0xffffffffu, l1, 2);
    float inv0 = 1.0f / l0, inv1 = 1.0f / l1;

    int q = qrow0 + gid;
    size_t tk0 = (size_t)(b * SEQ + q) * DM + head * 64;
    size_t tk1 = tk0 + (size_t)8 * DM;
    #pragma unroll
    for (int od = 0; od < 8; od++){
        int d = od*8 + tig*2;
        split_store(oacc[od][0] * inv0, Oh, Ol, tk0 + d);
        split_store(oacc[od][1] * inv0, Oh, Ol, tk0 + d + 1);
        split_store(oacc[od][2] * inv1, Oh, Ol, tk1 + d);
        split_store(oacc[od][3] * inv1, Oh, Ol, tk1 + d + 1);
    }
}

// ---------------- launch ----------------
extern "C" void kernel_launch(void* const* d_in, const int* in_sizes, int n_in,
                              void* d_out, int out_size)
{
    const float* x  = (const float*)d_in[0];
    const float* Wq = (const float*)d_in[1];
    const float* Wk = (const float*)d_in[2];
    const float* Wv = (const float*)d_in[3];
    const float* Wo = (const float*)d_in[4];
    const float* g1 = (const float*)d_in[5];
    const float* g2 = (const float*)d_in[6];
    const float* W1 = (const float*)d_in[7];
    const float* W3 = (const float*)d_in[8];
    const float* W2 = (const float*)d_in[9];
    float* out = (float*)d_out;

    float *x1;
    __nv_bfloat16 *hh,*hl,*ath,*atl,*h2h,*h2l,*gbh,*gbl,*wh,*wl;
    __nv_bfloat16 *qhh,*qhl,*khh,*khl,*vhh,*vhl;
    cudaGetSymbolAddress((void**)&x1,   g_x1);
    cudaGetSymbolAddress((void**)&hh,   g_hh);
    cudaGetSymbolAddress((void**)&hl,   g_hl);
    cudaGetSymbolAddress((void**)&ath,  g_ath);
    cudaGetSymbolAddress((void**)&atl,  g_atl);
    cudaGetSymbolAddress((void**)&h2h,  g_h2h);
    cudaGetSymbolAddress((void**)&h2l,  g_h2l);
    cudaGetSymbolAddress((void**)&gbh,  g_gbh);
    cudaGetSymbolAddress((void**)&gbl,  g_gbl);
    cudaGetSymbolAddress((void**)&wh,   g_wh);
    cudaGetSymbolAddress((void**)&wl,   g_wl);
    cudaGetSymbolAddress((void**)&qhh,  g_qhh);
    cudaGetSymbolAddress((void**)&qhl,  g_qhl);
    cudaGetSymbolAddress((void**)&khh,  g_khh);
    cudaGetSymbolAddress((void**)&khl,  g_khl);
    cudaGetSymbolAddress((void**)&vhh,  g_vhh);
    cudaGetSymbolAddress((void**)&vhl,  g_vhl);

    cudaFuncSetAttribute(gemm_qkv, cudaFuncAttributeMaxDynamicSharedMemorySize, GEMM_SMEM);
    cudaFuncSetAttribute(gemm_add, cudaFuncAttributeMaxDynamicSharedMemorySize, GEMM_SMEM);
    cudaFuncSetAttribute(gemm_w13, cudaFuncAttributeMaxDynamicSharedMemorySize, W13_SMEM);
    cudaFuncSetAttribute(flash_tc, cudaFuncAttributeMaxDynamicSharedMemorySize, FA_SMEM);

    rope_table_k<<<SEQ * 32 / 256, 256>>>();
    split_all_k<<<4096, 256>>>(Wq, Wk, Wv, Wo, W1, W3, W2, wh, wl);

    rms_split_k<<<TOKENS, 256>>>(x, g1, hh, hl);

    // fused QKV: N=3072 over contiguous packed weights
    gemm_qkv<<<dim3(3*DM/128, TOKENS/128), 512, GEMM_SMEM>>>(
        hh, hl, wh, wl, qhh, qhl, khh, khl, vhh, vhl);

    flash_tc<<<dim3(SEQ / 128, 2 * NH), 256, FA_SMEM>>>(qhh, qhl, khh, khl, vhh, vhl, ath, atl);

    gemm_add<<<dim3(DM/128, TOKENS/128), 512, GEMM_SMEM>>>(
        ath, atl, wh+WOFF_O, wl+WOFF_O, x1, x, DM, DM);
    rms_split_k<<<TOKENS, 256>>>(x1, g2, h2h, h2l);

    gemm_w13<<<dim3(DFF/128, TOKENS/128), 512, W13_SMEM>>>(
        h2h, h2l, wh+WOFF_1, wl+WOFF_1, wh+WOFF_3, wl+WOFF_3, gbh, gbl);
    gemm_add<<<dim3(DM/128, TOKENS/128), 512, GEMM_SMEM>>>(
        gbh, gbl, wh+WOFF_2, wl+WOFF_2, out, x1, DM, DFF);
}

// round 8
// speedup vs baseline: 3.0495x; 1.0181x over previous
#include <cuda_runtime.h>
#include <cuda_bf16.h>
#include <math.h>
#include <stdint.h>

#define TOKENS 4096
#define DM     1024
#define DFF    4096
#define SEQ    2048
#define NH     16
#define DK     64

// ---------------- scratch ----------------
__device__ float g_x1[TOKENS*DM];
__device__ float g_cs[SEQ*32];
__device__ float g_sn[SEQ*32];

__device__ __nv_bfloat16 g_hh[TOKENS*DM],  g_hl[TOKENS*DM];
__device__ __nv_bfloat16 g_ath[TOKENS*DM], g_atl[TOKENS*DM];
__device__ __nv_bfloat16 g_h2h[TOKENS*DM], g_h2l[TOKENS*DM];
__device__ __nv_bfloat16 g_gbh[TOKENS*DFF], g_gbl[TOKENS*DFF];
__device__ __nv_bfloat16 g_qhh[TOKENS*DM], g_qhl[TOKENS*DM];
__device__ __nv_bfloat16 g_khh[TOKENS*DM], g_khl[TOKENS*DM];
__device__ __nv_bfloat16 g_vhh[TOKENS*DM], g_vhl[TOKENS*DM];

#define WOFF_Q  0
#define WOFF_K  (1u<<20)
#define WOFF_V  (2u<<20)
#define WOFF_O  (3u<<20)
#define WOFF_1  (4u<<20)
#define WOFF_3  (8u<<20)
#define WOFF_2  (12u<<20)
__device__ __nv_bfloat16 g_wh[16u<<20];
__device__ __nv_bfloat16 g_wl[16u<<20];

// ---------------- helpers ----------------
__device__ __forceinline__ uint32_t smem_u32(const void* p){
    uint32_t r;
    asm("{ .reg .u64 t; cvta.to.shared.u64 t, %1; cvt.u32.u64 %0, t; }" : "=r"(r) : "l"(p));
    return r;
}
__device__ __forceinline__ void cpa16(uint32_t dst, const void* src){
    asm volatile("cp.async.cg.shared.global [%0], [%1], 16;" :: "r"(dst), "l"(src) : "memory");
}
__device__ __forceinline__ void cp_commit(){ asm volatile("cp.async.commit_group;" ::: "memory"); }
__device__ __forceinline__ void cp_wait2(){ asm volatile("cp.async.wait_group 2;" ::: "memory"); }
__device__ __forceinline__ void cp_wait1(){ asm volatile("cp.async.wait_group 1;" ::: "memory"); }
__device__ __forceinline__ void cp_wait0(){ asm volatile("cp.async.wait_group 0;" ::: "memory"); }

__device__ __forceinline__ void ldsm4(uint32_t* r, uint32_t addr){
    asm volatile("ldmatrix.sync.aligned.m8n8.x4.shared.b16 {%0,%1,%2,%3}, [%4];"
        : "=r"(r[0]),"=r"(r[1]),"=r"(r[2]),"=r"(r[3]) : "r"(addr));
}
__device__ __forceinline__ void ldsm4t(uint32_t* r, uint32_t addr){
    asm volatile("ldmatrix.sync.aligned.m8n8.x4.trans.shared.b16 {%0,%1,%2,%3}, [%4];"
        : "=r"(r[0]),"=r"(r[1]),"=r"(r[2]),"=r"(r[3]) : "r"(addr));
}
__device__ __forceinline__ void mma16816(float* c, const uint32_t* a, uint32_t b0, uint32_t b1){
    asm volatile("mma.sync.aligned.m16n8k16.row.col.f32.bf16.bf16.f32 "
        "{%0,%1,%2,%3}, {%4,%5,%6,%7}, {%8,%9}, {%0,%1,%2,%3};"
        : "+f"(c[0]),"+f"(c[1]),"+f"(c[2]),"+f"(c[3])
        : "r"(a[0]),"r"(a[1]),"r"(a[2]),"r"(a[3]), "r"(b0),"r"(b1));
}
#define SW128(o) ((o) ^ (((o)>>3)&0x70))   // 128B rows

__device__ __forceinline__ void split_store(float w, __nv_bfloat16* h, __nv_bfloat16* l, size_t i){
    __nv_bfloat16 hh = __float2bfloat16(w);
    h[i] = hh;
    l[i] = __float2bfloat16(w - __bfloat162float(hh));
}
__device__ __forceinline__ void splitpack(float x, float y, uint32_t& ph, uint32_t& pl){
    __nv_bfloat16 hx = __float2bfloat16(x), hy = __float2bfloat16(y);
    __nv_bfloat16 lx = __float2bfloat16(x - __bfloat162float(hx));
    __nv_bfloat16 ly = __float2bfloat16(y - __bfloat162float(hy));
    ph = ((uint32_t)__bfloat16_as_ushort(hy) << 16) | __bfloat16_as_ushort(hx);
    pl = ((uint32_t)__bfloat16_as_ushort(ly) << 16) | __bfloat16_as_ushort(lx);
}

// ---------------- RoPE table ----------------
__global__ void rope_table_k() {
    __shared__ float invf[32];
    int t = threadIdx.x;
    if (t < 32) invf[t] = (float)pow(10000.0, -(double)(2 * t) / 64.0);
    __syncthreads();
    int i = blockIdx.x * 256 + t;
    int pos = i >> 5;
    int j   = i & 31;
    float ang = (float)pos * invf[j];
    g_cs[i] = cosf(ang);
    g_sn[i] = sinf(ang);
}

// ---------------- all weight splits, vectorized ----------------
__global__ void split_all_k(const float* __restrict__ Wq, const float* __restrict__ Wk,
                            const float* __restrict__ Wv, const float* __restrict__ Wo,
                            const float* __restrict__ W1, const float* __restrict__ W3,
                            const float* __restrict__ W2,
                            __nv_bfloat16* __restrict__ wh, __nv_bfloat16* __restrict__ wl){
    int gb = blockIdx.x;
    const float* src; uint32_t woff; int lb;
    if (gb < 1024){
        int m = gb >> 8; lb = gb & 255;
        src = (m==0)?Wq:(m==1)?Wk:(m==2)?Wv:Wo;
        woff = (uint32_t)m << 20;
    } else if (gb < 2048){ src = W1; woff = WOFF_1; lb = gb - 1024; }
    else if (gb < 3072){ src = W3; woff = WOFF_3; lb = gb - 2048; }
    else               { src = W2; woff = WOFF_2; lb = gb - 3072; }
    uint2* hp = (uint2*)(wh + woff);
    uint2* lp = (uint2*)(wl + woff);
    #pragma unroll
    for (int j = 0; j < 4; j++){
        int i4 = lb * 1024 + j * 256 + threadIdx.x;
        float4 v = ((const float4*)src)[i4];
        uint32_t h01, l01, h23, l23;
        splitpack(v.x, v.y, h01, l01);
        splitpack(v.z, v.w, h23, l23);
        hp[i4] = make_uint2(h01, h23);
        lp[i4] = make_uint2(l01, l23);
    }
}

// ---------------- RMSNorm -> bf16 hi/lo ----------------
__global__ __launch_bounds__(256) void rms_split_k(const float* __restrict__ x,
                                                   const float* __restrict__ g,
                                                   __nv_bfloat16* __restrict__ oh,
                                                   __nv_bfloat16* __restrict__ ol) {
    int row = blockIdx.x;
    int t   = threadIdx.x;
    const float4* xr = (const float4*)(x + (size_t)row * DM);
    float4 xv = xr[t];
    float ss = xv.x*xv.x + xv.y*xv.y + xv.z*xv.z + xv.w*xv.w;
    #pragma unroll
    for (int off = 16; off > 0; off >>= 1)
        ss += __shfl_xor_sync(0xffffffffu, ss, off);
    __shared__ float warpsum[8];
    if ((t & 31) == 0) warpsum[t >> 5] = ss;
    __syncthreads();
    float tot = warpsum[0]+warpsum[1]+warpsum[2]+warpsum[3]
              + warpsum[4]+warpsum[5]+warpsum[6]+warpsum[7];
    float r = rsqrtf(tot * (1.0f / (float)DM) + 1e-5f);
    float4 gv = ((const float4*)g)[t];
    float v[4] = { xv.x*r*gv.x, xv.y*r*gv.y, xv.z*r*gv.z, xv.w*r*gv.w };
    size_t base = (size_t)row * DM + t * 4;
    uint32_t h01, l01, h23, l23;
    splitpack(v[0], v[1], h01, l01);
    splitpack(v[2], v[3], h23, l23);
    *(uint2*)(oh + base) = make_uint2(h01, h23);
    *(uint2*)(ol + base) = make_uint2(l01, l23);
}

// =====================================================================
// GEMM machinery: CTA 128x128, 512 thr, warp grid 4x4 (tile 32x32),
// BK=64, SW128 128B rows. Stage = [Ah|Al|Bh|Bl] x 16 KB.
// =====================================================================
#define STG_BYTES 65536
#define GEMM_SMEM (3*STG_BYTES)

__device__ __forceinline__ void g_load_chunk(
    uint32_t tb, int tid, int m0, int n0, int kc, int K,
    const __nv_bfloat16* Ah, const __nv_bfloat16* Al,
    const __nv_bfloat16* Bh, const __nv_bfloat16* Bl)
{
    int k0 = kc * 64;
    #pragma unroll
    for (int mtx = 0; mtx < 4; mtx++){
        const __nv_bfloat16* base = (mtx==0)?Ah:(mtx==1)?Al:(mtx==2)?Bh:Bl;
        int row0 = (mtx < 2) ? m0 : n0;
        #pragma unroll
        for (int j = 0; j < 2; j++){
            int i = j * 512 + tid;
            int r = i >> 3, c16 = i & 7;
            uint32_t o = (uint32_t)(r << 7) + (c16 << 4);
            cpa16(tb + (mtx << 14) + SW128(o),
                  base + (size_t)(row0 + r) * K + k0 + c16 * 8);
        }
    }
    cp_commit();
}

// fragments for one k16 step, warp tile 32x32
struct Frags { uint32_t ah[2][4], al[2][4], bh[2][4], bl[2][4]; };

__device__ __forceinline__ void ld_frags(Frags& f, uint32_t tb, int lane, int wm, int wn, int s){
    uint32_t colb = (uint32_t)(s*32) + ((lane >> 4) << 4);
    #pragma unroll
    for (int t = 0; t < 2; t++){
        uint32_t so = SW128((uint32_t)((wm*32 + t*16 + (lane & 15)) << 7) + colb);
        ldsm4(f.ah[t], tb + so);
        ldsm4(f.al[t], tb + 16384 + so);
    }
    #pragma unroll
    for (int g = 0; g < 2; g++){
        uint32_t so = SW128((uint32_t)((wn*32 + g*16 + (lane & 15)) << 7) + colb);
        ldsm4(f.bh[g], tb + 32768 + so);
        ldsm4(f.bl[g], tb + 49152 + so);
    }
}

__device__ __forceinline__ void mma_frags(float acc[2][4][4], const Frags& f){
    #pragma unroll
    for (int t = 0; t < 2; t++)
        #pragma unroll
        for (int g = 0; g < 2; g++)
            #pragma unroll
            for (int j = 0; j < 2; j++)
                mma16816(acc[t][g*2+j], f.ah[t], f.bh[g][j], f.bh[g][j+2]);
    #pragma unroll
    for (int t = 0; t < 2; t++)
        #pragma unroll
        for (int g = 0; g < 2; g++)
            #pragma unroll
            for (int j = 0; j < 2; j++)
                mma16816(acc[t][g*2+j], f.ah[t], f.bl[g][j], f.bl[g][j+2]);
    #pragma unroll
    for (int t = 0; t < 2; t++)
        #pragma unroll
        for (int g = 0; g < 2; g++)
            #pragma unroll
            for (int j = 0; j < 2; j++)
                mma16816(acc[t][g*2+j], f.al[t], f.bh[g][j], f.bh[g][j+2]);
}

// BK=64 chunk: 4 k-steps, double-buffered fragments
__device__ __forceinline__ void g_compute_chunk(
    uint32_t tb, int lane, int wm, int wn, float acc[2][4][4])
{
    Frags f0, f1;
    ld_frags(f0, tb, lane, wm, wn, 0);
    ld_frags(f1, tb, lane, wm, wn, 1);
    mma_frags(acc, f0);
    ld_frags(f0, tb, lane, wm, wn, 2);
    mma_frags(acc, f1);
    ld_frags(f1, tb, lane, wm, wn, 3);
    mma_frags(acc, f0);
    mma_frags(acc, f1);
}

// ---------------- fused QKV GEMM ----------------
__global__ __launch_bounds__(512, 1) void gemm_qkv(
    const __nv_bfloat16* __restrict__ Ah, const __nv_bfloat16* __restrict__ Al,
    const __nv_bfloat16* __restrict__ Bh, const __nv_bfloat16* __restrict__ Bl,
    __nv_bfloat16* __restrict__ Qh, __nv_bfloat16* __restrict__ Ql,
    __nv_bfloat16* __restrict__ Kh, __nv_bfloat16* __restrict__ Kl,
    __nv_bfloat16* __restrict__ Vh, __nv_bfloat16* __restrict__ Vl)
{
    extern __shared__ char smem[];
    uint32_t sb = smem_u32(smem);
    const int tid  = threadIdx.x;
    const int lane = tid & 31;
    const int wid  = tid >> 5;
    const int wm   = wid & 3;        // 4 row groups of 32
    const int wn   = wid >> 2;       // 4 col groups of 32
    const int m0 = blockIdx.y * 128, n0 = blockIdx.x * 128;
    const int NC = DM / 64;
    const int K  = DM;

    float acc[2][4][4];
    #pragma unroll
    for (int i = 0; i < 2; i++)
        #pragma unroll
        for (int j = 0; j < 4; j++)
            #pragma unroll
            for (int k = 0; k < 4; k++) acc[i][j][k] = 0.0f;

    g_load_chunk(sb, tid, m0, n0, 0, K, Ah, Al, Bh, Bl);
    g_load_chunk(sb + STG_BYTES, tid, m0, n0, 1, K, Ah, Al, Bh, Bl);

    for (int kc = 0; kc < NC; kc++){
        if (kc + 1 < NC) cp_wait1(); else cp_wait0();
        __syncthreads();
        if (kc + 2 < NC)
            g_load_chunk(sb + ((kc+2)%3)*STG_BYTES, tid, m0, n0, kc+2, K, Ah, Al, Bh, Bl);
        g_compute_chunk(sb + (kc%3)*STG_BYTES, lane, wm, wn, acc);
    }

    const int mtx = n0 >> 10;
    const float scl = (mtx == 0) ? 0.125f : 1.0f;
    __nv_bfloat16* Dh = (mtx==0)?Qh:(mtx==1)?Kh:Vh;
    __nv_bfloat16* Dl = (mtx==0)?Ql:(mtx==1)?Kl:Vl;
    const int gid = lane >> 2, tig = lane & 3;
    #pragma unroll
    for (int tm = 0; tm < 2; tm++){
        #pragma unroll
        for (int half = 0; half < 2; half++){
            int m = m0 + wm*32 + tm*16 + gid + half*8;
            int pos = m & (SEQ - 1), b = m >> 11;
            #pragma unroll
            for (int tn = 0; tn < 4; tn++){
                int cc = (n0 & 1023) + wn*32 + tn*8 + tig*2;
                int head = cc >> 6, hi = cc & 63;
                size_t ob = ((size_t)(b * NH + head) * SEQ + pos) * DK + hi;
                float v0 = acc[tm][tn][half*2];
                float v1 = acc[tm][tn][half*2 + 1];
                float w0, w1;
                if (mtx < 2){
                    float cs = g_cs[pos * 32 + (hi >> 1)];
                    float sn = g_sn[pos * 32 + (hi >> 1)];
                    w0 = (v0 * cs - v1 * sn) * scl;
                    w1 = (v0 * sn + v1 * cs) * scl;
                } else { w0 = v0; w1 = v1; }
                split_store(w0, Dh, Dl, ob);
                split_store(w1, Dh, Dl, ob + 1);
            }
        }
    }
}

// ---------------- GEMM + residual add (Wo, W2) ----------------
__global__ __launch_bounds__(512, 1) void gemm_add(
    const __nv_bfloat16* __restrict__ Ah, const __nv_bfloat16* __restrict__ Al,
    const __nv_bfloat16* __restrict__ Bh, const __nv_bfloat16* __restrict__ Bl,
    float* __restrict__ C, const float* __restrict__ other, int N, int K)
{
    extern __shared__ char smem[];
    uint32_t sb = smem_u32(smem);
    const int tid  = threadIdx.x;
    const int lane = tid & 31;
    const int wid  = tid >> 5;
    const int wm   = wid & 3;
    const int wn   = wid >> 2;
    const int m0 = blockIdx.y * 128, n0 = blockIdx.x * 128;
    const int NC = K / 64;

    float acc[2][4][4];
    #pragma unroll
    for (int i = 0; i < 2; i++)
        #pragma unroll
        for (int j = 0; j < 4; j++)
            #pragma unroll
            for (int k = 0; k < 4; k++) acc[i][j][k] = 0.0f;

    g_load_chunk(sb, tid, m0, n0, 0, K, Ah, Al, Bh, Bl);
    g_load_chunk(sb + STG_BYTES, tid, m0, n0, 1, K, Ah, Al, Bh, Bl);

    for (int kc = 0; kc < NC; kc++){
        if (kc + 1 < NC) cp_wait1(); else cp_wait0();
        __syncthreads();
        if (kc + 2 < NC)
            g_load_chunk(sb + ((kc+2)%3)*STG_BYTES, tid, m0, n0, kc+2, K, Ah, Al, Bh, Bl);
        g_compute_chunk(sb + (kc%3)*STG_BYTES, lane, wm, wn, acc);
    }

    const int gid = lane >> 2, tig = lane & 3;
    #pragma unroll
    for (int tm = 0; tm < 2; tm++){
        #pragma unroll
        for (int half = 0; half < 2; half++){
            int m = m0 + wm*32 + tm*16 + gid + half*8;
            #pragma unroll
            for (int tn = 0; tn < 4; tn++){
                int c = n0 + wn*32 + tn*8 + tig*2;
                size_t base = (size_t)m * N + c;
                C[base]     = other[base] + acc[tm][tn][half*2];
                C[base + 1] = other[base + 1] + acc[tm][tn][half*2 + 1];
            }
        }
    }
}

// ---------------- fused W1/W3 GEMM + silu(u)*v -> bf16 split ----------------
#define W13_STG   98304
#define W13_SMEM  (2*W13_STG)

__global__ __launch_bounds__(512, 1) void gemm_w13(
    const __nv_bfloat16* __restrict__ Ah, const __nv_bfloat16* __restrict__ Al,
    const __nv_bfloat16* __restrict__ B1h, const __nv_bfloat16* __restrict__ B1l,
    const __nv_bfloat16* __restrict__ B3h, const __nv_bfloat16* __restrict__ B3l,
    __nv_bfloat16* __restrict__ Chi, __nv_bfloat16* __restrict__ Clo)
{
    extern __shared__ char smem[];
    uint32_t sb = smem_u32(smem);
    const int tid  = threadIdx.x;
    const int lane = tid & 31;
    const int wid  = tid >> 5;
    const int wm   = wid & 3;
    const int wn   = wid >> 2;
    const int m0 = blockIdx.y * 128, n0 = blockIdx.x * 128;
    const int NC = DM / 64;
    const int K  = DM;

    float accU[2][4][4], accV[2][4][4];
    #pragma unroll
    for (int i = 0; i < 2; i++)
        #pragma unroll
        for (int j = 0; j < 4; j++)
            #pragma unroll
            for (int k = 0; k < 4; k++){ accU[i][j][k] = 0.0f; accV[i][j][k] = 0.0f; }

    auto load_chunk = [&](int kc, int stage){
        uint32_t tb = sb + stage * W13_STG;
        int k0 = kc * 64;
        #pragma unroll
        for (int mtx = 0; mtx < 6; mtx++){
            const __nv_bfloat16* base =
                (mtx==0)?Ah:(mtx==1)?Al:(mtx==2)?B1h:(mtx==3)?B1l:(mtx==4)?B3h:B3l;
            int row0 = (mtx < 2) ? m0 : n0;
            #pragma unroll
            for (int j = 0; j < 2; j++){
                int i = j * 512 + tid;
                int r = i >> 3, c16 = i & 7;
                uint32_t o = (uint32_t)(r << 7) + (c16 << 4);
                cpa16(tb + (mtx << 14) + SW128(o),
                      base + (size_t)(row0 + r) * K + k0 + c16 * 8);
            }
        }
        cp_commit();
    };

    load_chunk(0, 0);

    for (int kc = 0; kc < NC; kc++){
        cp_wait0();
        __syncthreads();
        if (kc + 1 < NC) load_chunk(kc + 1, (kc + 1) & 1);
        uint32_t tb = sb + (kc & 1) * W13_STG;

        #pragma unroll
        for (int s = 0; s < 4; s++){
            uint32_t colb = (uint32_t)(s*32) + ((lane >> 4) << 4);
            uint32_t ah[2][4], al[2][4];
            #pragma unroll
            for (int t = 0; t < 2; t++){
                uint32_t so = SW128((uint32_t)((wm*32 + t*16 + (lane & 15)) << 7) + colb);
                ldsm4(ah[t], tb + so);
                ldsm4(al[t], tb + 16384 + so);
            }
            uint32_t b1h[2][4], b1l[2][4], b3h[2][4], b3l[2][4];
            #pragma unroll
            for (int g = 0; g < 2; g++){
                uint32_t so = SW128((uint32_t)((wn*32 + g*16 + (lane & 15)) << 7) + colb);
                ldsm4(b1h[g], tb + 32768 + so);
                ldsm4(b1l[g], tb + 49152 + so);
                ldsm4(b3h[g], tb + 65536 + so);
                ldsm4(b3l[g], tb + 81920 + so);
            }
            #pragma unroll
            for (int t = 0; t < 2; t++)
                #pragma unroll
                for (int g = 0; g < 2; g++)
                    #pragma unroll
                    for (int j = 0; j < 2; j++){
                        mma16816(accU[t][g*2+j], ah[t], b1h[g][j], b1h[g][j+2]);
                        mma16816(accV[t][g*2+j], ah[t], b3h[g][j], b3h[g][j+2]);
                    }
            #pragma unroll
            for (int t = 0; t < 2; t++)
                #pragma unroll
                for (int g = 0; g < 2; g++)
                    #pragma unroll
                    for (int j = 0; j < 2; j++){
                        mma16816(accU[t][g*2+j], ah[t], b1l[g][j], b1l[g][j+2]);
                        mma16816(accV[t][g*2+j], ah[t], b3l[g][j], b3l[g][j+2]);
                    }
            #pragma unroll
            for (int t = 0; t < 2; t++)
                #pragma unroll
                for (int g = 0; g < 2; g++)
                    #pragma unroll
                    for (int j = 0; j < 2; j++){
                        mma16816(accU[t][g*2+j], al[t], b1h[g][j], b1h[g][j+2]);
                        mma16816(accV[t][g*2+j], al[t], b3h[g][j], b3h[g][j+2]);
                    }
        }
    }

    const int gid = lane >> 2, tig = lane & 3;
    #pragma unroll
    for (int tm = 0; tm < 2; tm++){
        #pragma unroll
        for (int half = 0; half < 2; half++){
            int m = m0 + wm*32 + tm*16 + gid + half*8;
            #pragma unroll
            for (int tn = 0; tn < 4; tn++){
                int c = n0 + wn*32 + tn*8 + tig*2;
                size_t base = (size_t)m * DFF + c;
                float u0 = accU[tm][tn][half*2], u1 = accU[tm][tn][half*2+1];
                float v0 = accV[tm][tn][half*2], v1 = accV[tm][tn][half*2+1];
                float w0 = v0 * u0 / (1.0f + __expf(-u0));
                float w1 = v1 * u1 / (1.0f + __expf(-u1));
                split_store(w0, Chi, Clo, base);
                split_store(w1, Chi, Clo, base + 1);
            }
        }
    }
}

// ---------------- Tensor-core flash attention (causal, bf16-split x3) ----------------
#define FA_SMEM (32768 + 3*32768)

__global__ __launch_bounds__(256, 1) void flash_tc(
    const __nv_bfloat16* __restrict__ Qh_, const __nv_bfloat16* __restrict__ Ql_,
    const __nv_bfloat16* __restrict__ Kh_, const __nv_bfloat16* __restrict__ Kl_,
    const __nv_bfloat16* __restrict__ Vh_, const __nv_bfloat16* __restrict__ Vl_,
    __nv_bfloat16* __restrict__ Oh, __nv_bfloat16* __restrict__ Ol)
{
    extern __shared__ char smem[];
    uint32_t sb = smem_u32(smem);
    const int tid  = threadIdx.x;
    const int lane = tid & 31;
    const int w    = tid >> 5;
    const int gid  = lane >> 2, tig = lane & 3;
    const int qt   = (int)gridDim.x - 1 - (int)blockIdx.x;
    const int bh   = blockIdx.y;
    const int b    = bh >> 4, head = bh & 15;
    const size_t base = (size_t)bh * SEQ * DK;
    const int q0 = qt * 128;
    const int NT = 2 * qt + 2;

    #pragma unroll
    for (int m = 0; m < 2; m++){
        const __nv_bfloat16* src = m ? Ql_ : Qh_;
        #pragma unroll
        for (int j = 0; j < 4; j++){
            int i = j * 256 + tid;
            int r = i >> 3, c16 = i & 7;
            cpa16(sb + (m << 14) + SW128((r << 7) + (c16 << 4)),
                  src + base + (size_t)(q0 + r) * DK + c16 * 8);
        }
    }
    cp_commit();

    auto load_kv = [&](int kt, int stage){
        uint32_t tb = sb + 32768 + stage * 32768;
        size_t kb = base + (size_t)kt * 64 * DK;
        #pragma unroll
        for (int m = 0; m < 4; m++){
            const __nv_bfloat16* src = (m==0)?Kh_:(m==1)?Kl_:(m==2)?Vh_:Vl_;
            #pragma unroll
            for (int j = 0; j < 2; j++){
                int i = j * 256 + tid;
                int r = i >> 3, c16 = i & 7;
                cpa16(tb + (m << 13) + SW128((r << 7) + (c16 << 4)),
                      src + kb + (size_t)r * DK + c16 * 8);
            }
        }
        cp_commit();
    };
    load_kv(0, 0);
    load_kv(1, 1);

    cp_wait2();
    __syncthreads();

    uint32_t qh[4][4], ql[4][4];
    #pragma unroll
    for (int s = 0; s < 4; s++){
        uint32_t o = (uint32_t)((w*16 + (lane & 15)) << 7) + s*32 + ((lane >> 4) << 4);
        uint32_t so = SW128(o);
        ldsm4(qh[s], sb + so);
        ldsm4(ql[s], sb + 16384 + so);
    }

    float oacc[8][4];
    #pragma unroll
    for (int i = 0; i < 8; i++)
        #pragma unroll
        for (int j = 0; j < 4; j++) oacc[i][j] = 0.0f;
    float m0 = -1e30f, m1 = -1e30f, l0 = 0.0f, l1 = 0.0f;
    const int qrow0 = q0 + w * 16;

    for (int kt = 0; kt < NT; kt++){
        if (kt + 1 < NT) cp_wait1(); else cp_wait0();
        __syncthreads();
        uint32_t tb = sb + 32768 + (kt % 3) * 32768;

        float sc[8][4];
        #pragma unroll
        for (int i = 0; i < 8; i++)
            #pragma unroll
            for (int j = 0; j < 4; j++) sc[i][j] = 0.0f;

        #pragma unroll
        for (int s = 0; s < 4; s++){
            uint32_t khf[4][4], klf[4][4];
            #pragma unroll
            for (int g = 0; g < 4; g++){
                uint32_t o = (uint32_t)((g*16 + (lane & 15)) << 7) + s*32 + ((lane >> 4) << 4);
                uint32_t so = SW128(o);
                ldsm4(khf[g], tb + so);
                ldsm4(klf[g], tb + 8192 + so);
            }
            #pragma unroll
            for (int g = 0; g < 4; g++)
                #pragma unroll
                for (int j = 0; j < 2; j++)
                    mma16816(sc[g*2+j], qh[s], khf[g][j], khf[g][j+2]);
            #pragma unroll
            for (int g = 0; g < 4; g++)
                #pragma unroll
                for (int j = 0; j < 2; j++)
                    mma16816(sc[g*2+j], qh[s], klf[g][j], klf[g][j+2]);
            #pragma unroll
            for (int g = 0; g < 4; g++)
                #pragma unroll
                for (int j = 0; j < 2; j++)
                    mma16816(sc[g*2+j], ql[s], khf[g][j], khf[g][j+2]);
        }

        if (kt*64 + 63 > qrow0){
            int r0 = qrow0 + gid, r1 = r0 + 8;
            #pragma unroll
            for (int tn = 0; tn < 8; tn++){
                int key = kt*64 + tn*8 + tig*2;
                if (key     > r0) sc[tn][0] = -1e9f;
                if (key + 1 > r0) sc[tn][1] = -1e9f;
                if (key     > r1) sc[tn][2] = -1e9f;
                if (key + 1 > r1) sc[tn][3] = -1e9f;
            }
        }

        float t0 = -1e30f, t1 = -1e30f;
        #pragma unroll
        for (int tn = 0; tn < 8; tn++){
            t0 = fmaxf(t0, fmaxf(sc[tn][0], sc[tn][1]));
            t1 = fmaxf(t1, fmaxf(sc[tn][2], sc[tn][3]));
        }
        t0 = fmaxf(t0, __shfl_xor_sync(0xffffffffu, t0, 1));
        t0 = fmaxf(t0, __shfl_xor_sync(0xffffffffu, t0, 2));
        t1 = fmaxf(t1, __shfl_xor_sync(0xffffffffu, t1, 1));
        t1 = fmaxf(t1, __shfl_xor_sync(0xffffffffu, t1, 2));
        float nm0 = fmaxf(m0, t0), nm1 = fmaxf(m1, t1);
        float c0 = __expf(m0 - nm0), c1 = __expf(m1 - nm1);
        l0 *= c0; l1 *= c1;
        #pragma unroll
        for (int tn = 0; tn < 8; tn++){
            sc[tn][0] = __expf(sc[tn][0] - nm0);
            sc[tn][1] = __expf(sc[tn][1] - nm0);
            sc[tn][2] = __expf(sc[tn][2] - nm1);
            sc[tn][3] = __expf(sc[tn][3] - nm1);
            l0 += sc[tn][0] + sc[tn][1];
            l1 += sc[tn][2] + sc[tn][3];
        }
        #pragma unroll
        for (int od = 0; od < 8; od++){
            oacc[od][0] *= c0; oacc[od][1] *= c0;
            oacc[od][2] *= c1; oacc[od][3] *= c1;
        }
        m0 = nm0; m1 = nm1;

        uint32_t ph[4][4], pl[4][4];
        #pragma unroll
        for (int s = 0; s < 4; s++){
            splitpack(sc[2*s][0],   sc[2*s][1],   ph[s][0], pl[s][0]);
            splitpack(sc[2*s][2],   sc[2*s][3],   ph[s][1], pl[s][1]);
            splitpack(sc[2*s+1][0], sc[2*s+1][1], ph[s][2], pl[s][2]);
            splitpack(sc[2*s+1][2], sc[2*s+1][3], ph[s][3], pl[s][3]);
        }

        #pragma unroll
        for (int s = 0; s < 4; s++){
            uint32_t vhf[4][4], vlf[4][4];
            #pragma unroll
            for (int gd = 0; gd < 4; gd++){
                uint32_t row = s*16 + (lane & 7) + ((lane & 16) >> 1);
                uint32_t col = gd*16 + (lane & 8);
                uint32_t o = (row << 7) + (col << 1);
                uint32_t so = SW128(o);
                ldsm4t(vhf[gd], tb + 16384 + so);
                ldsm4t(vlf[gd], tb + 24576 + so);
            }
            #pragma unroll
            for (int gd = 0; gd < 4; gd++)
                #pragma unroll
                for (int j = 0; j < 2; j++)
                    mma16816(oacc[gd*2+j], ph[s], vhf[gd][j], vhf[gd][j+2]);
            #pragma unroll
            for (int gd = 0; gd < 4; gd++)
                #pragma unroll
                for (int j = 0; j < 2; j++)
                    mma16816(oacc[gd*2+j], ph[s], vlf[gd][j], vlf[gd][j+2]);
            #pragma unroll
            for (int gd = 0; gd < 4; gd++)
                #pragma unroll
                for (int j = 0; j < 2; j++)
                    mma16816(oacc[gd*2+j], pl[s], vhf[gd][j], vhf[gd][j+2]);
        }

        if (kt + 2 < NT) load_kv(kt + 2, (kt + 2) % 3);
    }

    l0 += __shfl_xor_sync(0xffffffffu, l0, 1);
    l0 += __shfl_xor_sync(0xffffffffu, l0, 2);
    l1 += __shfl_xor_sync(0xffffffffu, l1, 1);
    l1 += __shfl_xor_sync(0xffffffffu, l1, 2);
    float inv0 = 1.0f / l0, inv1 = 1.0f / l1;

    int q = qrow0 + gid;
    size_t tk0 = (size_t)(b * SEQ + q) * DM + head * 64;
    size_t tk1 = tk0 + (size_t)8 * DM;
    #pragma unroll
    for (int od = 0; od < 8; od++){
        int d = od*8 + tig*2;
        split_store(oacc[od][0] * inv0, Oh, Ol, tk0 + d);
        split_store(oacc[od][1] * inv0, Oh, Ol, tk0 + d + 1);
        split_store(oacc[od][2] * inv1, Oh, Ol, tk1 + d);
        split_store(oacc[od][3] * inv1, Oh, Ol, tk1 + d + 1);
    }
}

// ---------------- launch ----------------
extern "C" void kernel_launch(void* const* d_in, const int* in_sizes, int n_in,
                              void* d_out, int out_size)
{
    const float* x  = (const float*)d_in[0];
    const float* Wq = (const float*)d_in[1];
    const float* Wk = (const float*)d_in[2];
    const float* Wv = (const float*)d_in[3];
    const float* Wo = (const float*)d_in[4];
    const float* g1 = (const float*)d_in[5];
    const float* g2 = (const float*)d_in[6];
    const float* W1 = (const float*)d_in[7];
    const float* W3 = (const float*)d_in[8];
    const float* W2 = (const float*)d_in[9];
    float* out = (float*)d_out;

    float *x1;
    __nv_bfloat16 *hh,*hl,*ath,*atl,*h2h,*h2l,*gbh,*gbl,*wh,*wl;
    __nv_bfloat16 *qhh,*qhl,*khh,*khl,*vhh,*vhl;
    cudaGetSymbolAddress((void**)&x1,   g_x1);
    cudaGetSymbolAddress((void**)&hh,   g_hh);
    cudaGetSymbolAddress((void**)&hl,   g_hl);
    cudaGetSymbolAddress((void**)&ath,  g_ath);
    cudaGetSymbolAddress((void**)&atl,  g_atl);
    cudaGetSymbolAddress((void**)&h2h,  g_h2h);
    cudaGetSymbolAddress((void**)&h2l,  g_h2l);
    cudaGetSymbolAddress((void**)&gbh,  g_gbh);
    cudaGetSymbolAddress((void**)&gbl,  g_gbl);
    cudaGetSymbolAddress((void**)&wh,   g_wh);
    cudaGetSymbolAddress((void**)&wl,   g_wl);
    cudaGetSymbolAddress((void**)&qhh,  g_qhh);
    cudaGetSymbolAddress((void**)&qhl,  g_qhl);
    cudaGetSymbolAddress((void**)&khh,  g_khh);
    cudaGetSymbolAddress((void**)&khl,  g_khl);
    cudaGetSymbolAddress((void**)&vhh,  g_vhh);
    cudaGetSymbolAddress((void**)&vhl,  g_vhl);

    cudaFuncSetAttribute(gemm_qkv, cudaFuncAttributeMaxDynamicSharedMemorySize, GEMM_SMEM);
    cudaFuncSetAttribute(gemm_add, cudaFuncAttributeMaxDynamicSharedMemorySize, GEMM_SMEM);
    cudaFuncSetAttribute(gemm_w13, cudaFuncAttributeMaxDynamicSharedMemorySize, W13_SMEM);
    cudaFuncSetAttribute(flash_tc, cudaFuncAttributeMaxDynamicSharedMemorySize, FA_SMEM);

    rope_table_k<<<SEQ * 32 / 256, 256>>>();
    split_all_k<<<4096, 256>>>(Wq, Wk, Wv, Wo, W1, W3, W2, wh, wl);

    rms_split_k<<<TOKENS, 256>>>(x, g1, hh, hl);

    gemm_qkv<<<dim3(3*DM/128, TOKENS/128), 512, GEMM_SMEM>>>(
        hh, hl, wh, wl, qhh, qhl, khh, khl, vhh, vhl);

    flash_tc<<<dim3(SEQ / 128, 2 * NH), 256, FA_SMEM>>>(qhh, qhl, khh, khl, vhh, vhl, ath, atl);

    gemm_add<<<dim3(DM/128, TOKENS/128), 512, GEMM_SMEM>>>(
        ath, atl, wh+WOFF_O, wl+WOFF_O, x1, x, DM, DM);
    rms_split_k<<<TOKENS, 256>>>(x1, g2, h2h, h2l);

    gemm_w13<<<dim3(DFF/128, TOKENS/128), 512, W13_SMEM>>>(
        h2h, h2l, wh+WOFF_1, wl+WOFF_1, wh+WOFF_3, wl+WOFF_3, gbh, gbl);
    gemm_add<<<dim3(DM/128, TOKENS/128), 512, GEMM_SMEM>>>(
        gbh, gbl, wh+WOFF_2, wl+WOFF_2, out, x1, DM, DFF);
}

// round 9
// speedup vs baseline: 3.1500x; 1.0330x over previous
#include <cuda_runtime.h>
#include <cuda_bf16.h>
#include <math.h>
#include <stdint.h>

#define TOKENS 4096
#define DM     1024
#define DFF    4096
#define SEQ    2048
#define NH     16
#define DK     64

// ---------------- scratch ----------------
__device__ float g_x1[TOKENS*DM];
__device__ float g_cs[SEQ*32];
__device__ float g_sn[SEQ*32];

__device__ __nv_bfloat16 g_hh[TOKENS*DM],  g_hl[TOKENS*DM];
__device__ __nv_bfloat16 g_ath[TOKENS*DM], g_atl[TOKENS*DM];
__device__ __nv_bfloat16 g_h2h[TOKENS*DM], g_h2l[TOKENS*DM];
__device__ __nv_bfloat16 g_gbh[TOKENS*DFF], g_gbl[TOKENS*DFF];
__device__ __nv_bfloat16 g_qhh[TOKENS*DM], g_qhl[TOKENS*DM];
__device__ __nv_bfloat16 g_khh[TOKENS*DM], g_khl[TOKENS*DM];
__device__ __nv_bfloat16 g_vhh[TOKENS*DM], g_vhl[TOKENS*DM];

#define WOFF_Q  0
#define WOFF_K  (1u<<20)
#define WOFF_V  (2u<<20)
#define WOFF_O  (3u<<20)
#define WOFF_1  (4u<<20)
#define WOFF_3  (8u<<20)
#define WOFF_2  (12u<<20)
__device__ __nv_bfloat16 g_wh[16u<<20];
__device__ __nv_bfloat16 g_wl[16u<<20];

// ---------------- helpers ----------------
__device__ __forceinline__ uint32_t smem_u32(const void* p){
    uint32_t r;
    asm("{ .reg .u64 t; cvta.to.shared.u64 t, %1; cvt.u32.u64 %0, t; }" : "=r"(r) : "l"(p));
    return r;
}
__device__ __forceinline__ void cpa16(uint32_t dst, const void* src){
    asm volatile("cp.async.cg.shared.global [%0], [%1], 16;" :: "r"(dst), "l"(src) : "memory");
}
__device__ __forceinline__ void cp_commit(){ asm volatile("cp.async.commit_group;" ::: "memory"); }
__device__ __forceinline__ void cp_wait2(){ asm volatile("cp.async.wait_group 2;" ::: "memory"); }
__device__ __forceinline__ void cp_wait1(){ asm volatile("cp.async.wait_group 1;" ::: "memory"); }
__device__ __forceinline__ void cp_wait0(){ asm volatile("cp.async.wait_group 0;" ::: "memory"); }

__device__ __forceinline__ void ldsm4(uint32_t* r, uint32_t addr){
    asm volatile("ldmatrix.sync.aligned.m8n8.x4.shared.b16 {%0,%1,%2,%3}, [%4];"
        : "=r"(r[0]),"=r"(r[1]),"=r"(r[2]),"=r"(r[3]) : "r"(addr));
}
__device__ __forceinline__ void ldsm4t(uint32_t* r, uint32_t addr){
    asm volatile("ldmatrix.sync.aligned.m8n8.x4.trans.shared.b16 {%0,%1,%2,%3}, [%4];"
        : "=r"(r[0]),"=r"(r[1]),"=r"(r[2]),"=r"(r[3]) : "r"(addr));
}
__device__ __forceinline__ void mma16816(float* c, const uint32_t* a, uint32_t b0, uint32_t b1){
    asm volatile("mma.sync.aligned.m16n8k16.row.col.f32.bf16.bf16.f32 "
        "{%0,%1,%2,%3}, {%4,%5,%6,%7}, {%8,%9}, {%0,%1,%2,%3};"
        : "+f"(c[0]),"+f"(c[1]),"+f"(c[2]),"+f"(c[3])
        : "r"(a[0]),"r"(a[1]),"r"(a[2]),"r"(a[3]), "r"(b0),"r"(b1));
}
#define SW128(o) ((o) ^ (((o)>>3)&0x70))   // 128B rows

__device__ __forceinline__ void split_store(float w, __nv_bfloat16* h, __nv_bfloat16* l, size_t i){
    __nv_bfloat16 hh = __float2bfloat16(w);
    h[i] = hh;
    l[i] = __float2bfloat16(w - __bfloat162float(hh));
}
__device__ __forceinline__ void splitpack(float x, float y, uint32_t& ph, uint32_t& pl){
    __nv_bfloat16 hx = __float2bfloat16(x), hy = __float2bfloat16(y);
    __nv_bfloat16 lx = __float2bfloat16(x - __bfloat162float(hx));
    __nv_bfloat16 ly = __float2bfloat16(y - __bfloat162float(hy));
    ph = ((uint32_t)__bfloat16_as_ushort(hy) << 16) | __bfloat16_as_ushort(hx);
    pl = ((uint32_t)__bfloat16_as_ushort(ly) << 16) | __bfloat16_as_ushort(lx);
}

// ---------------- RoPE table ----------------
__global__ void rope_table_k() {
    __shared__ float invf[32];
    int t = threadIdx.x;
    if (t < 32) invf[t] = (float)pow(10000.0, -(double)(2 * t) / 64.0);
    __syncthreads();
    int i = blockIdx.x * 256 + t;
    int pos = i >> 5;
    int j   = i & 31;
    float ang = (float)pos * invf[j];
    g_cs[i] = cosf(ang);
    g_sn[i] = sinf(ang);
}

// ---------------- all weight splits, vectorized ----------------
__global__ void split_all_k(const float* __restrict__ Wq, const float* __restrict__ Wk,
                            const float* __restrict__ Wv, const float* __restrict__ Wo,
                            const float* __restrict__ W1, const float* __restrict__ W3,
                            const float* __restrict__ W2,
                            __nv_bfloat16* __restrict__ wh, __nv_bfloat16* __restrict__ wl){
    int gb = blockIdx.x;
    const float* src; uint32_t woff; int lb;
    if (gb < 1024){
        int m = gb >> 8; lb = gb & 255;
        src = (m==0)?Wq:(m==1)?Wk:(m==2)?Wv:Wo;
        woff = (uint32_t)m << 20;
    } else if (gb < 2048){ src = W1; woff = WOFF_1; lb = gb - 1024; }
    else if (gb < 3072){ src = W3; woff = WOFF_3; lb = gb - 2048; }
    else               { src = W2; woff = WOFF_2; lb = gb - 3072; }
    uint2* hp = (uint2*)(wh + woff);
    uint2* lp = (uint2*)(wl + woff);
    #pragma unroll
    for (int j = 0; j < 4; j++){
        int i4 = lb * 1024 + j * 256 + threadIdx.x;
        float4 v = ((const float4*)src)[i4];
        uint32_t h01, l01, h23, l23;
        splitpack(v.x, v.y, h01, l01);
        splitpack(v.z, v.w, h23, l23);
        hp[i4] = make_uint2(h01, h23);
        lp[i4] = make_uint2(l01, l23);
    }
}

// ---------------- RMSNorm -> bf16 hi/lo ----------------
__global__ __launch_bounds__(256) void rms_split_k(const float* __restrict__ x,
                                                   const float* __restrict__ g,
                                                   __nv_bfloat16* __restrict__ oh,
                                                   __nv_bfloat16* __restrict__ ol) {
    int row = blockIdx.x;
    int t   = threadIdx.x;
    const float4* xr = (const float4*)(x + (size_t)row * DM);
    float4 xv = xr[t];
    float ss = xv.x*xv.x + xv.y*xv.y + xv.z*xv.z + xv.w*xv.w;
    #pragma unroll
    for (int off = 16; off > 0; off >>= 1)
        ss += __shfl_xor_sync(0xffffffffu, ss, off);
    __shared__ float warpsum[8];
    if ((t & 31) == 0) warpsum[t >> 5] = ss;
    __syncthreads();
    float tot = warpsum[0]+warpsum[1]+warpsum[2]+warpsum[3]
              + warpsum[4]+warpsum[5]+warpsum[6]+warpsum[7];
    float r = rsqrtf(tot * (1.0f / (float)DM) + 1e-5f);
    float4 gv = ((const float4*)g)[t];
    float v[4] = { xv.x*r*gv.x, xv.y*r*gv.y, xv.z*r*gv.z, xv.w*r*gv.w };
    size_t base = (size_t)row * DM + t * 4;
    uint32_t h01, l01, h23, l23;
    splitpack(v[0], v[1], h01, l01);
    splitpack(v[2], v[3], h23, l23);
    *(uint2*)(oh + base) = make_uint2(h01, h23);
    *(uint2*)(ol + base) = make_uint2(l01, l23);
}

// =====================================================================
// GEMM engine: CTA 128x64, 256 thr (2 CTAs/SM), warp grid 4x2 (32x32),
// BK=64, SW128 128B rows, 2-stage pipeline.
// Stage (48 KB): Ah@0 Al@16K Bh@32K Bl@40K.
// =====================================================================
#define STG64     49152
#define G64_SMEM  (2*STG64)     // 96 KB -> 2 CTAs/SM

__device__ __forceinline__ void g64_load(
    uint32_t tb, int tid, int m0, int n0, int kc, int K,
    const __nv_bfloat16* Ah, const __nv_bfloat16* Al,
    const __nv_bfloat16* Bh, const __nv_bfloat16* Bl)
{
    int k0 = kc * 64;
    #pragma unroll
    for (int j = 0; j < 4; j++){
        int i = j * 256 + tid;        // 0..1023 : A rows 0..127
        int r = i >> 3, c16 = i & 7;
        uint32_t o = SW128((uint32_t)(r << 7) + (c16 << 4));
        const __nv_bfloat16* a = Ah + (size_t)(m0 + r) * K + k0 + c16 * 8;
        cpa16(tb + o, a);
        cpa16(tb + 16384 + o, Al + (size_t)(m0 + r) * K + k0 + c16 * 8);
    }
    #pragma unroll
    for (int j = 0; j < 2; j++){
        int i = j * 256 + tid;        // 0..511 : B rows 0..63
        int r = i >> 3, c16 = i & 7;
        uint32_t o = SW128((uint32_t)(r << 7) + (c16 << 4));
        cpa16(tb + 32768 + o, Bh + (size_t)(n0 + r) * K + k0 + c16 * 8);
        cpa16(tb + 40960 + o, Bl + (size_t)(n0 + r) * K + k0 + c16 * 8);
    }
    cp_commit();
}

struct Frags { uint32_t ah[2][4], al[2][4], bh[2][4], bl[2][4]; };

__device__ __forceinline__ void g64_ldfrag(Frags& f, uint32_t tb, int lane, int wm, int wn, int s){
    uint32_t colb = (uint32_t)(s*32) + ((lane >> 4) << 4);
    #pragma unroll
    for (int t = 0; t < 2; t++){
        uint32_t so = SW128((uint32_t)((wm*32 + t*16 + (lane & 15)) << 7) + colb);
        ldsm4(f.ah[t], tb + so);
        ldsm4(f.al[t], tb + 16384 + so);
    }
    #pragma unroll
    for (int g = 0; g < 2; g++){
        uint32_t so = SW128((uint32_t)((wn*32 + g*16 + (lane & 15)) << 7) + colb);
        ldsm4(f.bh[g], tb + 32768 + so);
        ldsm4(f.bl[g], tb + 49152 - 8192 + so);   // 40960
    }
}

__device__ __forceinline__ void g64_mma(float acc[2][4][4], const Frags& f){
    #pragma unroll
    for (int t = 0; t < 2; t++)
        #pragma unroll
        for (int g = 0; g < 2; g++)
            #pragma unroll
            for (int j = 0; j < 2; j++)
                mma16816(acc[t][g*2+j], f.ah[t], f.bh[g][j], f.bh[g][j+2]);
    #pragma unroll
    for (int t = 0; t < 2; t++)
        #pragma unroll
        for (int g = 0; g < 2; g++)
            #pragma unroll
            for (int j = 0; j < 2; j++)
                mma16816(acc[t][g*2+j], f.ah[t], f.bl[g][j], f.bl[g][j+2]);
    #pragma unroll
    for (int t = 0; t < 2; t++)
        #pragma unroll
        for (int g = 0; g < 2; g++)
            #pragma unroll
            for (int j = 0; j < 2; j++)
                mma16816(acc[t][g*2+j], f.al[t], f.bh[g][j], f.bh[g][j+2]);
}

__device__ __forceinline__ void g64_chunk(uint32_t tb, int lane, int wm, int wn, float acc[2][4][4]){
    Frags f0, f1;
    g64_ldfrag(f0, tb, lane, wm, wn, 0);
    g64_ldfrag(f1, tb, lane, wm, wn, 1);
    g64_mma(acc, f0);
    g64_ldfrag(f0, tb, lane, wm, wn, 2);
    g64_mma(acc, f1);
    g64_ldfrag(f1, tb, lane, wm, wn, 3);
    g64_mma(acc, f0);
    g64_mma(acc, f1);
}

// core mainloop (2-stage)
#define G64_MAIN(AH,AL,BH,BL,KDIM)                                            \
    g64_load(sb, tid, m0, n0, 0, KDIM, AH, AL, BH, BL);                       \
    for (int kc = 0; kc < NC; kc++){                                          \
        cp_wait0();                                                           \
        __syncthreads();                                                      \
        if (kc + 1 < NC)                                                      \
            g64_load(sb + ((kc+1)&1)*STG64, tid, m0, n0, kc+1, KDIM, AH, AL, BH, BL); \
        g64_chunk(sb + (kc&1)*STG64, lane, wm, wn, acc);                      \
    }

// ---------------- fused QKV GEMM (N=3072) ----------------
__global__ __launch_bounds__(256, 2) void gemm_qkv(
    const __nv_bfloat16* __restrict__ Ah, const __nv_bfloat16* __restrict__ Al,
    const __nv_bfloat16* __restrict__ Bh, const __nv_bfloat16* __restrict__ Bl,
    __nv_bfloat16* __restrict__ Qh, __nv_bfloat16* __restrict__ Ql,
    __nv_bfloat16* __restrict__ Kh, __nv_bfloat16* __restrict__ Kl,
    __nv_bfloat16* __restrict__ Vh, __nv_bfloat16* __restrict__ Vl)
{
    extern __shared__ char smem[];
    uint32_t sb = smem_u32(smem);
    const int tid  = threadIdx.x;
    const int lane = tid & 31;
    const int wid  = tid >> 5;
    const int wm   = wid & 3;       // 4 row groups of 32
    const int wn   = wid >> 2;      // 2 col groups of 32
    const int m0 = blockIdx.y * 128, n0 = blockIdx.x * 64;
    const int NC = DM / 64;

    float acc[2][4][4];
    #pragma unroll
    for (int i = 0; i < 2; i++)
        #pragma unroll
        for (int j = 0; j < 4; j++)
            #pragma unroll
            for (int k = 0; k < 4; k++) acc[i][j][k] = 0.0f;

    G64_MAIN(Ah, Al, Bh, Bl, DM)

    const int mtx = n0 >> 10;
    const float scl = (mtx == 0) ? 0.125f : 1.0f;
    __nv_bfloat16* Dh = (mtx==0)?Qh:(mtx==1)?Kh:Vh;
    __nv_bfloat16* Dl = (mtx==0)?Ql:(mtx==1)?Kl:Vl;
    const int gid = lane >> 2, tig = lane & 3;
    #pragma unroll
    for (int tm = 0; tm < 2; tm++){
        #pragma unroll
        for (int half = 0; half < 2; half++){
            int m = m0 + wm*32 + tm*16 + gid + half*8;
            int pos = m & (SEQ - 1), b = m >> 11;
            #pragma unroll
            for (int tn = 0; tn < 4; tn++){
                int cc = (n0 & 1023) + wn*32 + tn*8 + tig*2;
                int head = cc >> 6, hi = cc & 63;
                size_t ob = ((size_t)(b * NH + head) * SEQ + pos) * DK + hi;
                float v0 = acc[tm][tn][half*2];
                float v1 = acc[tm][tn][half*2 + 1];
                float w0, w1;
                if (mtx < 2){
                    float cs = g_cs[pos * 32 + (hi >> 1)];
                    float sn = g_sn[pos * 32 + (hi >> 1)];
                    w0 = (v0 * cs - v1 * sn) * scl;
                    w1 = (v0 * sn + v1 * cs) * scl;
                } else { w0 = v0; w1 = v1; }
                split_store(w0, Dh, Dl, ob);
                split_store(w1, Dh, Dl, ob + 1);
            }
        }
    }
}

// ---------------- GEMM + residual add (Wo, W2) ----------------
__global__ __launch_bounds__(256, 2) void gemm_add(
    const __nv_bfloat16* __restrict__ Ah, const __nv_bfloat16* __restrict__ Al,
    const __nv_bfloat16* __restrict__ Bh, const __nv_bfloat16* __restrict__ Bl,
    float* __restrict__ C, const float* __restrict__ other, int N, int K)
{
    extern __shared__ char smem[];
    uint32_t sb = smem_u32(smem);
    const int tid  = threadIdx.x;
    const int lane = tid & 31;
    const int wid  = tid >> 5;
    const int wm   = wid & 3;
    const int wn   = wid >> 2;
    const int m0 = blockIdx.y * 128, n0 = blockIdx.x * 64;
    const int NC = K / 64;

    float acc[2][4][4];
    #pragma unroll
    for (int i = 0; i < 2; i++)
        #pragma unroll
        for (int j = 0; j < 4; j++)
            #pragma unroll
            for (int k = 0; k < 4; k++) acc[i][j][k] = 0.0f;

    G64_MAIN(Ah, Al, Bh, Bl, K)

    const int gid = lane >> 2, tig = lane & 3;
    #pragma unroll
    for (int tm = 0; tm < 2; tm++){
        #pragma unroll
        for (int half = 0; half < 2; half++){
            int m = m0 + wm*32 + tm*16 + gid + half*8;
            #pragma unroll
            for (int tn = 0; tn < 4; tn++){
                int c = n0 + wn*32 + tn*8 + tig*2;
                size_t base = (size_t)m * N + c;
                C[base]     = other[base] + acc[tm][tn][half*2];
                C[base + 1] = other[base + 1] + acc[tm][tn][half*2 + 1];
            }
        }
    }
}

// ---------------- fused W1/W3 GEMM + silu(u)*v -> bf16 split (unchanged shape) ----------------
#define W13_STG   98304
#define W13_SMEM  (2*W13_STG)

__global__ __launch_bounds__(512, 1) void gemm_w13(
    const __nv_bfloat16* __restrict__ Ah, const __nv_bfloat16* __restrict__ Al,
    const __nv_bfloat16* __restrict__ B1h, const __nv_bfloat16* __restrict__ B1l,
    const __nv_bfloat16* __restrict__ B3h, const __nv_bfloat16* __restrict__ B3l,
    __nv_bfloat16* __restrict__ Chi, __nv_bfloat16* __restrict__ Clo)
{
    extern __shared__ char smem[];
    uint32_t sb = smem_u32(smem);
    const int tid  = threadIdx.x;
    const int lane = tid & 31;
    const int wid  = tid >> 5;
    const int wm   = wid & 3;
    const int wn   = wid >> 2;
    const int m0 = blockIdx.y * 128, n0 = blockIdx.x * 128;
    const int NC = DM / 64;
    const int K  = DM;

    float accU[2][4][4], accV[2][4][4];
    #pragma unroll
    for (int i = 0; i < 2; i++)
        #pragma unroll
        for (int j = 0; j < 4; j++)
            #pragma unroll
            for (int k = 0; k < 4; k++){ accU[i][j][k] = 0.0f; accV[i][j][k] = 0.0f; }

    auto load_chunk = [&](int kc, int stage){
        uint32_t tb = sb + stage * W13_STG;
        int k0 = kc * 64;
        #pragma unroll
        for (int mtx = 0; mtx < 6; mtx++){
            const __nv_bfloat16* base =
                (mtx==0)?Ah:(mtx==1)?Al:(mtx==2)?B1h:(mtx==3)?B1l:(mtx==4)?B3h:B3l;
            int row0 = (mtx < 2) ? m0 : n0;
            #pragma unroll
            for (int j = 0; j < 2; j++){
                int i = j * 512 + tid;
                int r = i >> 3, c16 = i & 7;
                uint32_t o = (uint32_t)(r << 7) + (c16 << 4);
                cpa16(tb + (mtx << 14) + SW128(o),
                      base + (size_t)(row0 + r) * K + k0 + c16 * 8);
            }
        }
        cp_commit();
    };

    load_chunk(0, 0);

    for (int kc = 0; kc < NC; kc++){
        cp_wait0();
        __syncthreads();
        if (kc + 1 < NC) load_chunk(kc + 1, (kc + 1) & 1);
        uint32_t tb = sb + (kc & 1) * W13_STG;

        #pragma unroll
        for (int s = 0; s < 4; s++){
            uint32_t colb = (uint32_t)(s*32) + ((lane >> 4) << 4);
            uint32_t ah[2][4], al[2][4];
            #pragma unroll
            for (int t = 0; t < 2; t++){
                uint32_t so = SW128((uint32_t)((wm*32 + t*16 + (lane & 15)) << 7) + colb);
                ldsm4(ah[t], tb + so);
                ldsm4(al[t], tb + 16384 + so);
            }
            uint32_t b1h[2][4], b1l[2][4], b3h[2][4], b3l[2][4];
            #pragma unroll
            for (int g = 0; g < 2; g++){
                uint32_t so = SW128((uint32_t)((wn*32 + g*16 + (lane & 15)) << 7) + colb);
                ldsm4(b1h[g], tb + 32768 + so);
                ldsm4(b1l[g], tb + 49152 + so);
                ldsm4(b3h[g], tb + 65536 + so);
                ldsm4(b3l[g], tb + 81920 + so);
            }
            #pragma unroll
            for (int t = 0; t < 2; t++)
                #pragma unroll
                for (int g = 0; g < 2; g++)
                    #pragma unroll
                    for (int j = 0; j < 2; j++){
                        mma16816(accU[t][g*2+j], ah[t], b1h[g][j], b1h[g][j+2]);
                        mma16816(accV[t][g*2+j], ah[t], b3h[g][j], b3h[g][j+2]);
                    }
            #pragma unroll
            for (int t = 0; t < 2; t++)
                #pragma unroll
                for (int g = 0; g < 2; g++)
                    #pragma unroll
                    for (int j = 0; j < 2; j++){
                        mma16816(accU[t][g*2+j], ah[t], b1l[g][j], b1l[g][j+2]);
                        mma16816(accV[t][g*2+j], ah[t], b3l[g][j], b3l[g][j+2]);
                    }
            #pragma unroll
            for (int t = 0; t < 2; t++)
                #pragma unroll
                for (int g = 0; g < 2; g++)
                    #pragma unroll
                    for (int j = 0; j < 2; j++){
                        mma16816(accU[t][g*2+j], al[t], b1h[g][j], b1h[g][j+2]);
                        mma16816(accV[t][g*2+j], al[t], b3h[g][j], b3h[g][j+2]);
                    }
        }
    }

    const int gid = lane >> 2, tig = lane & 3;
    #pragma unroll
    for (int tm = 0; tm < 2; tm++){
        #pragma unroll
        for (int half = 0; half < 2; half++){
            int m = m0 + wm*32 + tm*16 + gid + half*8;
            #pragma unroll
            for (int tn = 0; tn < 4; tn++){
                int c = n0 + wn*32 + tn*8 + tig*2;
                size_t base = (size_t)m * DFF + c;
                float u0 = accU[tm][tn][half*2], u1 = accU[tm][tn][half*2+1];
                float v0 = accV[tm][tn][half*2], v1 = accV[tm][tn][half*2+1];
                float w0 = v0 * u0 / (1.0f + __expf(-u0));
                float w1 = v1 * u1 / (1.0f + __expf(-u1));
                split_store(w0, Chi, Clo, base);
                split_store(w1, Chi, Clo, base + 1);
            }
        }
    }
}

// ---------------- Tensor-core flash attention (causal, bf16-split x3) ----------------
#define FA_SMEM (32768 + 3*32768)

__global__ __launch_bounds__(256, 1) void flash_tc(
    const __nv_bfloat16* __restrict__ Qh_, const __nv_bfloat16* __restrict__ Ql_,
    const __nv_bfloat16* __restrict__ Kh_, const __nv_bfloat16* __restrict__ Kl_,
    const __nv_bfloat16* __restrict__ Vh_, const __nv_bfloat16* __restrict__ Vl_,
    __nv_bfloat16* __restrict__ Oh, __nv_bfloat16* __restrict__ Ol)
{
    extern __shared__ char smem[];
    uint32_t sb = smem_u32(smem);
    const int tid  = threadIdx.x;
    const int lane = tid & 31;
    const int w    = tid >> 5;
    const int gid  = lane >> 2, tig = lane & 3;
    const int qt   = (int)gridDim.x - 1 - (int)blockIdx.x;
    const int bh   = blockIdx.y;
    const int b    = bh >> 4, head = bh & 15;
    const size_t base = (size_t)bh * SEQ * DK;
    const int q0 = qt * 128;
    const int NT = 2 * qt + 2;

    #pragma unroll
    for (int m = 0; m < 2; m++){
        const __nv_bfloat16* src = m ? Ql_ : Qh_;
        #pragma unroll
        for (int j = 0; j < 4; j++){
            int i = j * 256 + tid;
            int r = i >> 3, c16 = i & 7;
            cpa16(sb + (m << 14) + SW128((r << 7) + (c16 << 4)),
                  src + base + (size_t)(q0 + r) * DK + c16 * 8);
        }
    }
    cp_commit();

    auto load_kv = [&](int kt, int stage){
        uint32_t tb = sb + 32768 + stage * 32768;
        size_t kb = base + (size_t)kt * 64 * DK;
        #pragma unroll
        for (int m = 0; m < 4; m++){
            const __nv_bfloat16* src = (m==0)?Kh_:(m==1)?Kl_:(m==2)?Vh_:Vl_;
            #pragma unroll
            for (int j = 0; j < 2; j++){
                int i = j * 256 + tid;
                int r = i >> 3, c16 = i & 7;
                cpa16(tb + (m << 13) + SW128((r << 7) + (c16 << 4)),
                      src + kb + (size_t)r * DK + c16 * 8);
            }
        }
        cp_commit();
    };
    load_kv(0, 0);
    load_kv(1, 1);

    cp_wait2();
    __syncthreads();

    uint32_t qh[4][4], ql[4][4];
    #pragma unroll
    for (int s = 0; s < 4; s++){
        uint32_t o = (uint32_t)((w*16 + (lane & 15)) << 7) + s*32 + ((lane >> 4) << 4);
        uint32_t so = SW128(o);
        ldsm4(qh[s], sb + so);
        ldsm4(ql[s], sb + 16384 + so);
    }

    float oacc[8][4];
    #pragma unroll
    for (int i = 0; i < 8; i++)
        #pragma unroll
        for (int j = 0; j < 4; j++) oacc[i][j] = 0.0f;
    float m0 = -1e30f, m1 = -1e30f, l0 = 0.0f, l1 = 0.0f;
    const int qrow0 = q0 + w * 16;

    for (int kt = 0; kt < NT; kt++){
        if (kt + 1 < NT) cp_wait1(); else cp_wait0();
        __syncthreads();
        uint32_t tb = sb + 32768 + (kt % 3) * 32768;

        float sc[8][4];
        #pragma unroll
        for (int i = 0; i < 8; i++)
            #pragma unroll
            for (int j = 0; j < 4; j++) sc[i][j] = 0.0f;

        #pragma unroll
        for (int s = 0; s < 4; s++){
            uint32_t khf[4][4], klf[4][4];
            #pragma unroll
            for (int g = 0; g < 4; g++){
                uint32_t o = (uint32_t)((g*16 + (lane & 15)) << 7) + s*32 + ((lane >> 4) << 4);
                uint32_t so = SW128(o);
                ldsm4(khf[g], tb + so);
                ldsm4(klf[g], tb + 8192 + so);
            }
            #pragma unroll
            for (int g = 0; g < 4; g++)
                #pragma unroll
                for (int j = 0; j < 2; j++)
                    mma16816(sc[g*2+j], qh[s], khf[g][j], khf[g][j+2]);
            #pragma unroll
            for (int g = 0; g < 4; g++)
                #pragma unroll
                for (int j = 0; j < 2; j++)
                    mma16816(sc[g*2+j], qh[s], klf[g][j], klf[g][j+2]);
            #pragma unroll
            for (int g = 0; g < 4; g++)
                #pragma unroll
                for (int j = 0; j < 2; j++)
                    mma16816(sc[g*2+j], ql[s], khf[g][j], khf[g][j+2]);
        }

        if (kt*64 + 63 > qrow0){
            int r0 = qrow0 + gid, r1 = r0 + 8;
            #pragma unroll
            for (int tn = 0; tn < 8; tn++){
                int key = kt*64 + tn*8 + tig*2;
                if (key     > r0) sc[tn][0] = -1e9f;
                if (key + 1 > r0) sc[tn][1] = -1e9f;
                if (key     > r1) sc[tn][2] = -1e9f;
                if (key + 1 > r1) sc[tn][3] = -1e9f;
            }
        }

        float t0 = -1e30f, t1 = -1e30f;
        #pragma unroll
        for (int tn = 0; tn < 8; tn++){
            t0 = fmaxf(t0, fmaxf(sc[tn][0], sc[tn][1]));
            t1 = fmaxf(t1, fmaxf(sc[tn][2], sc[tn][3]));
        }
        t0 = fmaxf(t0, __shfl_xor_sync(0xffffffffu, t0, 1));
        t0 = fmaxf(t0, __shfl_xor_sync(0xffffffffu, t0, 2));
        t1 = fmaxf(t1, __shfl_xor_sync(0xffffffffu, t1, 1));
        t1 = fmaxf(t1, __shfl_xor_sync(0xffffffffu, t1, 2));
        float nm0 = fmaxf(m0, t0), nm1 = fmaxf(m1, t1);
        float c0 = __expf(m0 - nm0), c1 = __expf(m1 - nm1);
        l0 *= c0; l1 *= c1;
        #pragma unroll
        for (int tn = 0; tn < 8; tn++){
            sc[tn][0] = __expf(sc[tn][0] - nm0);
            sc[tn][1] = __expf(sc[tn][1] - nm0);
            sc[tn][2] = __expf(sc[tn][2] - nm1);
            sc[tn][3] = __expf(sc[tn][3] - nm1);
            l0 += sc[tn][0] + sc[tn][1];
            l1 += sc[tn][2] + sc[tn][3];
        }
        #pragma unroll
        for (int od = 0; od < 8; od++){
            oacc[od][0] *= c0; oacc[od][1] *= c0;
            oacc[od][2] *= c1; oacc[od][3] *= c1;
        }
        m0 = nm0; m1 = nm1;

        uint32_t ph[4][4], pl[4][4];
        #pragma unroll
        for (int s = 0; s < 4; s++){
            splitpack(sc[2*s][0],   sc[2*s][1],   ph[s][0], pl[s][0]);
            splitpack(sc[2*s][2],   sc[2*s][3],   ph[s][1], pl[s][1]);
            splitpack(sc[2*s+1][0], sc[2*s+1][1], ph[s][2], pl[s][2]);
            splitpack(sc[2*s+1][2], sc[2*s+1][3], ph[s][3], pl[s][3]);
        }

        #pragma unroll
        for (int s = 0; s < 4; s++){
            uint32_t vhf[4][4], vlf[4][4];
            #pragma unroll
            for (int gd = 0; gd < 4; gd++){
                uint32_t row = s*16 + (lane & 7) + ((lane & 16) >> 1);
                uint32_t col = gd*16 + (lane & 8);
                uint32_t o = (row << 7) + (col << 1);
                uint32_t so = SW128(o);
                ldsm4t(vhf[gd], tb + 16384 + so);
                ldsm4t(vlf[gd], tb + 24576 + so);
            }
            #pragma unroll
            for (int gd = 0; gd < 4; gd++)
                #pragma unroll
                for (int j = 0; j < 2; j++)
                    mma16816(oacc[gd*2+j], ph[s], vhf[gd][j], vhf[gd][j+2]);
            #pragma unroll
            for (int gd = 0; gd < 4; gd++)
                #pragma unroll
                for (int j = 0; j < 2; j++)
                    mma16816(oacc[gd*2+j], ph[s], vlf[gd][j], vlf[gd][j+2]);
            #pragma unroll
            for (int gd = 0; gd < 4; gd++)
                #pragma unroll
                for (int j = 0; j < 2; j++)
                    mma16816(oacc[gd*2+j], pl[s], vhf[gd][j], vhf[gd][j+2]);
        }

        if (kt + 2 < NT) load_kv(kt + 2, (kt + 2) % 3);
    }

    l0 += __shfl_xor_sync(0xffffffffu, l0, 1);
    l0 += __shfl_xor_sync(0xffffffffu, l0, 2);
    l1 += __shfl_xor_sync(0xffffffffu, l1, 1);
    l1 += __shfl_xor_sync(0xffffffffu, l1, 2);
    float inv0 = 1.0f / l0, inv1 = 1.0f / l1;

    int q = qrow0 + gid;
    size_t tk0 = (size_t)(b * SEQ + q) * DM + head * 64;
    size_t tk1 = tk0 + (size_t)8 * DM;
    #pragma unroll
    for (int od = 0; od < 8; od++){
        int d = od*8 + tig*2;
        split_store(oacc[od][0] * inv0, Oh, Ol, tk0 + d);
        split_store(oacc[od][1] * inv0, Oh, Ol, tk0 + d + 1);
        split_store(oacc[od][2] * inv1, Oh, Ol, tk1 + d);
        split_store(oacc[od][3] * inv1, Oh, Ol, tk1 + d + 1);
    }
}

// ---------------- launch ----------------
extern "C" void kernel_launch(void* const* d_in, const int* in_sizes, int n_in,
                              void* d_out, int out_size)
{
    const float* x  = (const float*)d_in[0];
    const float* Wq = (const float*)d_in[1];
    const float* Wk = (const float*)d_in[2];
    const float* Wv = (const float*)d_in[3];
    const float* Wo = (const float*)d_in[4];
    const float* g1 = (const float*)d_in[5];
    const float* g2 = (const float*)d_in[6];
    const float* W1 = (const float*)d_in[7];
    const float* W3 = (const float*)d_in[8];
    const float* W2 = (const float*)d_in[9];
    float* out = (float*)d_out;

    float *x1;
    __nv_bfloat16 *hh,*hl,*ath,*atl,*h2h,*h2l,*gbh,*gbl,*wh,*wl;
    __nv_bfloat16 *qhh,*qhl,*khh,*khl,*vhh,*vhl;
    cudaGetSymbolAddress((void**)&x1,   g_x1);
    cudaGetSymbolAddress((void**)&hh,   g_hh);
    cudaGetSymbolAddress((void**)&hl,   g_hl);
    cudaGetSymbolAddress((void**)&ath,  g_ath);
    cudaGetSymbolAddress((void**)&atl,  g_atl);
    cudaGetSymbolAddress((void**)&h2h,  g_h2h);
    cudaGetSymbolAddress((void**)&h2l,  g_h2l);
    cudaGetSymbolAddress((void**)&gbh,  g_gbh);
    cudaGetSymbolAddress((void**)&gbl,  g_gbl);
    cudaGetSymbolAddress((void**)&wh,   g_wh);
    cudaGetSymbolAddress((void**)&wl,   g_wl);
    cudaGetSymbolAddress((void**)&qhh,  g_qhh);
    cudaGetSymbolAddress((void**)&qhl,  g_qhl);
    cudaGetSymbolAddress((void**)&khh,  g_khh);
    cudaGetSymbolAddress((void**)&khl,  g_khl);
    cudaGetSymbolAddress((void**)&vhh,  g_vhh);
    cudaGetSymbolAddress((void**)&vhl,  g_vhl);

    cudaFuncSetAttribute(gemm_qkv, cudaFuncAttributeMaxDynamicSharedMemorySize, G64_SMEM);
    cudaFuncSetAttribute(gemm_add, cudaFuncAttributeMaxDynamicSharedMemorySize, G64_SMEM);
    cudaFuncSetAttribute(gemm_w13, cudaFuncAttributeMaxDynamicSharedMemorySize, W13_SMEM);
    cudaFuncSetAttribute(flash_tc, cudaFuncAttributeMaxDynamicSharedMemorySize, FA_SMEM);

    rope_table_k<<<SEQ * 32 / 256, 256>>>();
    split_all_k<<<4096, 256>>>(Wq, Wk, Wv, Wo, W1, W3, W2, wh, wl);

    rms_split_k<<<TOKENS, 256>>>(x, g1, hh, hl);

    gemm_qkv<<<dim3(3*DM/64, TOKENS/128), 256, G64_SMEM>>>(
        hh, hl, wh, wl, qhh, qhl, khh, khl, vhh, vhl);

    flash_tc<<<dim3(SEQ / 128, 2 * NH), 256, FA_SMEM>>>(qhh, qhl, khh, khl, vhh, vhl, ath, atl);

    gemm_add<<<dim3(DM/64, TOKENS/128), 256, G64_SMEM>>>(
        ath, atl, wh+WOFF_O, wl+WOFF_O, x1, x, DM, DM);
    rms_split_k<<<TOKENS, 256>>>(x1, g2, h2h, h2l);

    gemm_w13<<<dim3(DFF/128, TOKENS/128), 512, W13_SMEM>>>(
        h2h, h2l, wh+WOFF_1, wl+WOFF_1, wh+WOFF_3, wl+WOFF_3, gbh, gbl);
    gemm_add<<<dim3(DM/64, TOKENS/128), 256, G64_SMEM>>>(
        gbh, gbl, wh+WOFF_2, wl+WOFF_2, out, x1, DM, DFF);
}

// round 10
// speedup vs baseline: 8.0685x; 2.5614x over previous
#include <cuda_runtime.h>
#include <cuda_fp16.h>
#include <math.h>
#include <stdint.h>

#define TOKENS 4096
#define DM     1024
#define DFF    4096
#define SEQ    2048
#define NH     16
#define DK     64

// ---------------- scratch ----------------
__device__ float g_x1[TOKENS*DM];
__device__ float g_cs[SEQ*32];
__device__ float g_sn[SEQ*32];

__device__ __half g_h1[TOKENS*DM];
__device__ __half g_at[TOKENS*DM];
__device__ __half g_h2[TOKENS*DM];
__device__ __half g_gb[TOKENS*DFF];
__device__ __half g_q[TOKENS*DM];
__device__ __half g_k[TOKENS*DM];
__device__ __half g_v[TOKENS*DM];

#define WOFF_Q  0
#define WOFF_K  (1u<<20)
#define WOFF_V  (2u<<20)
#define WOFF_O  (3u<<20)
#define WOFF_1  (4u<<20)
#define WOFF_3  (8u<<20)
#define WOFF_2  (12u<<20)
__device__ __half g_w[16u<<20];

// ---------------- helpers ----------------
__device__ __forceinline__ uint32_t smem_u32(const void* p){
    uint32_t r;
    asm("{ .reg .u64 t; cvta.to.shared.u64 t, %1; cvt.u32.u64 %0, t; }" : "=r"(r) : "l"(p));
    return r;
}
__device__ __forceinline__ void cpa16(uint32_t dst, const void* src){
    asm volatile("cp.async.cg.shared.global [%0], [%1], 16;" :: "r"(dst), "l"(src) : "memory");
}
__device__ __forceinline__ void cp_commit(){ asm volatile("cp.async.commit_group;" ::: "memory"); }
__device__ __forceinline__ void cp_wait2(){ asm volatile("cp.async.wait_group 2;" ::: "memory"); }
__device__ __forceinline__ void cp_wait1(){ asm volatile("cp.async.wait_group 1;" ::: "memory"); }
__device__ __forceinline__ void cp_wait0(){ asm volatile("cp.async.wait_group 0;" ::: "memory"); }

__device__ __forceinline__ void ldsm4(uint32_t* r, uint32_t addr){
    asm volatile("ldmatrix.sync.aligned.m8n8.x4.shared.b16 {%0,%1,%2,%3}, [%4];"
        : "=r"(r[0]),"=r"(r[1]),"=r"(r[2]),"=r"(r[3]) : "r"(addr));
}
__device__ __forceinline__ void ldsm4t(uint32_t* r, uint32_t addr){
    asm volatile("ldmatrix.sync.aligned.m8n8.x4.trans.shared.b16 {%0,%1,%2,%3}, [%4];"
        : "=r"(r[0]),"=r"(r[1]),"=r"(r[2]),"=r"(r[3]) : "r"(addr));
}
__device__ __forceinline__ void mma16816(float* c, const uint32_t* a, uint32_t b0, uint32_t b1){
    asm volatile("mma.sync.aligned.m16n8k16.row.col.f32.f16.f16.f32 "
        "{%0,%1,%2,%3}, {%4,%5,%6,%7}, {%8,%9}, {%0,%1,%2,%3};"
        : "+f"(c[0]),"+f"(c[1]),"+f"(c[2]),"+f"(c[3])
        : "r"(a[0]),"r"(a[1]),"r"(a[2]),"r"(a[3]), "r"(b0),"r"(b1));
}
#define SW128(o) ((o) ^ (((o)>>3)&0x70))

__device__ __forceinline__ uint32_t f22h(float x, float y){
    __half2 h = __floats2half2_rn(x, y);
    return *reinterpret_cast<uint32_t*>(&h);
}

// ---------------- RoPE table ----------------
__global__ void rope_table_k() {
    __shared__ float invf[32];
    int t = threadIdx.x;
    if (t < 32) invf[t] = (float)pow(10000.0, -(double)(2 * t) / 64.0);
    __syncthreads();
    int i = blockIdx.x * 256 + t;
    int pos = i >> 5;
    int j   = i & 31;
    float ang = (float)pos * invf[j];
    g_cs[i] = cosf(ang);
    g_sn[i] = sinf(ang);
}

// ---------------- all weight conversions fp32 -> fp16 ----------------
__global__ void cvt_all_k(const float* __restrict__ Wq, const float* __restrict__ Wk,
                          const float* __restrict__ Wv, const float* __restrict__ Wo,
                          const float* __restrict__ W1, const float* __restrict__ W3,
                          const float* __restrict__ W2, __half* __restrict__ w){
    int gb = blockIdx.x;
    const float* src; uint32_t woff; int lb;
    if (gb < 1024){
        int m = gb >> 8; lb = gb & 255;
        src = (m==0)?Wq:(m==1)?Wk:(m==2)?Wv:Wo;
        woff = (uint32_t)m << 20;
    } else if (gb < 2048){ src = W1; woff = WOFF_1; lb = gb - 1024; }
    else if (gb < 3072){ src = W3; woff = WOFF_3; lb = gb - 2048; }
    else               { src = W2; woff = WOFF_2; lb = gb - 3072; }
    uint2* hp = (uint2*)(w + woff);
    #pragma unroll
    for (int j = 0; j < 4; j++){
        int i4 = lb * 1024 + j * 256 + threadIdx.x;
        float4 v = ((const float4*)src)[i4];
        hp[i4] = make_uint2(f22h(v.x, v.y), f22h(v.z, v.w));
    }
}

// ---------------- RMSNorm -> fp16 ----------------
__global__ __launch_bounds__(256) void rms_h_k(const float* __restrict__ x,
                                               const float* __restrict__ g,
                                               __half* __restrict__ o) {
    int row = blockIdx.x;
    int t   = threadIdx.x;
    const float4* xr = (const float4*)(x + (size_t)row * DM);
    float4 xv = xr[t];
    float ss = xv.x*xv.x + xv.y*xv.y + xv.z*xv.z + xv.w*xv.w;
    #pragma unroll
    for (int off = 16; off > 0; off >>= 1)
        ss += __shfl_xor_sync(0xffffffffu, ss, off);
    __shared__ float warpsum[8];
    if ((t & 31) == 0) warpsum[t >> 5] = ss;
    __syncthreads();
    float tot = warpsum[0]+warpsum[1]+warpsum[2]+warpsum[3]
              + warpsum[4]+warpsum[5]+warpsum[6]+warpsum[7];
    float r = rsqrtf(tot * (1.0f / (float)DM) + 1e-5f);
    float4 gv = ((const float4*)g)[t];
    size_t base4 = (size_t)row * (DM/4) + t;
    ((uint2*)o)[base4] = make_uint2(f22h(xv.x*r*gv.x, xv.y*r*gv.y),
                                    f22h(xv.z*r*gv.z, xv.w*r*gv.w));
}

// =====================================================================
// fp16 GEMM engine: CTA 128x64, 256 thr (2 CTAs/SM), warp 4x2 of 32x32,
// BK=64, SW128 128B rows, 3-stage. Stage (24 KB): A@0(16K) B@16K(8K).
// =====================================================================
#define STGH     24576
#define GH_SMEM  (3*STGH)

__device__ __forceinline__ void gh_load(
    uint32_t tb, int tid, int m0, int n0, int kc, int K,
    const __half* A, const __half* B)
{
    int k0 = kc * 64;
    #pragma unroll
    for (int j = 0; j < 4; j++){
        int i = j * 256 + tid;
        int r = i >> 3, c16 = i & 7;
        cpa16(tb + SW128((uint32_t)(r << 7) + (c16 << 4)),
              A + (size_t)(m0 + r) * K + k0 + c16 * 8);
    }
    #pragma unroll
    for (int j = 0; j < 2; j++){
        int i = j * 256 + tid;
        int r = i >> 3, c16 = i & 7;
        cpa16(tb + 16384 + SW128((uint32_t)(r << 7) + (c16 << 4)),
              B + (size_t)(n0 + r) * K + k0 + c16 * 8);
    }
    cp_commit();
}

struct FragsH { uint32_t a[2][4], b[2][4]; };

__device__ __forceinline__ void gh_ldfrag(FragsH& f, uint32_t tb, int lane, int wm, int wn, int s){
    uint32_t colb = (uint32_t)(s*32) + ((lane >> 4) << 4);
    #pragma unroll
    for (int t = 0; t < 2; t++)
        ldsm4(f.a[t], tb + SW128((uint32_t)((wm*32 + t*16 + (lane & 15)) << 7) + colb));
    #pragma unroll
    for (int g = 0; g < 2; g++)
        ldsm4(f.b[g], tb + 16384 + SW128((uint32_t)((wn*32 + g*16 + (lane & 15)) << 7) + colb));
}

__device__ __forceinline__ void gh_mma(float acc[2][4][4], const FragsH& f){
    #pragma unroll
    for (int t = 0; t < 2; t++)
        #pragma unroll
        for (int g = 0; g < 2; g++)
            #pragma unroll
            for (int j = 0; j < 2; j++)
                mma16816(acc[t][g*2+j], f.a[t], f.b[g][j], f.b[g][j+2]);
}

__device__ __forceinline__ void gh_chunk(uint32_t tb, int lane, int wm, int wn, float acc[2][4][4]){
    FragsH f0, f1;
    gh_ldfrag(f0, tb, lane, wm, wn, 0);
    gh_ldfrag(f1, tb, lane, wm, wn, 1);
    gh_mma(acc, f0);
    gh_ldfrag(f0, tb, lane, wm, wn, 2);
    gh_mma(acc, f1);
    gh_ldfrag(f1, tb, lane, wm, wn, 3);
    gh_mma(acc, f0);
    gh_mma(acc, f1);
}

#define GH_MAIN(A_, B_, KDIM)                                                 \
    gh_load(sb, tid, m0, n0, 0, KDIM, A_, B_);                                \
    gh_load(sb + STGH, tid, m0, n0, 1, KDIM, A_, B_);                         \
    for (int kc = 0; kc < NC; kc++){                                          \
        if (kc + 1 < NC) cp_wait1(); else cp_wait0();                         \
        __syncthreads();                                                      \
        if (kc + 2 < NC)                                                      \
            gh_load(sb + ((kc+2)%3)*STGH, tid, m0, n0, kc+2, KDIM, A_, B_);   \
        gh_chunk(sb + (kc%3)*STGH, lane, wm, wn, acc);                        \
    }

// ---------------- fused QKV GEMM (N=3072) ----------------
__global__ __launch_bounds__(256, 2) void gemm_qkv(
    const __half* __restrict__ A, const __half* __restrict__ B,
    __half* __restrict__ Q, __half* __restrict__ K_, __half* __restrict__ V)
{
    extern __shared__ char smem[];
    uint32_t sb = smem_u32(smem);
    const int tid  = threadIdx.x;
    const int lane = tid & 31;
    const int wid  = tid >> 5;
    const int wm   = wid & 3;
    const int wn   = wid >> 2;
    const int m0 = blockIdx.y * 128, n0 = blockIdx.x * 64;
    const int NC = DM / 64;

    float acc[2][4][4];
    #pragma unroll
    for (int i = 0; i < 2; i++)
        #pragma unroll
        for (int j = 0; j < 4; j++)
            #pragma unroll
            for (int kk = 0; kk < 4; kk++) acc[i][j][kk] = 0.0f;

    GH_MAIN(A, B, DM)

    const int mtx = n0 >> 10;
    const float scl = (mtx == 0) ? 0.125f : 1.0f;
    __half* D = (mtx==0)?Q:(mtx==1)?K_:V;
    const int gid = lane >> 2, tig = lane & 3;
    #pragma unroll
    for (int tm = 0; tm < 2; tm++){
        #pragma unroll
        for (int half = 0; half < 2; half++){
            int m = m0 + wm*32 + tm*16 + gid + half*8;
            int pos = m & (SEQ - 1), b = m >> 11;
            #pragma unroll
            for (int tn = 0; tn < 4; tn++){
                int cc = (n0 & 1023) + wn*32 + tn*8 + tig*2;
                int head = cc >> 6, hi = cc & 63;
                size_t ob = ((size_t)(b * NH + head) * SEQ + pos) * DK + hi;
                float v0 = acc[tm][tn][half*2];
                float v1 = acc[tm][tn][half*2 + 1];
                float w0, w1;
                if (mtx < 2){
                    float cs = g_cs[pos * 32 + (hi >> 1)];
                    float sn = g_sn[pos * 32 + (hi >> 1)];
                    w0 = (v0 * cs - v1 * sn) * scl;
                    w1 = (v0 * sn + v1 * cs) * scl;
                } else { w0 = v0; w1 = v1; }
                *(uint32_t*)(D + ob) = f22h(w0, w1);
            }
        }
    }
}

// ---------------- GEMM + residual add (Wo, W2) ----------------
__global__ __launch_bounds__(256, 2) void gemm_add(
    const __half* __restrict__ A, const __half* __restrict__ B,
    float* __restrict__ C, const float* __restrict__ other, int N, int K)
{
    extern __shared__ char smem[];
    uint32_t sb = smem_u32(smem);
    const int tid  = threadIdx.x;
    const int lane = tid & 31;
    const int wid  = tid >> 5;
    const int wm   = wid & 3;
    const int wn   = wid >> 2;
    const int m0 = blockIdx.y * 128, n0 = blockIdx.x * 64;
    const int NC = K / 64;

    float acc[2][4][4];
    #pragma unroll
    for (int i = 0; i < 2; i++)
        #pragma unroll
        for (int j = 0; j < 4; j++)
            #pragma unroll
            for (int kk = 0; kk < 4; kk++) acc[i][j][kk] = 0.0f;

    GH_MAIN(A, B, K)

    const int gid = lane >> 2, tig = lane & 3;
    #pragma unroll
    for (int tm = 0; tm < 2; tm++){
        #pragma unroll
        for (int half = 0; half < 2; half++){
            int m = m0 + wm*32 + tm*16 + gid + half*8;
            #pragma unroll
            for (int tn = 0; tn < 4; tn++){
                int c = n0 + wn*32 + tn*8 + tig*2;
                size_t base = (size_t)m * N + c;
                C[base]     = other[base] + acc[tm][tn][half*2];
                C[base + 1] = other[base + 1] + acc[tm][tn][half*2 + 1];
            }
        }
    }
}

// ---------------- fused W1/W3 GEMM + silu(u)*v -> fp16 ----------------
#define W13_STG   32768
#define W13_SMEM  (3*W13_STG)

__global__ __launch_bounds__(256, 2) void gemm_w13(
    const __half* __restrict__ A,
    const __half* __restrict__ B1, const __half* __restrict__ B3,
    __half* __restrict__ Cg)
{
    extern __shared__ char smem[];
    uint32_t sb = smem_u32(smem);
    const int tid  = threadIdx.x;
    const int lane = tid & 31;
    const int wid  = tid >> 5;
    const int wm   = wid & 3;
    const int wn   = wid >> 2;
    const int m0 = blockIdx.y * 128, n0 = blockIdx.x * 64;
    const int NC = DM / 64;
    const int K  = DM;

    float accU[2][4][4], accV[2][4][4];
    #pragma unroll
    for (int i = 0; i < 2; i++)
        #pragma unroll
        for (int j = 0; j < 4; j++)
            #pragma unroll
            for (int kk = 0; kk < 4; kk++){ accU[i][j][kk] = 0.0f; accV[i][j][kk] = 0.0f; }

    auto load_chunk = [&](int kc, int stage){
        uint32_t tb = sb + stage * W13_STG;
        int k0 = kc * 64;
        #pragma unroll
        for (int j = 0; j < 4; j++){
            int i = j * 256 + tid;
            int r = i >> 3, c16 = i & 7;
            cpa16(tb + SW128((uint32_t)(r << 7) + (c16 << 4)),
                  A + (size_t)(m0 + r) * K + k0 + c16 * 8);
        }
        #pragma unroll
        for (int j = 0; j < 2; j++){
            int i = j * 256 + tid;
            int r = i >> 3, c16 = i & 7;
            uint32_t o = SW128((uint32_t)(r << 7) + (c16 << 4));
            cpa16(tb + 16384 + o, B1 + (size_t)(n0 + r) * K + k0 + c16 * 8);
            cpa16(tb + 24576 + o, B3 + (size_t)(n0 + r) * K + k0 + c16 * 8);
        }
        cp_commit();
    };

    load_chunk(0, 0);
    load_chunk(1, 1);

    for (int kc = 0; kc < NC; kc++){
        if (kc + 1 < NC) cp_wait1(); else cp_wait0();
        __syncthreads();
        if (kc + 2 < NC) load_chunk(kc + 2, (kc + 2) % 3);
        uint32_t tb = sb + (kc % 3) * W13_STG;

        #pragma unroll
        for (int s = 0; s < 4; s++){
            uint32_t colb = (uint32_t)(s*32) + ((lane >> 4) << 4);
            uint32_t a[2][4], b1[2][4], b3[2][4];
            #pragma unroll
            for (int t = 0; t < 2; t++)
                ldsm4(a[t], tb + SW128((uint32_t)((wm*32 + t*16 + (lane & 15)) << 7) + colb));
            #pragma unroll
            for (int g = 0; g < 2; g++){
                uint32_t so = SW128((uint32_t)((wn*32 + g*16 + (lane & 15)) << 7) + colb);
                ldsm4(b1[g], tb + 16384 + so);
                ldsm4(b3[g], tb + 24576 + so);
            }
            #pragma unroll
            for (int t = 0; t < 2; t++)
                #pragma unroll
                for (int g = 0; g < 2; g++)
                    #pragma unroll
                    for (int j = 0; j < 2; j++){
                        mma16816(accU[t][g*2+j], a[t], b1[g][j], b1[g][j+2]);
                        mma16816(accV[t][g*2+j], a[t], b3[g][j], b3[g][j+2]);
                    }
        }
    }

    const int gid = lane >> 2, tig = lane & 3;
    #pragma unroll
    for (int tm = 0; tm < 2; tm++){
        #pragma unroll
        for (int half = 0; half < 2; half++){
            int m = m0 + wm*32 + tm*16 + gid + half*8;
            #pragma unroll
            for (int tn = 0; tn < 4; tn++){
                int c = n0 + wn*32 + tn*8 + tig*2;
                size_t base = (size_t)m * DFF + c;
                float u0 = accU[tm][tn][half*2], u1 = accU[tm][tn][half*2+1];
                float v0 = accV[tm][tn][half*2], v1 = accV[tm][tn][half*2+1];
                float w0 = v0 * u0 / (1.0f + __expf(-u0));
                float w1 = v1 * u1 / (1.0f + __expf(-u1));
                *(uint32_t*)(Cg + base) = f22h(w0, w1);
            }
        }
    }
}

// ---------------- fp16 flash attention (causal) ----------------
// smem: Q 16K @0; KV stages @16K: [K 8K | V 8K] x3 = 64 KB total
#define FA_SMEM (16384 + 3*16384)

__global__ __launch_bounds__(256, 2) void flash_tc(
    const __half* __restrict__ Qg, const __half* __restrict__ Kg,
    const __half* __restrict__ Vg, __half* __restrict__ Og)
{
    extern __shared__ char smem[];
    uint32_t sb = smem_u32(smem);
    const int tid  = threadIdx.x;
    const int lane = tid & 31;
    const int w    = tid >> 5;
    const int gid  = lane >> 2, tig = lane & 3;
    const int qt   = (int)gridDim.x - 1 - (int)blockIdx.x;
    const int bh   = blockIdx.y;
    const int b    = bh >> 4, head = bh & 15;
    const size_t base = (size_t)bh * SEQ * DK;
    const int q0 = qt * 128;
    const int NT = 2 * qt + 2;

    // Q: 128 rows x 128 B = 1024 16B-chunks over 256 thr = 4 iters
    #pragma unroll
    for (int j = 0; j < 4; j++){
        int i = j * 256 + tid;
        int r = i >> 3, c16 = i & 7;
        cpa16(sb + SW128((uint32_t)(r << 7) + (c16 << 4)),
              Qg + base + (size_t)(q0 + r) * DK + c16 * 8);
    }
    cp_commit();

    auto load_kv = [&](int kt, int stage){
        uint32_t tb = sb + 16384 + stage * 16384;
        size_t kb = base + (size_t)kt * 64 * DK;
        #pragma unroll
        for (int j = 0; j < 2; j++){
            int i = j * 256 + tid;
            int r = i >> 3, c16 = i & 7;
            uint32_t o = SW128((uint32_t)(r << 7) + (c16 << 4));
            cpa16(tb + o,        Kg + kb + (size_t)r * DK + c16 * 8);
            cpa16(tb + 8192 + o, Vg + kb + (size_t)r * DK + c16 * 8);
        }
        cp_commit();
    };
    load_kv(0, 0);
    load_kv(1, 1);

    cp_wait2();
    __syncthreads();

    uint32_t qf[4][4];
    #pragma unroll
    for (int s = 0; s < 4; s++){
        uint32_t o = (uint32_t)((w*16 + (lane & 15)) << 7) + s*32 + ((lane >> 4) << 4);
        ldsm4(qf[s], sb + SW128(o));
    }

    float oacc[8][4];
    #pragma unroll
    for (int i = 0; i < 8; i++)
        #pragma unroll
        for (int j = 0; j < 4; j++) oacc[i][j] = 0.0f;
    float m0 = -1e30f, m1 = -1e30f, l0 = 0.0f, l1 = 0.0f;
    const int qrow0 = q0 + w * 16;

    for (int kt = 0; kt < NT; kt++){
        if (kt + 1 < NT) cp_wait1(); else cp_wait0();
        __syncthreads();
        uint32_t tb = sb + 16384 + (kt % 3) * 16384;

        float sc[8][4];
        #pragma unroll
        for (int i = 0; i < 8; i++)
            #pragma unroll
            for (int j = 0; j < 4; j++) sc[i][j] = 0.0f;

        #pragma unroll
        for (int s = 0; s < 4; s++){
            uint32_t kf[4][4];
            #pragma unroll
            for (int g = 0; g < 4; g++){
                uint32_t o = (uint32_t)((g*16 + (lane & 15)) << 7) + s*32 + ((lane >> 4) << 4);
                ldsm4(kf[g], tb + SW128(o));
            }
            #pragma unroll
            for (int g = 0; g < 4; g++)
                #pragma unroll
                for (int j = 0; j < 2; j++)
                    mma16816(sc[g*2+j], qf[s], kf[g][j], kf[g][j+2]);
        }

        if (kt*64 + 63 > qrow0){
            int r0 = qrow0 + gid, r1 = r0 + 8;
            #pragma unroll
            for (int tn = 0; tn < 8; tn++){
                int key = kt*64 + tn*8 + tig*2;
                if (key     > r0) sc[tn][0] = -1e9f;
                if (key + 1 > r0) sc[tn][1] = -1e9f;
                if (key     > r1) sc[tn][2] = -1e9f;
                if (key + 1 > r1) sc[tn][3] = -1e9f;
            }
        }

        float t0 = -1e30f, t1 = -1e30f;
        #pragma unroll
        for (int tn = 0; tn < 8; tn++){
            t0 = fmaxf(t0, fmaxf(sc[tn][0], sc[tn][1]));
            t1 = fmaxf(t1, fmaxf(sc[tn][2], sc[tn][3]));
        }
        t0 = fmaxf(t0, __shfl_xor_sync(0xffffffffu, t0, 1));
        t0 = fmaxf(t0, __shfl_xor_sync(0xffffffffu, t0, 2));
        t1 = fmaxf(t1, __shfl_xor_sync(0xffffffffu, t1, 1));
        t1 = fmaxf(t1, __shfl_xor_sync(0xffffffffu, t1, 2));
        float nm0 = fmaxf(m0, t0), nm1 = fmaxf(m1, t1);
        float c0 = __expf(m0 - nm0), c1 = __expf(m1 - nm1);
        l0 *= c0; l1 *= c1;
        #pragma unroll
        for (int tn = 0; tn < 8; tn++){
            sc[tn][0] = __expf(sc[tn][0] - nm0);
            sc[tn][1] = __expf(sc[tn][1] - nm0);
            sc[tn][2] = __expf(sc[tn][2] - nm1);
            sc[tn][3] = __expf(sc[tn][3] - nm1);
            l0 += sc[tn][0] + sc[tn][1];
            l1 += sc[tn][2] + sc[tn][3];
        }
        #pragma unroll
        for (int od = 0; od < 8; od++){
            oacc[od][0] *= c0; oacc[od][1] *= c0;
            oacc[od][2] *= c1; oacc[od][3] *= c1;
        }
        m0 = nm0; m1 = nm1;

        uint32_t pf[4][4];
        #pragma unroll
        for (int s = 0; s < 4; s++){
            pf[s][0] = f22h(sc[2*s][0],   sc[2*s][1]);
            pf[s][1] = f22h(sc[2*s][2],   sc[2*s][3]);
            pf[s][2] = f22h(sc[2*s+1][0], sc[2*s+1][1]);
            pf[s][3] = f22h(sc[2*s+1][2], sc[2*s+1][3]);
        }

        #pragma unroll
        for (int s = 0; s < 4; s++){
            uint32_t vf[4][4];
            #pragma unroll
            for (int gd = 0; gd < 4; gd++){
                uint32_t row = s*16 + (lane & 7) + ((lane & 16) >> 1);
                uint32_t col = gd*16 + (lane & 8);
                ldsm4t(vf[gd], tb + 8192 + SW128((row << 7) + (col << 1)));
            }
            #pragma unroll
            for (int gd = 0; gd < 4; gd++)
                #pragma unroll
                for (int j = 0; j < 2; j++)
                    mma16816(oacc[gd*2+j], pf[s], vf[gd][j], vf[gd][j+2]);
        }

        if (kt + 2 < NT) load_kv(kt + 2, (kt + 2) % 3);
    }

    l0 += __shfl_xor_sync(0xffffffffu, l0, 1);
    l0 += __shfl_xor_sync(0xffffffffu, l0, 2);
    l1 += __shfl_xor_sync(0xffffffffu, l1, 1);
    l1 += __shfl_xor_sync(0xffffffffu, l1, 2);
    float inv0 = 1.0f / l0, inv1 = 1.0f / l1;

    int q = qrow0 + gid;
    size_t tk0 = (size_t)(b * SEQ + q) * DM + head * 64;
    size_t tk1 = tk0 + (size_t)8 * DM;
    #pragma unroll
    for (int od = 0; od < 8; od++){
        int d = od*8 + tig*2;
        *(uint32_t*)(Og + tk0 + d) = f22h(oacc[od][0] * inv0, oacc[od][1] * inv0);
        *(uint32_t*)(Og + tk1 + d) = f22h(oacc[od][2] * inv1, oacc[od][3] * inv1);
    }
}

// ---------------- launch ----------------
extern "C" void kernel_launch(void* const* d_in, const int* in_sizes, int n_in,
                              void* d_out, int out_size)
{
    const float* x  = (const float*)d_in[0];
    const float* Wq = (const float*)d_in[1];
    const float* Wk = (const float*)d_in[2];
    const float* Wv = (const float*)d_in[3];
    const float* Wo = (const float*)d_in[4];
    const float* g1 = (const float*)d_in[5];
    const float* g2 = (const float*)d_in[6];
    const float* W1 = (const float*)d_in[7];
    const float* W3 = (const float*)d_in[8];
    const float* W2 = (const float*)d_in[9];
    float* out = (float*)d_out;

    float *x1;
    __half *h1,*at,*h2,*gb,*w,*q,*k,*v;
    cudaGetSymbolAddress((void**)&x1, g_x1);
    cudaGetSymbolAddress((void**)&h1, g_h1);
    cudaGetSymbolAddress((void**)&at, g_at);
    cudaGetSymbolAddress((void**)&h2, g_h2);
    cudaGetSymbolAddress((void**)&gb, g_gb);
    cudaGetSymbolAddress((void**)&w,  g_w);
    cudaGetSymbolAddress((void**)&q,  g_q);
    cudaGetSymbolAddress((void**)&k,  g_k);
    cudaGetSymbolAddress((void**)&v,  g_v);

    cudaFuncSetAttribute(gemm_qkv, cudaFuncAttributeMaxDynamicSharedMemorySize, GH_SMEM);
    cudaFuncSetAttribute(gemm_add, cudaFuncAttributeMaxDynamicSharedMemorySize, GH_SMEM);
    cudaFuncSetAttribute(gemm_w13, cudaFuncAttributeMaxDynamicSharedMemorySize, W13_SMEM);
    cudaFuncSetAttribute(flash_tc, cudaFuncAttributeMaxDynamicSharedMemorySize, FA_SMEM);

    rope_table_k<<<SEQ * 32 / 256, 256>>>();
    cvt_all_k<<<4096, 256>>>(Wq, Wk, Wv, Wo, W1, W3, W2, w);

    rms_h_k<<<TOKENS, 256>>>(x, g1, h1);

    gemm_qkv<<<dim3(3*DM/64, TOKENS/128), 256, GH_SMEM>>>(h1, w, q, k, v);

    flash_tc<<<dim3(SEQ / 128, 2 * NH), 256, FA_SMEM>>>(q, k, v, at);

    gemm_add<<<dim3(DM/64, TOKENS/128), 256, GH_SMEM>>>(at, w + WOFF_O, x1, x, DM, DM);
    rms_h_k<<<TOKENS, 256>>>(x1, g2, h2);

    gemm_w13<<<dim3(DFF/64, TOKENS/128), 256, W13_SMEM>>>(h2, w + WOFF_1, w + WOFF_3, gb);
    gemm_add<<<dim3(DM/64, TOKENS/128), 256, GH_SMEM>>>(gb, w + WOFF_2, out, x1, DM, DFF);
}